// round 3
// baseline (speedup 1.0000x reference)
#include <cuda_runtime.h>
#include <cuda_bf16.h>
#include <cstdint>
#include <cstddef>

// ---------------- problem constants ----------------
#define NVOX   196608
#define CDIM   192
#define SETS   4096
#define SETSZ  48
#define NHEAD  8
#define HD     24
#define DFF    384

// ---------------- scratch (device globals) ----------------
__device__ float g_qk  [(size_t)NVOX * 2 * CDIM]; // q cols 0..191, k 192..383 (set-slot order)
__device__ float g_v   [(size_t)NVOX * CDIM];
__device__ float g_ctx [(size_t)NVOX * CDIM];
__device__ float g_src2[(size_t)NVOX * CDIM];
__device__ float g_x   [(size_t)NVOX * CDIM];     // after LN1, voxel order
__device__ float g_h   [(size_t)NVOX * DFF];
__device__ float g_ffn [(size_t)NVOX * CDIM];

// ---------------- bf16x3 tensor-core GEMM, BM=128 BN=192 BK=32 -------------
// C[m,n] = sum_k A[m,k]*B[n,k] + bias[n].  A rows optionally gathered:
//   GATHER=0: A[row]            GATHER=1: src[vidx[row]]+pos[vidx[row]]
//   GATHER=2: src[vidx[row]]
#define ASTR 20  // u32 row stride (16 data pairs + 4 pad) -> conflict-free

// dynamic smem layout (u32 units)
#define OFF_AH 0
#define OFF_AL (OFF_AH + 128 * ASTR)
#define OFF_BH (OFF_AL + 128 * ASTR)
#define OFF_BL (OFF_BH + 192 * ASTR)
#define OFF_VI (OFF_BL + 192 * ASTR)
#define GEMM_SMEM_BYTES ((OFF_VI + 128) * 4)

__device__ __forceinline__ void split_pack(float x, float y, uint32_t& h, uint32_t& l)
{
    __nv_bfloat162 h2 = __floats2bfloat162_rn(x, y);
    h = *reinterpret_cast<const uint32_t*>(&h2);
    float rx = x - __bfloat162float(h2.x);
    float ry = y - __bfloat162float(h2.y);
    __nv_bfloat162 l2 = __floats2bfloat162_rn(rx, ry);
    l = *reinterpret_cast<const uint32_t*>(&l2);
}

__device__ __forceinline__ void mma_bf16(float c[4],
    uint32_t a0, uint32_t a1, uint32_t a2, uint32_t a3,
    uint32_t b0, uint32_t b1)
{
    asm volatile(
        "mma.sync.aligned.m16n8k16.row.col.f32.bf16.bf16.f32 "
        "{%0,%1,%2,%3}, {%4,%5,%6,%7}, {%8,%9}, {%0,%1,%2,%3};\n"
        : "+f"(c[0]), "+f"(c[1]), "+f"(c[2]), "+f"(c[3])
        : "r"(a0), "r"(a1), "r"(a2), "r"(a3), "r"(b0), "r"(b1));
}

template <int RELU, int GATHER>
__global__ void __launch_bounds__(256)
gemm_bf16x3(const float* __restrict__ A, const float* __restrict__ A2,
            const int* __restrict__ vidx,
            const float* __restrict__ B, const float* __restrict__ bias,
            float* __restrict__ C, int M, int N, int K)
{
    extern __shared__ uint32_t sm[];
    uint32_t* Ah = sm + OFF_AH;
    uint32_t* Al = sm + OFF_AL;
    uint32_t* Bh = sm + OFF_BH;
    uint32_t* Bl = sm + OFF_BL;
    int*      sv = (int*)(sm + OFF_VI);

    const int tid  = threadIdx.x;
    const int lane = tid & 31;
    const int warp = tid >> 5;
    const int wr   = warp >> 2;   // 0..1 -> m offset 64*wr
    const int wc   = warp & 3;    // 0..3 -> n offset 48*wc
    const int row0 = blockIdx.x * 128;
    const int col0 = blockIdx.y * 192;

    if (GATHER) {
        if (tid < 128) sv[tid] = vidx[row0 + tid];
    }
    __syncthreads();

    float acc[4][6][4];
    #pragma unroll
    for (int m = 0; m < 4; m++)
        #pragma unroll
        for (int n = 0; n < 6; n++)
            #pragma unroll
            for (int i = 0; i < 4; i++) acc[m][n][i] = 0.f;

    const int ar = tid >> 3;   // 0..31
    const int ac = tid & 7;    // 0..7 (float4)

    for (int k0 = 0; k0 < K; k0 += 32) {
        // ---- A tile (128 x 32) ----
        #pragma unroll
        for (int r = 0; r < 4; r++) {
            int row = ar + r * 32;
            float4 v;
            if (GATHER) {
                int vr = sv[row];
                v = *(const float4*)&A[(size_t)vr * K + k0 + ac * 4];
                if (GATHER == 1) {
                    float4 p = *(const float4*)&A2[(size_t)vr * K + k0 + ac * 4];
                    v.x += p.x; v.y += p.y; v.z += p.z; v.w += p.w;
                }
            } else {
                v = *(const float4*)&A[(size_t)(row0 + row) * K + k0 + ac * 4];
            }
            uint32_t h0, l0, h1, l1;
            split_pack(v.x, v.y, h0, l0);
            split_pack(v.z, v.w, h1, l1);
            Ah[row * ASTR + ac * 2]     = h0;
            Ah[row * ASTR + ac * 2 + 1] = h1;
            Al[row * ASTR + ac * 2]     = l0;
            Al[row * ASTR + ac * 2 + 1] = l1;
        }
        // ---- B tile (192 x 32) ----
        #pragma unroll
        for (int r = 0; r < 6; r++) {
            int row = ar + r * 32;
            float4 v = *(const float4*)&B[(size_t)(col0 + row) * K + k0 + ac * 4];
            uint32_t h0, l0, h1, l1;
            split_pack(v.x, v.y, h0, l0);
            split_pack(v.z, v.w, h1, l1);
            Bh[row * ASTR + ac * 2]     = h0;
            Bh[row * ASTR + ac * 2 + 1] = h1;
            Bl[row * ASTR + ac * 2]     = l0;
            Bl[row * ASTR + ac * 2 + 1] = l1;
        }
        __syncthreads();

        #pragma unroll
        for (int k16 = 0; k16 < 2; k16++) {
            const int kp = k16 * 8 + (lane & 3);
            // preload A fragments (hi + lo) for 4 m-tiles
            uint32_t ah[4][4], al[4][4];
            #pragma unroll
            for (int mt = 0; mt < 4; mt++) {
                int rl = wr * 64 + mt * 16 + (lane >> 2);
                int rh = rl + 8;
                ah[mt][0] = Ah[rl * ASTR + kp];
                ah[mt][1] = Ah[rh * ASTR + kp];
                ah[mt][2] = Ah[rl * ASTR + kp + 4];
                ah[mt][3] = Ah[rh * ASTR + kp + 4];
                al[mt][0] = Al[rl * ASTR + kp];
                al[mt][1] = Al[rh * ASTR + kp];
                al[mt][2] = Al[rl * ASTR + kp + 4];
                al[mt][3] = Al[rh * ASTR + kp + 4];
            }
            #pragma unroll
            for (int nt = 0; nt < 6; nt++) {
                int n = wc * 48 + nt * 8 + (lane >> 2);
                uint32_t bh0 = Bh[n * ASTR + kp];
                uint32_t bh1 = Bh[n * ASTR + kp + 4];
                uint32_t bl0 = Bl[n * ASTR + kp];
                uint32_t bl1 = Bl[n * ASTR + kp + 4];
                #pragma unroll
                for (int mt = 0; mt < 4; mt++) {
                    mma_bf16(acc[mt][nt], ah[mt][0], ah[mt][1], ah[mt][2], ah[mt][3], bh0, bh1);
                    mma_bf16(acc[mt][nt], ah[mt][0], ah[mt][1], ah[mt][2], ah[mt][3], bl0, bl1);
                    mma_bf16(acc[mt][nt], al[mt][0], al[mt][1], al[mt][2], al[mt][3], bh0, bh1);
                }
            }
        }
        __syncthreads();
    }

    // ---- epilogue ----
    #pragma unroll
    for (int mt = 0; mt < 4; mt++) {
        int r0 = row0 + wr * 64 + mt * 16 + (lane >> 2);
        #pragma unroll
        for (int nt = 0; nt < 6; nt++) {
            int c = col0 + wc * 48 + nt * 8 + 2 * (lane & 3);
            float bx = bias[c], by = bias[c + 1];
            float2 o0, o1;
            o0.x = acc[mt][nt][0] + bx; o0.y = acc[mt][nt][1] + by;
            o1.x = acc[mt][nt][2] + bx; o1.y = acc[mt][nt][3] + by;
            if (RELU) {
                o0.x = fmaxf(o0.x, 0.f); o0.y = fmaxf(o0.y, 0.f);
                o1.x = fmaxf(o1.x, 0.f); o1.y = fmaxf(o1.y, 0.f);
            }
            *(float2*)&C[(size_t)r0 * N + c]       = o0;
            *(float2*)&C[(size_t)(r0 + 8) * N + c] = o1;
        }
    }
}

// ---------------- attention: 192 threads = 4 (set,head) pairs ---------------
__global__ void __launch_bounds__(192)
attn_kernel(const uint8_t* __restrict__ mask)
{
    const int p   = threadIdx.x / SETSZ;   // pair slot 0..3
    const int i   = threadIdx.x % SETSZ;   // row 0..47
    const int gp  = blockIdx.x * 4 + p;
    const int s   = gp >> 3;
    const int h   = gp & 7;

    __shared__ float ks[4][SETSZ][28];
    __shared__ float vs[4][SETSZ][28];
    __shared__ float mf[4][SETSZ];

    const size_t ro = (size_t)s * SETSZ + i;
    const float* qrow = &g_qk[ro * (2 * CDIM) + h * HD];

    // own-row loads: q -> regs, k/v -> smem
    float4 q[6];
    #pragma unroll
    for (int t = 0; t < 6; t++) {
        q[t] = *(const float4*)&qrow[t * 4];
        float4 kk = *(const float4*)&qrow[CDIM + t * 4];
        *(float4*)&ks[p][i][t * 4] = kk;
        float4 vv = *(const float4*)&g_v[ro * CDIM + h * HD + t * 4];
        *(float4*)&vs[p][i][t * 4] = vv;
    }
    mf[p][i] = (mask[(size_t)s * SETSZ + i] != 0) ? -1e9f : 0.f;
    __syncthreads();

    const float scale = 0.20412414523193154f; // 1/sqrt(24)
    float sc[SETSZ];
    #pragma unroll 8
    for (int j = 0; j < SETSZ; j++) {
        float a0 = 0.f, a1 = 0.f, a2 = 0.f, a3 = 0.f, a4 = 0.f, a5 = 0.f;
        float4 k0 = *(const float4*)&ks[p][j][0];
        float4 k1 = *(const float4*)&ks[p][j][4];
        float4 k2 = *(const float4*)&ks[p][j][8];
        float4 k3 = *(const float4*)&ks[p][j][12];
        float4 k4 = *(const float4*)&ks[p][j][16];
        float4 k5 = *(const float4*)&ks[p][j][20];
        a0 = q[0].x * k0.x + q[0].y * k0.y + q[0].z * k0.z + q[0].w * k0.w;
        a1 = q[1].x * k1.x + q[1].y * k1.y + q[1].z * k1.z + q[1].w * k1.w;
        a2 = q[2].x * k2.x + q[2].y * k2.y + q[2].z * k2.z + q[2].w * k2.w;
        a3 = q[3].x * k3.x + q[3].y * k3.y + q[3].z * k3.z + q[3].w * k3.w;
        a4 = q[4].x * k4.x + q[4].y * k4.y + q[4].z * k4.z + q[4].w * k4.w;
        a5 = q[5].x * k5.x + q[5].y * k5.y + q[5].z * k5.z + q[5].w * k5.w;
        sc[j] = ((a0 + a1) + (a2 + a3) + (a4 + a5)) * scale + mf[p][j];
    }

    float m = -1e30f;
    #pragma unroll
    for (int j = 0; j < SETSZ; j++) m = fmaxf(m, sc[j]);
    float sum = 0.f;
    #pragma unroll
    for (int j = 0; j < SETSZ; j++) { float e = __expf(sc[j] - m); sc[j] = e; sum += e; }
    float inv = 1.f / sum;

    float4 o[6];
    #pragma unroll
    for (int t = 0; t < 6; t++) { o[t].x = 0.f; o[t].y = 0.f; o[t].z = 0.f; o[t].w = 0.f; }
    #pragma unroll 4
    for (int j = 0; j < SETSZ; j++) {
        float pr = sc[j] * inv;
        #pragma unroll
        for (int t = 0; t < 6; t++) {
            float4 v4 = *(const float4*)&vs[p][j][t * 4];
            o[t].x += pr * v4.x; o[t].y += pr * v4.y;
            o[t].z += pr * v4.z; o[t].w += pr * v4.w;
        }
    }
    float* crow = &g_ctx[ro * CDIM + h * HD];
    #pragma unroll
    for (int t = 0; t < 6; t++) *(float4*)&crow[t * 4] = o[t];
}

// ---------------- scatter + residual + LN1 (warp per slot row) --------------
__global__ void __launch_bounds__(256)
scatter_ln1(const float* __restrict__ src, const int* __restrict__ vidx,
            const float* __restrict__ g, const float* __restrict__ b)
{
    int warp = (blockIdx.x * blockDim.x + threadIdx.x) >> 5;
    int lane = threadIdx.x & 31;
    if (warp >= NVOX) return;
    int v = vidx[warp];

    float vals[6];
    float s1 = 0.f, s2 = 0.f;
    #pragma unroll
    for (int t = 0; t < 6; t++) {
        int c = lane + t * 32;
        float val = src[(size_t)v * CDIM + c] + g_src2[(size_t)warp * CDIM + c];
        vals[t] = val;
        s1 += val; s2 += val * val;
    }
    #pragma unroll
    for (int o = 16; o > 0; o >>= 1) {
        s1 += __shfl_xor_sync(0xFFFFFFFFu, s1, o);
        s2 += __shfl_xor_sync(0xFFFFFFFFu, s2, o);
    }
    float mean = s1 * (1.f / CDIM);
    float var  = s2 * (1.f / CDIM) - mean * mean;
    float inv  = rsqrtf(var + 1e-5f);
    #pragma unroll
    for (int t = 0; t < 6; t++) {
        int c = lane + t * 32;
        g_x[(size_t)v * CDIM + c] = (vals[t] - mean) * inv * g[c] + b[c];
    }
}

// --------- fused: t = LN2(x + ffn); out = LN3(t + src) (warp per row) -------
__global__ void __launch_bounds__(256)
ln23_kernel(const float* __restrict__ src,
            const float* __restrict__ g2, const float* __restrict__ b2,
            const float* __restrict__ g3, const float* __restrict__ b3,
            float* __restrict__ out)
{
    int warp = (blockIdx.x * blockDim.x + threadIdx.x) >> 5;
    int lane = threadIdx.x & 31;
    if (warp >= NVOX) return;

    float vals[6];
    float s1 = 0.f, s2 = 0.f;
    #pragma unroll
    for (int t = 0; t < 6; t++) {
        int c = lane + t * 32;
        float val = g_x[(size_t)warp * CDIM + c] + g_ffn[(size_t)warp * CDIM + c];
        vals[t] = val;
        s1 += val; s2 += val * val;
    }
    #pragma unroll
    for (int o = 16; o > 0; o >>= 1) {
        s1 += __shfl_xor_sync(0xFFFFFFFFu, s1, o);
        s2 += __shfl_xor_sync(0xFFFFFFFFu, s2, o);
    }
    float mean = s1 * (1.f / CDIM);
    float var  = s2 * (1.f / CDIM) - mean * mean;
    float inv  = rsqrtf(var + 1e-5f);

    float u[6];
    s1 = 0.f; s2 = 0.f;
    #pragma unroll
    for (int t = 0; t < 6; t++) {
        int c = lane + t * 32;
        float t2 = (vals[t] - mean) * inv * g2[c] + b2[c];
        float uu = t2 + src[(size_t)warp * CDIM + c];
        u[t] = uu;
        s1 += uu; s2 += uu * uu;
    }
    #pragma unroll
    for (int o = 16; o > 0; o >>= 1) {
        s1 += __shfl_xor_sync(0xFFFFFFFFu, s1, o);
        s2 += __shfl_xor_sync(0xFFFFFFFFu, s2, o);
    }
    float mean3 = s1 * (1.f / CDIM);
    float var3  = s2 * (1.f / CDIM) - mean3 * mean3;
    float inv3  = rsqrtf(var3 + 1e-5f);
    #pragma unroll
    for (int t = 0; t < 6; t++) {
        int c = lane + t * 32;
        out[(size_t)warp * CDIM + c] = (u[t] - mean3) * inv3 * g3[c] + b3[c];
    }
}

// ---------------- launch --------------------------------------------------
extern "C" void kernel_launch(void* const* d_in, const int* in_sizes, int n_in,
                              void* d_out, int out_size)
{
    const float* src   = (const float*)d_in[0];
    const float* pos   = (const float*)d_in[1];
    const float* w_qkv = (const float*)d_in[2];
    const float* b_qkv = (const float*)d_in[3];
    const float* w_out = (const float*)d_in[4];
    const float* b_out = (const float*)d_in[5];
    const float* w1    = (const float*)d_in[6];
    const float* b1    = (const float*)d_in[7];
    const float* w2    = (const float*)d_in[8];
    const float* b2    = (const float*)d_in[9];
    const float* ln1g  = (const float*)d_in[10];
    const float* ln1b  = (const float*)d_in[11];
    const float* ln2g  = (const float*)d_in[12];
    const float* ln2b  = (const float*)d_in[13];
    const float* ln3g  = (const float*)d_in[14];
    const float* ln3b  = (const float*)d_in[15];
    const int*   vidx  = (const int*)d_in[16];
    const uint8_t* msk = (const uint8_t*)d_in[17];
    float* out = (float*)d_out;

    float *p_qk, *p_v, *p_ctx, *p_src2, *p_x, *p_h, *p_ffn;
    cudaGetSymbolAddress((void**)&p_qk,   g_qk);
    cudaGetSymbolAddress((void**)&p_v,    g_v);
    cudaGetSymbolAddress((void**)&p_ctx,  g_ctx);
    cudaGetSymbolAddress((void**)&p_src2, g_src2);
    cudaGetSymbolAddress((void**)&p_x,    g_x);
    cudaGetSymbolAddress((void**)&p_h,    g_h);
    cudaGetSymbolAddress((void**)&p_ffn,  g_ffn);

    cudaFuncSetAttribute(gemm_bf16x3<0,1>, cudaFuncAttributeMaxDynamicSharedMemorySize, GEMM_SMEM_BYTES);
    cudaFuncSetAttribute(gemm_bf16x3<0,2>, cudaFuncAttributeMaxDynamicSharedMemorySize, GEMM_SMEM_BYTES);
    cudaFuncSetAttribute(gemm_bf16x3<0,0>, cudaFuncAttributeMaxDynamicSharedMemorySize, GEMM_SMEM_BYTES);
    cudaFuncSetAttribute(gemm_bf16x3<1,0>, cudaFuncAttributeMaxDynamicSharedMemorySize, GEMM_SMEM_BYTES);

    const int MB = NVOX / 128;  // 1536

    // 1) q,k projection with fused gather (src+pos): (N x 384)
    gemm_bf16x3<0,1><<<dim3(MB, 2), 256, GEMM_SMEM_BYTES>>>(
        src, pos, vidx, w_qkv, b_qkv, p_qk, NVOX, 2 * CDIM, CDIM);

    // 2) v projection with fused gather (src): (N x 192)
    gemm_bf16x3<0,2><<<dim3(MB, 1), 256, GEMM_SMEM_BYTES>>>(
        src, nullptr, vidx, w_qkv + (size_t)2 * CDIM * CDIM,
        b_qkv + 2 * CDIM, p_v, NVOX, CDIM, CDIM);

    // 3) attention: 4 (set,head) pairs per block
    attn_kernel<<<(SETS * NHEAD) / 4, 192>>>(msk);

    // 4) output projection
    gemm_bf16x3<0,0><<<dim3(MB, 1), 256, GEMM_SMEM_BYTES>>>(
        p_ctx, nullptr, nullptr, w_out, b_out, p_src2, NVOX, CDIM, CDIM);

    // 5) scatter back + residual + LN1 -> g_x (voxel order)
    scatter_ln1<<<NVOX / 8, 256>>>(src, vidx, ln1g, ln1b);

    // 6) FFN
    gemm_bf16x3<1,0><<<dim3(MB, 2), 256, GEMM_SMEM_BYTES>>>(
        p_x, nullptr, nullptr, w1, b1, p_h, NVOX, DFF, CDIM);
    gemm_bf16x3<0,0><<<dim3(MB, 1), 256, GEMM_SMEM_BYTES>>>(
        p_h, nullptr, nullptr, w2, b2, p_ffn, NVOX, CDIM, DFF);

    // 7) LN2 + residual + LN3 -> out
    ln23_kernel<<<NVOX / 8, 256>>>(src, ln2g, ln2b, ln3g, ln3b, out);
}

// round 4
// speedup vs baseline: 1.1992x; 1.1992x over previous
#include <cuda_runtime.h>
#include <cuda_bf16.h>
#include <cstdint>
#include <cstddef>

// ---------------- problem constants ----------------
#define NVOX   196608
#define CDIM   192
#define SETS   4096
#define SETSZ  48
#define NHEAD  8
#define HD     24
#define DFF    384

// ---------------- scratch (device globals) ----------------
__device__ float g_qk [(size_t)NVOX * 2 * CDIM]; // q cols 0..191, k 192..383 (set-slot order)
__device__ float g_v  [(size_t)NVOX * CDIM];
__device__ float g_ctx[(size_t)NVOX * CDIM];
__device__ float g_x  [(size_t)NVOX * CDIM];     // after LN1, voxel order
__device__ float g_h  [(size_t)NVOX * DFF];

// ---------------- bf16x3 tensor-core GEMM, BM=128 BN=192 BK=32, 512 thr ----
// C[m,n] = sum_k A[m,k]*B[n,k] + bias[n]
// GATHER: 0 none | 1 A=src[vidx]+pos[vidx] | 2 A=src[vidx]
// EPI:    0 plain (+optional RELU)
//         1 LN1:  C[vidx[row]] = LN(acc+bias + src[vidx[row]]) * g1 + b1
//         2 LN23: t=LN(acc+bias + x[row])*g2+b2; C[row]=LN(t+src[row])*g3+b3
#define ASTR 20  // u32 row stride (16 data pairs + 4 pad)

#define OFF_AH 0
#define OFF_AL (OFF_AH + 128 * ASTR)
#define OFF_BH (OFF_AL + 128 * ASTR)
#define OFF_BL (OFF_BH + 192 * ASTR)
#define OFF_VI (OFF_BL + 192 * ASTR)
#define GEMM_SMEM_BYTES ((OFF_VI + 128) * 4)

__device__ __forceinline__ void split_pack(float x, float y, uint32_t& h, uint32_t& l)
{
    __nv_bfloat162 h2 = __floats2bfloat162_rn(x, y);
    h = *reinterpret_cast<const uint32_t*>(&h2);
    float rx = x - __bfloat162float(h2.x);
    float ry = y - __bfloat162float(h2.y);
    __nv_bfloat162 l2 = __floats2bfloat162_rn(rx, ry);
    l = *reinterpret_cast<const uint32_t*>(&l2);
}

__device__ __forceinline__ void mma_bf16(float c[4],
    uint32_t a0, uint32_t a1, uint32_t a2, uint32_t a3,
    uint32_t b0, uint32_t b1)
{
    asm volatile(
        "mma.sync.aligned.m16n8k16.row.col.f32.bf16.bf16.f32 "
        "{%0,%1,%2,%3}, {%4,%5,%6,%7}, {%8,%9}, {%0,%1,%2,%3};\n"
        : "+f"(c[0]), "+f"(c[1]), "+f"(c[2]), "+f"(c[3])
        : "r"(a0), "r"(a1), "r"(a2), "r"(a3), "r"(b0), "r"(b1));
}

template <int RELU, int GATHER, int EPI>
__global__ void __launch_bounds__(512)
gemm_bf16x3(const float* __restrict__ A, const float* __restrict__ A2,
            const int* __restrict__ vidx,
            const float* __restrict__ B, const float* __restrict__ bias,
            float* __restrict__ C,
            const float* __restrict__ e_src, const float* __restrict__ e_x,
            const float* __restrict__ e_g1, const float* __restrict__ e_b1,
            const float* __restrict__ e_g2, const float* __restrict__ e_b2,
            int M, int N, int K)
{
    extern __shared__ uint32_t sm[];
    uint32_t* Ah = sm + OFF_AH;
    uint32_t* Al = sm + OFF_AL;
    uint32_t* Bh = sm + OFF_BH;
    uint32_t* Bl = sm + OFF_BL;
    int*      sv = (int*)(sm + OFF_VI);

    const int tid  = threadIdx.x;
    const int lane = tid & 31;
    const int warp = tid >> 5;
    const int wr   = warp >> 2;   // 0..3 -> m offset 32*wr
    const int wc   = warp & 3;    // 0..3 -> n offset 48*wc
    const int row0 = blockIdx.x * 128;
    const int col0 = blockIdx.y * 192;

    if (GATHER || EPI == 1) {
        if (tid < 128) sv[tid] = vidx[row0 + tid];
        __syncthreads();
    }

    float acc[2][6][4];
    #pragma unroll
    for (int m = 0; m < 2; m++)
        #pragma unroll
        for (int n = 0; n < 6; n++)
            #pragma unroll
            for (int i = 0; i < 4; i++) acc[m][n][i] = 0.f;

    const int ar = tid >> 3;   // 0..63
    const int ac = tid & 7;    // 0..7 (float4 col)

    auto ldA = [&](int kk, int rr) -> float4 {
        int row = ar + rr * 64;
        if (GATHER) {
            int vr = sv[row];
            float4 v = *(const float4*)&A[(size_t)vr * K + kk + ac * 4];
            if (GATHER == 1) {
                float4 p = *(const float4*)&A2[(size_t)vr * K + kk + ac * 4];
                v.x += p.x; v.y += p.y; v.z += p.z; v.w += p.w;
            }
            return v;
        }
        return *(const float4*)&A[(size_t)(row0 + row) * K + kk + ac * 4];
    };
    auto ldB = [&](int kk, int rr) -> float4 {
        return *(const float4*)&B[(size_t)(col0 + ar + rr * 64) * K + kk + ac * 4];
    };

    float4 pa0 = ldA(0, 0), pa1 = ldA(0, 1);
    float4 pb0 = ldB(0, 0), pb1 = ldB(0, 1), pb2 = ldB(0, 2);

    for (int k0 = 0; k0 < K; k0 += 32) {
        // ---- split + store staged tile ----
        uint32_t h0, l0, h1, l1;
        split_pack(pa0.x, pa0.y, h0, l0); split_pack(pa0.z, pa0.w, h1, l1);
        Ah[ar * ASTR + ac * 2] = h0; Ah[ar * ASTR + ac * 2 + 1] = h1;
        Al[ar * ASTR + ac * 2] = l0; Al[ar * ASTR + ac * 2 + 1] = l1;
        split_pack(pa1.x, pa1.y, h0, l0); split_pack(pa1.z, pa1.w, h1, l1);
        Ah[(ar + 64) * ASTR + ac * 2] = h0; Ah[(ar + 64) * ASTR + ac * 2 + 1] = h1;
        Al[(ar + 64) * ASTR + ac * 2] = l0; Al[(ar + 64) * ASTR + ac * 2 + 1] = l1;
        split_pack(pb0.x, pb0.y, h0, l0); split_pack(pb0.z, pb0.w, h1, l1);
        Bh[ar * ASTR + ac * 2] = h0; Bh[ar * ASTR + ac * 2 + 1] = h1;
        Bl[ar * ASTR + ac * 2] = l0; Bl[ar * ASTR + ac * 2 + 1] = l1;
        split_pack(pb1.x, pb1.y, h0, l0); split_pack(pb1.z, pb1.w, h1, l1);
        Bh[(ar + 64) * ASTR + ac * 2] = h0; Bh[(ar + 64) * ASTR + ac * 2 + 1] = h1;
        Bl[(ar + 64) * ASTR + ac * 2] = l0; Bl[(ar + 64) * ASTR + ac * 2 + 1] = l1;
        split_pack(pb2.x, pb2.y, h0, l0); split_pack(pb2.z, pb2.w, h1, l1);
        Bh[(ar + 128) * ASTR + ac * 2] = h0; Bh[(ar + 128) * ASTR + ac * 2 + 1] = h1;
        Bl[(ar + 128) * ASTR + ac * 2] = l0; Bl[(ar + 128) * ASTR + ac * 2 + 1] = l1;
        __syncthreads();

        // ---- prefetch next tile (overlaps with MMA below) ----
        if (k0 + 32 < K) {
            pa0 = ldA(k0 + 32, 0); pa1 = ldA(k0 + 32, 1);
            pb0 = ldB(k0 + 32, 0); pb1 = ldB(k0 + 32, 1); pb2 = ldB(k0 + 32, 2);
        }

        // ---- MMA ----
        #pragma unroll
        for (int k16 = 0; k16 < 2; k16++) {
            const int kp = k16 * 8 + (lane & 3);
            uint32_t ah[2][4], al[2][4];
            #pragma unroll
            for (int mt = 0; mt < 2; mt++) {
                int rl = wr * 32 + mt * 16 + (lane >> 2);
                int rh = rl + 8;
                ah[mt][0] = Ah[rl * ASTR + kp];
                ah[mt][1] = Ah[rh * ASTR + kp];
                ah[mt][2] = Ah[rl * ASTR + kp + 4];
                ah[mt][3] = Ah[rh * ASTR + kp + 4];
                al[mt][0] = Al[rl * ASTR + kp];
                al[mt][1] = Al[rh * ASTR + kp];
                al[mt][2] = Al[rl * ASTR + kp + 4];
                al[mt][3] = Al[rh * ASTR + kp + 4];
            }
            #pragma unroll
            for (int nt = 0; nt < 6; nt++) {
                int n = wc * 48 + nt * 8 + (lane >> 2);
                uint32_t bh0 = Bh[n * ASTR + kp];
                uint32_t bh1 = Bh[n * ASTR + kp + 4];
                uint32_t bl0 = Bl[n * ASTR + kp];
                uint32_t bl1 = Bl[n * ASTR + kp + 4];
                #pragma unroll
                for (int mt = 0; mt < 2; mt++) {
                    mma_bf16(acc[mt][nt], ah[mt][0], ah[mt][1], ah[mt][2], ah[mt][3], bh0, bh1);
                    mma_bf16(acc[mt][nt], ah[mt][0], ah[mt][1], ah[mt][2], ah[mt][3], bl0, bl1);
                    mma_bf16(acc[mt][nt], al[mt][0], al[mt][1], al[mt][2], al[mt][3], bh0, bh1);
                }
            }
        }
        __syncthreads();
    }

    // ================= epilogue =================
    if (EPI == 0) {
        #pragma unroll
        for (int mt = 0; mt < 2; mt++) {
            int r0 = row0 + wr * 32 + mt * 16 + (lane >> 2);
            #pragma unroll
            for (int nt = 0; nt < 6; nt++) {
                int c = col0 + wc * 48 + nt * 8 + 2 * (lane & 3);
                float bx = bias[c], by = bias[c + 1];
                float2 o0, o1;
                o0.x = acc[mt][nt][0] + bx; o0.y = acc[mt][nt][1] + by;
                o1.x = acc[mt][nt][2] + bx; o1.y = acc[mt][nt][3] + by;
                if (RELU) {
                    o0.x = fmaxf(o0.x, 0.f); o0.y = fmaxf(o0.y, 0.f);
                    o1.x = fmaxf(o1.x, 0.f); o1.y = fmaxf(o1.y, 0.f);
                }
                *(float2*)&C[(size_t)r0 * N + c]       = o0;
                *(float2*)&C[(size_t)(r0 + 8) * N + c] = o1;
            }
        }
        return;
    }

    // LN epilogues: N == 192 (full row per block), col0 == 0
    float* rsum = (float*)sm;         // [128]
    float* rsq  = (float*)sm + 128;   // [128]
    if (tid < 128) { rsum[tid] = 0.f; rsq[tid] = 0.f; }
    __syncthreads();

    // phase A: acc += bias + residual; accumulate row sums
    #pragma unroll
    for (int mt = 0; mt < 2; mt++) {
        #pragma unroll
        for (int half = 0; half < 2; half++) {
            int row = wr * 32 + mt * 16 + (lane >> 2) + half * 8;
            float s1 = 0.f, s2 = 0.f;
            #pragma unroll
            for (int nt = 0; nt < 6; nt++) {
                int c = wc * 48 + nt * 8 + 2 * (lane & 3);
                float2 res;
                if (EPI == 1) {
                    int v = sv[row];
                    res = *(const float2*)&e_src[(size_t)v * CDIM + c];
                } else {
                    res = *(const float2*)&e_x[(size_t)(row0 + row) * CDIM + c];
                }
                float v0 = acc[mt][nt][half * 2 + 0] + bias[c]     + res.x;
                float v1 = acc[mt][nt][half * 2 + 1] + bias[c + 1] + res.y;
                acc[mt][nt][half * 2 + 0] = v0;
                acc[mt][nt][half * 2 + 1] = v1;
                s1 += v0 + v1; s2 += v0 * v0 + v1 * v1;
            }
            atomicAdd(&rsum[row], s1);
            atomicAdd(&rsq[row],  s2);
        }
    }
    __syncthreads();

    if (EPI == 1) {
        #pragma unroll
        for (int mt = 0; mt < 2; mt++) {
            #pragma unroll
            for (int half = 0; half < 2; half++) {
                int row = wr * 32 + mt * 16 + (lane >> 2) + half * 8;
                int v = sv[row];
                float mean = rsum[row] * (1.f / CDIM);
                float var  = rsq[row] * (1.f / CDIM) - mean * mean;
                float inv  = rsqrtf(var + 1e-5f);
                #pragma unroll
                for (int nt = 0; nt < 6; nt++) {
                    int c = wc * 48 + nt * 8 + 2 * (lane & 3);
                    float2 o;
                    o.x = (acc[mt][nt][half * 2 + 0] - mean) * inv * e_g1[c]     + e_b1[c];
                    o.y = (acc[mt][nt][half * 2 + 1] - mean) * inv * e_g1[c + 1] + e_b1[c + 1];
                    *(float2*)&C[(size_t)v * CDIM + c] = o;
                }
            }
        }
        return;
    }

    // EPI == 2: LN2 then +src then LN3
    float su1[4], su2[4];
    #pragma unroll
    for (int mt = 0; mt < 2; mt++) {
        #pragma unroll
        for (int half = 0; half < 2; half++) {
            int row = wr * 32 + mt * 16 + (lane >> 2) + half * 8;
            float mean = rsum[row] * (1.f / CDIM);
            float var  = rsq[row] * (1.f / CDIM) - mean * mean;
            float inv  = rsqrtf(var + 1e-5f);
            float s1 = 0.f, s2 = 0.f;
            #pragma unroll
            for (int nt = 0; nt < 6; nt++) {
                int c = wc * 48 + nt * 8 + 2 * (lane & 3);
                float2 sr = *(const float2*)&e_src[(size_t)(row0 + row) * CDIM + c];
                float u0 = (acc[mt][nt][half * 2 + 0] - mean) * inv * e_g1[c]     + e_b1[c]     + sr.x;
                float u1 = (acc[mt][nt][half * 2 + 1] - mean) * inv * e_g1[c + 1] + e_b1[c + 1] + sr.y;
                acc[mt][nt][half * 2 + 0] = u0;
                acc[mt][nt][half * 2 + 1] = u1;
                s1 += u0 + u1; s2 += u0 * u0 + u1 * u1;
            }
            su1[mt * 2 + half] = s1;
            su2[mt * 2 + half] = s2;
        }
    }
    __syncthreads();  // all rsum/rsq reads done
    if (tid < 128) { rsum[tid] = 0.f; rsq[tid] = 0.f; }
    __syncthreads();
    #pragma unroll
    for (int mt = 0; mt < 2; mt++) {
        #pragma unroll
        for (int half = 0; half < 2; half++) {
            int row = wr * 32 + mt * 16 + (lane >> 2) + half * 8;
            atomicAdd(&rsum[row], su1[mt * 2 + half]);
            atomicAdd(&rsq[row],  su2[mt * 2 + half]);
        }
    }
    __syncthreads();
    #pragma unroll
    for (int mt = 0; mt < 2; mt++) {
        #pragma unroll
        for (int half = 0; half < 2; half++) {
            int row = wr * 32 + mt * 16 + (lane >> 2) + half * 8;
            float mean = rsum[row] * (1.f / CDIM);
            float var  = rsq[row] * (1.f / CDIM) - mean * mean;
            float inv  = rsqrtf(var + 1e-5f);
            #pragma unroll
            for (int nt = 0; nt < 6; nt++) {
                int c = wc * 48 + nt * 8 + 2 * (lane & 3);
                float2 o;
                o.x = (acc[mt][nt][half * 2 + 0] - mean) * inv * e_g2[c]     + e_b2[c];
                o.y = (acc[mt][nt][half * 2 + 1] - mean) * inv * e_g2[c + 1] + e_b2[c + 1];
                *(float2*)&C[(size_t)(row0 + row) * CDIM + c] = o;
            }
        }
    }
}

// ---------------- attention: 192 threads = 4 (set,head) pairs ---------------
__global__ void __launch_bounds__(192)
attn_kernel(const uint8_t* __restrict__ mask)
{
    const int p   = threadIdx.x / SETSZ;   // pair slot 0..3
    const int i   = threadIdx.x % SETSZ;   // row 0..47
    const int gp  = blockIdx.x * 4 + p;
    const int s   = gp >> 3;
    const int h   = gp & 7;

    __shared__ float ks[4][SETSZ][28];
    __shared__ float vs[4][SETSZ][28];
    __shared__ float mf[4][SETSZ];

    const size_t ro = (size_t)s * SETSZ + i;
    const float* qrow = &g_qk[ro * (2 * CDIM) + h * HD];

    float4 q[6];
    #pragma unroll
    for (int t = 0; t < 6; t++) {
        q[t] = *(const float4*)&qrow[t * 4];
        float4 kk = *(const float4*)&qrow[CDIM + t * 4];
        *(float4*)&ks[p][i][t * 4] = kk;
        float4 vv = *(const float4*)&g_v[ro * CDIM + h * HD + t * 4];
        *(float4*)&vs[p][i][t * 4] = vv;
    }
    mf[p][i] = (mask[(size_t)s * SETSZ + i] != 0) ? -1e9f : 0.f;
    __syncthreads();

    const float scale = 0.20412414523193154f; // 1/sqrt(24)
    float sc[SETSZ];
    #pragma unroll 8
    for (int j = 0; j < SETSZ; j++) {
        float4 k0 = *(const float4*)&ks[p][j][0];
        float4 k1 = *(const float4*)&ks[p][j][4];
        float4 k2 = *(const float4*)&ks[p][j][8];
        float4 k3 = *(const float4*)&ks[p][j][12];
        float4 k4 = *(const float4*)&ks[p][j][16];
        float4 k5 = *(const float4*)&ks[p][j][20];
        float a0 = q[0].x * k0.x + q[0].y * k0.y + q[0].z * k0.z + q[0].w * k0.w;
        float a1 = q[1].x * k1.x + q[1].y * k1.y + q[1].z * k1.z + q[1].w * k1.w;
        float a2 = q[2].x * k2.x + q[2].y * k2.y + q[2].z * k2.z + q[2].w * k2.w;
        float a3 = q[3].x * k3.x + q[3].y * k3.y + q[3].z * k3.z + q[3].w * k3.w;
        float a4 = q[4].x * k4.x + q[4].y * k4.y + q[4].z * k4.z + q[4].w * k4.w;
        float a5 = q[5].x * k5.x + q[5].y * k5.y + q[5].z * k5.z + q[5].w * k5.w;
        sc[j] = ((a0 + a1) + (a2 + a3) + (a4 + a5)) * scale + mf[p][j];
    }

    float m = -1e30f;
    #pragma unroll
    for (int j = 0; j < SETSZ; j++) m = fmaxf(m, sc[j]);
    float sum = 0.f;
    #pragma unroll
    for (int j = 0; j < SETSZ; j++) { float e = __expf(sc[j] - m); sc[j] = e; sum += e; }
    float inv = 1.f / sum;

    float4 o[6];
    #pragma unroll
    for (int t = 0; t < 6; t++) { o[t].x = 0.f; o[t].y = 0.f; o[t].z = 0.f; o[t].w = 0.f; }
    #pragma unroll 4
    for (int j = 0; j < SETSZ; j++) {
        float pr = sc[j] * inv;
        #pragma unroll
        for (int t = 0; t < 6; t++) {
            float4 v4 = *(const float4*)&vs[p][j][t * 4];
            o[t].x += pr * v4.x; o[t].y += pr * v4.y;
            o[t].z += pr * v4.z; o[t].w += pr * v4.w;
        }
    }
    float* crow = &g_ctx[ro * CDIM + h * HD];
    #pragma unroll
    for (int t = 0; t < 6; t++) *(float4*)&crow[t * 4] = o[t];
}

// ---------------- launch --------------------------------------------------
extern "C" void kernel_launch(void* const* d_in, const int* in_sizes, int n_in,
                              void* d_out, int out_size)
{
    const float* src   = (const float*)d_in[0];
    const float* pos   = (const float*)d_in[1];
    const float* w_qkv = (const float*)d_in[2];
    const float* b_qkv = (const float*)d_in[3];
    const float* w_out = (const float*)d_in[4];
    const float* b_out = (const float*)d_in[5];
    const float* w1    = (const float*)d_in[6];
    const float* b1    = (const float*)d_in[7];
    const float* w2    = (const float*)d_in[8];
    const float* b2    = (const float*)d_in[9];
    const float* ln1g  = (const float*)d_in[10];
    const float* ln1b  = (const float*)d_in[11];
    const float* ln2g  = (const float*)d_in[12];
    const float* ln2b  = (const float*)d_in[13];
    const float* ln3g  = (const float*)d_in[14];
    const float* ln3b  = (const float*)d_in[15];
    const int*   vidx  = (const int*)d_in[16];
    const uint8_t* msk = (const uint8_t*)d_in[17];
    float* out = (float*)d_out;

    float *p_qk, *p_v, *p_ctx, *p_x, *p_h;
    cudaGetSymbolAddress((void**)&p_qk,  g_qk);
    cudaGetSymbolAddress((void**)&p_v,   g_v);
    cudaGetSymbolAddress((void**)&p_ctx, g_ctx);
    cudaGetSymbolAddress((void**)&p_x,   g_x);
    cudaGetSymbolAddress((void**)&p_h,   g_h);

    cudaFuncSetAttribute(gemm_bf16x3<0,1,0>, cudaFuncAttributeMaxDynamicSharedMemorySize, GEMM_SMEM_BYTES);
    cudaFuncSetAttribute(gemm_bf16x3<0,2,0>, cudaFuncAttributeMaxDynamicSharedMemorySize, GEMM_SMEM_BYTES);
    cudaFuncSetAttribute(gemm_bf16x3<0,0,1>, cudaFuncAttributeMaxDynamicSharedMemorySize, GEMM_SMEM_BYTES);
    cudaFuncSetAttribute(gemm_bf16x3<1,0,0>, cudaFuncAttributeMaxDynamicSharedMemorySize, GEMM_SMEM_BYTES);
    cudaFuncSetAttribute(gemm_bf16x3<0,0,2>, cudaFuncAttributeMaxDynamicSharedMemorySize, GEMM_SMEM_BYTES);

    const int MB = NVOX / 128;  // 1536

    // 1) q,k projection with fused gather (src+pos): (N x 384)
    gemm_bf16x3<0,1,0><<<dim3(MB, 2), 512, GEMM_SMEM_BYTES>>>(
        src, pos, vidx, w_qkv, b_qkv, p_qk,
        nullptr, nullptr, nullptr, nullptr, nullptr, nullptr,
        NVOX, 2 * CDIM, CDIM);

    // 2) v projection with fused gather (src): (N x 192)
    gemm_bf16x3<0,2,0><<<dim3(MB, 1), 512, GEMM_SMEM_BYTES>>>(
        src, nullptr, vidx, w_qkv + (size_t)2 * CDIM * CDIM, b_qkv + 2 * CDIM, p_v,
        nullptr, nullptr, nullptr, nullptr, nullptr, nullptr,
        NVOX, CDIM, CDIM);

    // 3) attention
    attn_kernel<<<(SETS * NHEAD) / 4, 192>>>(msk);

    // 4) output projection + fused scatter + residual + LN1 -> g_x (voxel order)
    gemm_bf16x3<0,0,1><<<dim3(MB, 1), 512, GEMM_SMEM_BYTES>>>(
        p_ctx, nullptr, vidx, w_out, b_out, p_x,
        src, nullptr, ln1g, ln1b, nullptr, nullptr,
        NVOX, CDIM, CDIM);

    // 5) FFN1 (relu)
    gemm_bf16x3<1,0,0><<<dim3(MB, 2), 512, GEMM_SMEM_BYTES>>>(
        p_x, nullptr, nullptr, w1, b1, p_h,
        nullptr, nullptr, nullptr, nullptr, nullptr, nullptr,
        NVOX, DFF, CDIM);

    // 6) FFN2 + fused LN2 + residual + LN3 -> out
    gemm_bf16x3<0,0,2><<<dim3(MB, 1), 512, GEMM_SMEM_BYTES>>>(
        p_h, nullptr, nullptr, w2, b2, out,
        src, p_x, ln2g, ln2b, ln3g, ln3b,
        NVOX, CDIM, DFF);
}

// round 5
// speedup vs baseline: 1.2814x; 1.0686x over previous
#include <cuda_runtime.h>
#include <cuda_bf16.h>
#include <cstdint>
#include <cstddef>

// ---------------- problem constants ----------------
#define NVOX   196608
#define CDIM   192
#define SETS   4096
#define SETSZ  48
#define NHEAD  8
#define HD     24
#define DFF    384

// ---------------- scratch (device globals) ----------------
__device__ float g_qk [(size_t)NVOX * 2 * CDIM]; // q cols 0..191, k 192..383 (set-slot order)
__device__ float g_v  [(size_t)NVOX * CDIM];
__device__ float g_ctx[(size_t)NVOX * CDIM];
__device__ float g_x  [(size_t)NVOX * CDIM];     // after LN1, voxel order
__device__ float g_h  [(size_t)NVOX * DFF];

// ---------------- bf16x3 tensor-core GEMM, BM=128 BN=192 BK=32, 512 thr ----
// Double-buffered smem + ldmatrix fragment loads.
// C[m,n] = sum_k A[m,k]*B[n,k] + bias[n]
// GATHER: 0 none | 1 A=src[vidx]+pos[vidx] | 2 A=src[vidx]
// EPI: 0 plain(+RELU) | 1 LN1 scatter | 2 LN2+res+LN3
#define ASTR 20  // u32 row stride (16 data pairs + 4 pad) -> ldmatrix conflict-free

#define OFF_AH 0
#define OFF_AL (128 * ASTR)
#define OFF_BH (256 * ASTR)
#define OFF_BL (448 * ASTR)
#define STAGE_U32 (640 * ASTR)            // 12800 u32 per stage
#define OFF_SV (2 * STAGE_U32)            // vidx cache
#define GEMM_SMEM_BYTES ((OFF_SV + 128) * 4)

__device__ __forceinline__ void split_pack(float x, float y, uint32_t& h, uint32_t& l)
{
    __nv_bfloat162 h2 = __floats2bfloat162_rn(x, y);
    h = *reinterpret_cast<const uint32_t*>(&h2);
    float rx = x - __bfloat162float(h2.x);
    float ry = y - __bfloat162float(h2.y);
    __nv_bfloat162 l2 = __floats2bfloat162_rn(rx, ry);
    l = *reinterpret_cast<const uint32_t*>(&l2);
}

__device__ __forceinline__ void mma_bf16(float c[4],
    uint32_t a0, uint32_t a1, uint32_t a2, uint32_t a3,
    uint32_t b0, uint32_t b1)
{
    asm volatile(
        "mma.sync.aligned.m16n8k16.row.col.f32.bf16.bf16.f32 "
        "{%0,%1,%2,%3}, {%4,%5,%6,%7}, {%8,%9}, {%0,%1,%2,%3};\n"
        : "+f"(c[0]), "+f"(c[1]), "+f"(c[2]), "+f"(c[3])
        : "r"(a0), "r"(a1), "r"(a2), "r"(a3), "r"(b0), "r"(b1));
}

__device__ __forceinline__ void ldsm_x4(uint32_t& r0, uint32_t& r1,
                                        uint32_t& r2, uint32_t& r3, uint32_t addr)
{
    asm volatile("ldmatrix.sync.aligned.m8n8.x4.shared.b16 {%0,%1,%2,%3}, [%4];"
                 : "=r"(r0), "=r"(r1), "=r"(r2), "=r"(r3) : "r"(addr));
}

template <int RELU, int GATHER, int EPI>
__global__ void __launch_bounds__(512)
gemm_bf16x3(const float* __restrict__ A, const float* __restrict__ A2,
            const int* __restrict__ vidx,
            const float* __restrict__ B, const float* __restrict__ bias,
            float* __restrict__ C,
            const float* __restrict__ e_src, const float* __restrict__ e_x,
            const float* __restrict__ e_g1, const float* __restrict__ e_b1,
            const float* __restrict__ e_g2, const float* __restrict__ e_b2,
            int M, int N, int K)
{
    extern __shared__ uint32_t sm[];
    int* sv = (int*)(sm + OFF_SV);

    const int tid  = threadIdx.x;
    const int lane = tid & 31;
    const int warp = tid >> 5;
    const int wr   = warp >> 2;   // 0..3 -> m offset 32*wr
    const int wc   = warp & 3;    // 0..3 -> n offset 48*wc
    const int row0 = blockIdx.x * 128;
    const int col0 = blockIdx.y * 192;

    if (GATHER || EPI == 1) {
        if (tid < 128) sv[tid] = vidx[row0 + tid];
        __syncthreads();
    }

    float acc[2][6][4];
    #pragma unroll
    for (int m = 0; m < 2; m++)
        #pragma unroll
        for (int n = 0; n < 6; n++)
            #pragma unroll
            for (int i = 0; i < 4; i++) acc[m][n][i] = 0.f;

    const int ar = tid >> 3;   // 0..63
    const int ac = tid & 7;    // 0..7 (float4 col)

    auto ldA = [&](int kk, int rr) -> float4 {
        int row = ar + rr * 64;
        if (GATHER) {
            int vr = sv[row];
            float4 v = *(const float4*)&A[(size_t)vr * K + kk + ac * 4];
            if (GATHER == 1) {
                float4 p = *(const float4*)&A2[(size_t)vr * K + kk + ac * 4];
                v.x += p.x; v.y += p.y; v.z += p.z; v.w += p.w;
            }
            return v;
        }
        return *(const float4*)&A[(size_t)(row0 + row) * K + kk + ac * 4];
    };
    auto ldB = [&](int kk, int rr) -> float4 {
        return *(const float4*)&B[(size_t)(col0 + ar + rr * 64) * K + kk + ac * 4];
    };
    auto store_stage = [&](int st, float4 pa0, float4 pa1,
                           float4 pb0, float4 pb1, float4 pb2) {
        uint32_t* Ah = sm + st * STAGE_U32 + OFF_AH;
        uint32_t* Al = sm + st * STAGE_U32 + OFF_AL;
        uint32_t* Bh = sm + st * STAGE_U32 + OFF_BH;
        uint32_t* Bl = sm + st * STAGE_U32 + OFF_BL;
        uint32_t h0, l0, h1, l1;
        split_pack(pa0.x, pa0.y, h0, l0); split_pack(pa0.z, pa0.w, h1, l1);
        Ah[ar * ASTR + ac * 2] = h0; Ah[ar * ASTR + ac * 2 + 1] = h1;
        Al[ar * ASTR + ac * 2] = l0; Al[ar * ASTR + ac * 2 + 1] = l1;
        split_pack(pa1.x, pa1.y, h0, l0); split_pack(pa1.z, pa1.w, h1, l1);
        Ah[(ar + 64) * ASTR + ac * 2] = h0; Ah[(ar + 64) * ASTR + ac * 2 + 1] = h1;
        Al[(ar + 64) * ASTR + ac * 2] = l0; Al[(ar + 64) * ASTR + ac * 2 + 1] = l1;
        split_pack(pb0.x, pb0.y, h0, l0); split_pack(pb0.z, pb0.w, h1, l1);
        Bh[ar * ASTR + ac * 2] = h0; Bh[ar * ASTR + ac * 2 + 1] = h1;
        Bl[ar * ASTR + ac * 2] = l0; Bl[ar * ASTR + ac * 2 + 1] = l1;
        split_pack(pb1.x, pb1.y, h0, l0); split_pack(pb1.z, pb1.w, h1, l1);
        Bh[(ar + 64) * ASTR + ac * 2] = h0; Bh[(ar + 64) * ASTR + ac * 2 + 1] = h1;
        Bl[(ar + 64) * ASTR + ac * 2] = l0; Bl[(ar + 64) * ASTR + ac * 2 + 1] = l1;
        split_pack(pb2.x, pb2.y, h0, l0); split_pack(pb2.z, pb2.w, h1, l1);
        Bh[(ar + 128) * ASTR + ac * 2] = h0; Bh[(ar + 128) * ASTR + ac * 2 + 1] = h1;
        Bl[(ar + 128) * ASTR + ac * 2] = l0; Bl[(ar + 128) * ASTR + ac * 2 + 1] = l1;
    };

    const uint32_t sbase = (uint32_t)__cvta_generic_to_shared(sm);
    // ldmatrix lane address components (verified fragment mapping)
    const int a_row = wr * 32 + (lane & 7) + ((lane >> 3) & 1) * 8;
    const int a_cb  = ((lane >> 4) & 1) * 4;
    const int b_row = wc * 48 + (lane & 7) + ((lane >> 4) & 1) * 8;
    const int b_cb  = ((lane >> 3) & 1) * 4;

    // prologue: tile 0
    float4 pa0 = ldA(0, 0), pa1 = ldA(0, 1);
    float4 pb0 = ldB(0, 0), pb1 = ldB(0, 1), pb2 = ldB(0, 2);
    store_stage(0, pa0, pa1, pb0, pb1, pb2);
    __syncthreads();

    const int nk = K >> 5;
    for (int it = 0; it < nk; it++) {
        const int st = it & 1;
        // prefetch next tile from global (overlaps MMA)
        if (it + 1 < nk) {
            int kk = (it + 1) * 32;
            pa0 = ldA(kk, 0); pa1 = ldA(kk, 1);
            pb0 = ldB(kk, 0); pb1 = ldB(kk, 1); pb2 = ldB(kk, 2);
        }
        const uint32_t stAh = sbase + (st * STAGE_U32 + OFF_AH) * 4;
        const uint32_t stAl = sbase + (st * STAGE_U32 + OFF_AL) * 4;
        const uint32_t stBh = sbase + (st * STAGE_U32 + OFF_BH) * 4;
        const uint32_t stBl = sbase + (st * STAGE_U32 + OFF_BL) * 4;

        #pragma unroll
        for (int k16 = 0; k16 < 2; k16++) {
            const int kp = k16 * 8;
            uint32_t ah[2][4], al[2][4];
            #pragma unroll
            for (int mt = 0; mt < 2; mt++) {
                uint32_t off = (uint32_t)(((a_row + mt * 16) * ASTR + kp + a_cb) * 4);
                ldsm_x4(ah[mt][0], ah[mt][1], ah[mt][2], ah[mt][3], stAh + off);
                ldsm_x4(al[mt][0], al[mt][1], al[mt][2], al[mt][3], stAl + off);
            }
            uint32_t bh[12], bl[12];
            #pragma unroll
            for (int p = 0; p < 3; p++) {
                uint32_t off = (uint32_t)(((b_row + p * 16) * ASTR + kp + b_cb) * 4);
                ldsm_x4(bh[p * 4 + 0], bh[p * 4 + 1], bh[p * 4 + 2], bh[p * 4 + 3], stBh + off);
                ldsm_x4(bl[p * 4 + 0], bl[p * 4 + 1], bl[p * 4 + 2], bl[p * 4 + 3], stBl + off);
            }
            #pragma unroll
            for (int nt = 0; nt < 6; nt++) {
                uint32_t bh0 = bh[nt * 2], bh1 = bh[nt * 2 + 1];
                uint32_t bl0 = bl[nt * 2], bl1 = bl[nt * 2 + 1];
                #pragma unroll
                for (int mt = 0; mt < 2; mt++) {
                    mma_bf16(acc[mt][nt], ah[mt][0], ah[mt][1], ah[mt][2], ah[mt][3], bh0, bh1);
                    mma_bf16(acc[mt][nt], ah[mt][0], ah[mt][1], ah[mt][2], ah[mt][3], bl0, bl1);
                    mma_bf16(acc[mt][nt], al[mt][0], al[mt][1], al[mt][2], al[mt][3], bh0, bh1);
                }
            }
        }
        // store prefetched tile into the other stage
        if (it + 1 < nk) store_stage(st ^ 1, pa0, pa1, pb0, pb1, pb2);
        __syncthreads();
    }

    // ================= epilogue =================
    if (EPI == 0) {
        #pragma unroll
        for (int mt = 0; mt < 2; mt++) {
            int r0 = row0 + wr * 32 + mt * 16 + (lane >> 2);
            #pragma unroll
            for (int nt = 0; nt < 6; nt++) {
                int c = col0 + wc * 48 + nt * 8 + 2 * (lane & 3);
                float bx = bias[c], by = bias[c + 1];
                float2 o0, o1;
                o0.x = acc[mt][nt][0] + bx; o0.y = acc[mt][nt][1] + by;
                o1.x = acc[mt][nt][2] + bx; o1.y = acc[mt][nt][3] + by;
                if (RELU) {
                    o0.x = fmaxf(o0.x, 0.f); o0.y = fmaxf(o0.y, 0.f);
                    o1.x = fmaxf(o1.x, 0.f); o1.y = fmaxf(o1.y, 0.f);
                }
                *(float2*)&C[(size_t)r0 * N + c]       = o0;
                *(float2*)&C[(size_t)(r0 + 8) * N + c] = o1;
            }
        }
        return;
    }

    // LN epilogues: N == 192 (full row per block), col0 == 0
    float* rsum = (float*)sm;         // [128]
    float* rsq  = (float*)sm + 128;   // [128]
    if (tid < 128) { rsum[tid] = 0.f; rsq[tid] = 0.f; }
    __syncthreads();

    #pragma unroll
    for (int mt = 0; mt < 2; mt++) {
        #pragma unroll
        for (int half = 0; half < 2; half++) {
            int row = wr * 32 + mt * 16 + (lane >> 2) + half * 8;
            float s1 = 0.f, s2 = 0.f;
            #pragma unroll
            for (int nt = 0; nt < 6; nt++) {
                int c = wc * 48 + nt * 8 + 2 * (lane & 3);
                float2 res;
                if (EPI == 1) {
                    int v = sv[row];
                    res = *(const float2*)&e_src[(size_t)v * CDIM + c];
                } else {
                    res = *(const float2*)&e_x[(size_t)(row0 + row) * CDIM + c];
                }
                float v0 = acc[mt][nt][half * 2 + 0] + bias[c]     + res.x;
                float v1 = acc[mt][nt][half * 2 + 1] + bias[c + 1] + res.y;
                acc[mt][nt][half * 2 + 0] = v0;
                acc[mt][nt][half * 2 + 1] = v1;
                s1 += v0 + v1; s2 += v0 * v0 + v1 * v1;
            }
            atomicAdd(&rsum[row], s1);
            atomicAdd(&rsq[row],  s2);
        }
    }
    __syncthreads();

    if (EPI == 1) {
        #pragma unroll
        for (int mt = 0; mt < 2; mt++) {
            #pragma unroll
            for (int half = 0; half < 2; half++) {
                int row = wr * 32 + mt * 16 + (lane >> 2) + half * 8;
                int v = sv[row];
                float mean = rsum[row] * (1.f / CDIM);
                float var  = rsq[row] * (1.f / CDIM) - mean * mean;
                float inv  = rsqrtf(var + 1e-5f);
                #pragma unroll
                for (int nt = 0; nt < 6; nt++) {
                    int c = wc * 48 + nt * 8 + 2 * (lane & 3);
                    float2 o;
                    o.x = (acc[mt][nt][half * 2 + 0] - mean) * inv * e_g1[c]     + e_b1[c];
                    o.y = (acc[mt][nt][half * 2 + 1] - mean) * inv * e_g1[c + 1] + e_b1[c + 1];
                    *(float2*)&C[(size_t)v * CDIM + c] = o;
                }
            }
        }
        return;
    }

    // EPI == 2: LN2 then +src then LN3
    float su1[4], su2[4];
    #pragma unroll
    for (int mt = 0; mt < 2; mt++) {
        #pragma unroll
        for (int half = 0; half < 2; half++) {
            int row = wr * 32 + mt * 16 + (lane >> 2) + half * 8;
            float mean = rsum[row] * (1.f / CDIM);
            float var  = rsq[row] * (1.f / CDIM) - mean * mean;
            float inv  = rsqrtf(var + 1e-5f);
            float s1 = 0.f, s2 = 0.f;
            #pragma unroll
            for (int nt = 0; nt < 6; nt++) {
                int c = wc * 48 + nt * 8 + 2 * (lane & 3);
                float2 sr = *(const float2*)&e_src[(size_t)(row0 + row) * CDIM + c];
                float u0 = (acc[mt][nt][half * 2 + 0] - mean) * inv * e_g1[c]     + e_b1[c]     + sr.x;
                float u1 = (acc[mt][nt][half * 2 + 1] - mean) * inv * e_g1[c + 1] + e_b1[c + 1] + sr.y;
                acc[mt][nt][half * 2 + 0] = u0;
                acc[mt][nt][half * 2 + 1] = u1;
                s1 += u0 + u1; s2 += u0 * u0 + u1 * u1;
            }
            su1[mt * 2 + half] = s1;
            su2[mt * 2 + half] = s2;
        }
    }
    __syncthreads();
    if (tid < 128) { rsum[tid] = 0.f; rsq[tid] = 0.f; }
    __syncthreads();
    #pragma unroll
    for (int mt = 0; mt < 2; mt++) {
        #pragma unroll
        for (int half = 0; half < 2; half++) {
            int row = wr * 32 + mt * 16 + (lane >> 2) + half * 8;
            atomicAdd(&rsum[row], su1[mt * 2 + half]);
            atomicAdd(&rsq[row],  su2[mt * 2 + half]);
        }
    }
    __syncthreads();
    #pragma unroll
    for (int mt = 0; mt < 2; mt++) {
        #pragma unroll
        for (int half = 0; half < 2; half++) {
            int row = wr * 32 + mt * 16 + (lane >> 2) + half * 8;
            float mean = rsum[row] * (1.f / CDIM);
            float var  = rsq[row] * (1.f / CDIM) - mean * mean;
            float inv  = rsqrtf(var + 1e-5f);
            #pragma unroll
            for (int nt = 0; nt < 6; nt++) {
                int c = wc * 48 + nt * 8 + 2 * (lane & 3);
                float2 o;
                o.x = (acc[mt][nt][half * 2 + 0] - mean) * inv * e_g2[c]     + e_b2[c];
                o.y = (acc[mt][nt][half * 2 + 1] - mean) * inv * e_g2[c + 1] + e_b2[c + 1];
                *(float2*)&C[(size_t)(row0 + row) * CDIM + c] = o;
            }
        }
    }
}

// ---------------- attention: 192 threads = 4 (set,head) pairs ---------------
__global__ void __launch_bounds__(192)
attn_kernel(const uint8_t* __restrict__ mask)
{
    const int p   = threadIdx.x / SETSZ;
    const int i   = threadIdx.x % SETSZ;
    const int gp  = blockIdx.x * 4 + p;
    const int s   = gp >> 3;
    const int h   = gp & 7;

    __shared__ float ks[4][SETSZ][28];
    __shared__ float vs[4][SETSZ][28];
    __shared__ float mf[4][SETSZ];

    const size_t ro = (size_t)s * SETSZ + i;
    const float* qrow = &g_qk[ro * (2 * CDIM) + h * HD];

    float4 q[6];
    #pragma unroll
    for (int t = 0; t < 6; t++) {
        q[t] = *(const float4*)&qrow[t * 4];
        float4 kk = *(const float4*)&qrow[CDIM + t * 4];
        *(float4*)&ks[p][i][t * 4] = kk;
        float4 vv = *(const float4*)&g_v[ro * CDIM + h * HD + t * 4];
        *(float4*)&vs[p][i][t * 4] = vv;
    }
    mf[p][i] = (mask[(size_t)s * SETSZ + i] != 0) ? -1e9f : 0.f;
    __syncthreads();

    const float scale = 0.20412414523193154f; // 1/sqrt(24)
    float sc[SETSZ];
    #pragma unroll 8
    for (int j = 0; j < SETSZ; j++) {
        float4 k0 = *(const float4*)&ks[p][j][0];
        float4 k1 = *(const float4*)&ks[p][j][4];
        float4 k2 = *(const float4*)&ks[p][j][8];
        float4 k3 = *(const float4*)&ks[p][j][12];
        float4 k4 = *(const float4*)&ks[p][j][16];
        float4 k5 = *(const float4*)&ks[p][j][20];
        float a0 = q[0].x * k0.x + q[0].y * k0.y + q[0].z * k0.z + q[0].w * k0.w;
        float a1 = q[1].x * k1.x + q[1].y * k1.y + q[1].z * k1.z + q[1].w * k1.w;
        float a2 = q[2].x * k2.x + q[2].y * k2.y + q[2].z * k2.z + q[2].w * k2.w;
        float a3 = q[3].x * k3.x + q[3].y * k3.y + q[3].z * k3.z + q[3].w * k3.w;
        float a4 = q[4].x * k4.x + q[4].y * k4.y + q[4].z * k4.z + q[4].w * k4.w;
        float a5 = q[5].x * k5.x + q[5].y * k5.y + q[5].z * k5.z + q[5].w * k5.w;
        sc[j] = ((a0 + a1) + (a2 + a3) + (a4 + a5)) * scale + mf[p][j];
    }

    float m = -1e30f;
    #pragma unroll
    for (int j = 0; j < SETSZ; j++) m = fmaxf(m, sc[j]);
    float sum = 0.f;
    #pragma unroll
    for (int j = 0; j < SETSZ; j++) { float e = __expf(sc[j] - m); sc[j] = e; sum += e; }
    float inv = 1.f / sum;

    float4 o[6];
    #pragma unroll
    for (int t = 0; t < 6; t++) { o[t].x = 0.f; o[t].y = 0.f; o[t].z = 0.f; o[t].w = 0.f; }
    #pragma unroll 4
    for (int j = 0; j < SETSZ; j++) {
        float pr = sc[j] * inv;
        #pragma unroll
        for (int t = 0; t < 6; t++) {
            float4 v4 = *(const float4*)&vs[p][j][t * 4];
            o[t].x += pr * v4.x; o[t].y += pr * v4.y;
            o[t].z += pr * v4.z; o[t].w += pr * v4.w;
        }
    }
    float* crow = &g_ctx[ro * CDIM + h * HD];
    #pragma unroll
    for (int t = 0; t < 6; t++) *(float4*)&crow[t * 4] = o[t];
}

// ---------------- launch --------------------------------------------------
extern "C" void kernel_launch(void* const* d_in, const int* in_sizes, int n_in,
                              void* d_out, int out_size)
{
    const float* src   = (const float*)d_in[0];
    const float* pos   = (const float*)d_in[1];
    const float* w_qkv = (const float*)d_in[2];
    const float* b_qkv = (const float*)d_in[3];
    const float* w_out = (const float*)d_in[4];
    const float* b_out = (const float*)d_in[5];
    const float* w1    = (const float*)d_in[6];
    const float* b1    = (const float*)d_in[7];
    const float* w2    = (const float*)d_in[8];
    const float* b2    = (const float*)d_in[9];
    const float* ln1g  = (const float*)d_in[10];
    const float* ln1b  = (const float*)d_in[11];
    const float* ln2g  = (const float*)d_in[12];
    const float* ln2b  = (const float*)d_in[13];
    const float* ln3g  = (const float*)d_in[14];
    const float* ln3b  = (const float*)d_in[15];
    const int*   vidx  = (const int*)d_in[16];
    const uint8_t* msk = (const uint8_t*)d_in[17];
    float* out = (float*)d_out;

    float *p_qk, *p_v, *p_ctx, *p_x, *p_h;
    cudaGetSymbolAddress((void**)&p_qk,  g_qk);
    cudaGetSymbolAddress((void**)&p_v,   g_v);
    cudaGetSymbolAddress((void**)&p_ctx, g_ctx);
    cudaGetSymbolAddress((void**)&p_x,   g_x);
    cudaGetSymbolAddress((void**)&p_h,   g_h);

    cudaFuncSetAttribute(gemm_bf16x3<0,1,0>, cudaFuncAttributeMaxDynamicSharedMemorySize, GEMM_SMEM_BYTES);
    cudaFuncSetAttribute(gemm_bf16x3<0,2,0>, cudaFuncAttributeMaxDynamicSharedMemorySize, GEMM_SMEM_BYTES);
    cudaFuncSetAttribute(gemm_bf16x3<0,0,1>, cudaFuncAttributeMaxDynamicSharedMemorySize, GEMM_SMEM_BYTES);
    cudaFuncSetAttribute(gemm_bf16x3<1,0,0>, cudaFuncAttributeMaxDynamicSharedMemorySize, GEMM_SMEM_BYTES);
    cudaFuncSetAttribute(gemm_bf16x3<0,0,2>, cudaFuncAttributeMaxDynamicSharedMemorySize, GEMM_SMEM_BYTES);

    const int MB = NVOX / 128;  // 1536

    // 1) q,k projection with fused gather (src+pos): (N x 384)
    gemm_bf16x3<0,1,0><<<dim3(MB, 2), 512, GEMM_SMEM_BYTES>>>(
        src, pos, vidx, w_qkv, b_qkv, p_qk,
        nullptr, nullptr, nullptr, nullptr, nullptr, nullptr,
        NVOX, 2 * CDIM, CDIM);

    // 2) v projection with fused gather (src): (N x 192)
    gemm_bf16x3<0,2,0><<<dim3(MB, 1), 512, GEMM_SMEM_BYTES>>>(
        src, nullptr, vidx, w_qkv + (size_t)2 * CDIM * CDIM, b_qkv + 2 * CDIM, p_v,
        nullptr, nullptr, nullptr, nullptr, nullptr, nullptr,
        NVOX, CDIM, CDIM);

    // 3) attention
    attn_kernel<<<(SETS * NHEAD) / 4, 192>>>(msk);

    // 4) output projection + fused scatter + residual + LN1 -> g_x (voxel order)
    gemm_bf16x3<0,0,1><<<dim3(MB, 1), 512, GEMM_SMEM_BYTES>>>(
        p_ctx, nullptr, vidx, w_out, b_out, p_x,
        src, nullptr, ln1g, ln1b, nullptr, nullptr,
        NVOX, CDIM, CDIM);

    // 5) FFN1 (relu)
    gemm_bf16x3<1,0,0><<<dim3(MB, 2), 512, GEMM_SMEM_BYTES>>>(
        p_x, nullptr, nullptr, w1, b1, p_h,
        nullptr, nullptr, nullptr, nullptr, nullptr, nullptr,
        NVOX, DFF, CDIM);

    // 6) FFN2 + fused LN2 + residual + LN3 -> out
    gemm_bf16x3<0,0,2><<<dim3(MB, 1), 512, GEMM_SMEM_BYTES>>>(
        p_h, nullptr, nullptr, w2, b2, out,
        src, p_x, ln2g, ln2b, ln3g, ln3b,
        NVOX, CDIM, DFF);
}

// round 6
// speedup vs baseline: 1.2820x; 1.0004x over previous
#include <cuda_runtime.h>
#include <cuda_bf16.h>
#include <cstdint>
#include <cstddef>

// ---------------- problem constants ----------------
#define NVOX   196608
#define CDIM   192
#define SETS   4096
#define SETSZ  48
#define NHEAD  8
#define HD     24
#define DFF    384

// ---------------- scratch (device globals) ----------------
__device__ float g_qk [(size_t)NVOX * 2 * CDIM]; // q cols 0..191, k 192..383 (set-slot order)
__device__ float g_v  [(size_t)NVOX * CDIM];
__device__ float g_ctx[(size_t)NVOX * CDIM];
__device__ float g_x  [(size_t)NVOX * CDIM];     // after LN1, voxel order
__device__ float g_h  [(size_t)NVOX * DFF];

// ---------------- bf16x3 tensor-core GEMM, BM=64 BN=192 BK=32, 256 thr ----
// 2 CTAs/SM; double-buffered smem + ldmatrix fragment loads.
// C[m,n] = sum_k A[m,k]*B[n,k] + bias[n]
// GATHER: 0 none | 1 A=src[vidx]+pos[vidx] | 2 A=src[vidx]
// EPI: 0 plain(+RELU) | 1 LN1 scatter | 2 LN2+res+LN3
#define ASTR 20  // u32 row stride (16 data pairs + 4 pad) -> ldmatrix conflict-free

#define OFF_AH 0
#define OFF_AL (64 * ASTR)
#define OFF_BH (128 * ASTR)
#define OFF_BL (320 * ASTR)
#define STAGE_U32 (512 * ASTR)            // 10240 u32 per stage (40.96 KB)
#define OFF_SV (2 * STAGE_U32)            // vidx cache (64 ints)
#define GEMM_SMEM_BYTES ((OFF_SV + 64) * 4)

__device__ __forceinline__ void split_pack(float x, float y, uint32_t& h, uint32_t& l)
{
    __nv_bfloat162 h2 = __floats2bfloat162_rn(x, y);
    h = *reinterpret_cast<const uint32_t*>(&h2);
    float rx = x - __bfloat162float(h2.x);
    float ry = y - __bfloat162float(h2.y);
    __nv_bfloat162 l2 = __floats2bfloat162_rn(rx, ry);
    l = *reinterpret_cast<const uint32_t*>(&l2);
}

__device__ __forceinline__ void mma_bf16(float c[4],
    uint32_t a0, uint32_t a1, uint32_t a2, uint32_t a3,
    uint32_t b0, uint32_t b1)
{
    asm volatile(
        "mma.sync.aligned.m16n8k16.row.col.f32.bf16.bf16.f32 "
        "{%0,%1,%2,%3}, {%4,%5,%6,%7}, {%8,%9}, {%0,%1,%2,%3};\n"
        : "+f"(c[0]), "+f"(c[1]), "+f"(c[2]), "+f"(c[3])
        : "r"(a0), "r"(a1), "r"(a2), "r"(a3), "r"(b0), "r"(b1));
}

__device__ __forceinline__ void ldsm_x4(uint32_t& r0, uint32_t& r1,
                                        uint32_t& r2, uint32_t& r3, uint32_t addr)
{
    asm volatile("ldmatrix.sync.aligned.m8n8.x4.shared.b16 {%0,%1,%2,%3}, [%4];"
                 : "=r"(r0), "=r"(r1), "=r"(r2), "=r"(r3) : "r"(addr));
}

template <int RELU, int GATHER, int EPI>
__global__ void __launch_bounds__(256, 2)
gemm_bf16x3(const float* __restrict__ A, const float* __restrict__ A2,
            const int* __restrict__ vidx,
            const float* __restrict__ B, const float* __restrict__ bias,
            float* __restrict__ C,
            const float* __restrict__ e_src, const float* __restrict__ e_x,
            const float* __restrict__ e_g1, const float* __restrict__ e_b1,
            const float* __restrict__ e_g2, const float* __restrict__ e_b2,
            int M, int N, int K)
{
    extern __shared__ uint32_t sm[];
    int* sv = (int*)(sm + OFF_SV);

    const int tid  = threadIdx.x;
    const int lane = tid & 31;
    const int warp = tid >> 5;
    const int wr   = warp >> 2;   // 0..1 -> m offset 32*wr
    const int wc   = warp & 3;    // 0..3 -> n offset 48*wc
    const int row0 = blockIdx.x * 64;
    const int col0 = blockIdx.y * 192;

    if (GATHER || EPI == 1) {
        if (tid < 64) sv[tid] = vidx[row0 + tid];
        __syncthreads();
    }

    float acc[2][6][4];
    #pragma unroll
    for (int m = 0; m < 2; m++)
        #pragma unroll
        for (int n = 0; n < 6; n++)
            #pragma unroll
            for (int i = 0; i < 4; i++) acc[m][n][i] = 0.f;

    const int ar = tid >> 3;   // 0..31
    const int ac = tid & 7;    // 0..7 (float4 col)

    auto ldA = [&](int kk, int rr) -> float4 {
        int row = ar + rr * 32;
        if (GATHER) {
            int vr = sv[row];
            float4 v = *(const float4*)&A[(size_t)vr * K + kk + ac * 4];
            if (GATHER == 1) {
                float4 p = *(const float4*)&A2[(size_t)vr * K + kk + ac * 4];
                v.x += p.x; v.y += p.y; v.z += p.z; v.w += p.w;
            }
            return v;
        }
        return *(const float4*)&A[(size_t)(row0 + row) * K + kk + ac * 4];
    };
    auto ldB = [&](int kk, int rr) -> float4 {
        return *(const float4*)&B[(size_t)(col0 + ar + rr * 32) * K + kk + ac * 4];
    };
    auto store_stage = [&](int st, const float4* pa, const float4* pb) {
        uint32_t* Ah = sm + st * STAGE_U32 + OFF_AH;
        uint32_t* Al = sm + st * STAGE_U32 + OFF_AL;
        uint32_t* Bh = sm + st * STAGE_U32 + OFF_BH;
        uint32_t* Bl = sm + st * STAGE_U32 + OFF_BL;
        uint32_t h0, l0, h1, l1;
        #pragma unroll
        for (int r = 0; r < 2; r++) {
            int row = ar + r * 32;
            split_pack(pa[r].x, pa[r].y, h0, l0); split_pack(pa[r].z, pa[r].w, h1, l1);
            Ah[row * ASTR + ac * 2] = h0; Ah[row * ASTR + ac * 2 + 1] = h1;
            Al[row * ASTR + ac * 2] = l0; Al[row * ASTR + ac * 2 + 1] = l1;
        }
        #pragma unroll
        for (int r = 0; r < 6; r++) {
            int row = ar + r * 32;
            split_pack(pb[r].x, pb[r].y, h0, l0); split_pack(pb[r].z, pb[r].w, h1, l1);
            Bh[row * ASTR + ac * 2] = h0; Bh[row * ASTR + ac * 2 + 1] = h1;
            Bl[row * ASTR + ac * 2] = l0; Bl[row * ASTR + ac * 2 + 1] = l1;
        }
    };

    const uint32_t sbase = (uint32_t)__cvta_generic_to_shared(sm);
    // ldmatrix lane address components (verified fragment mapping)
    const int a_row = wr * 32 + (lane & 7) + ((lane >> 3) & 1) * 8;
    const int a_cb  = ((lane >> 4) & 1) * 4;
    const int b_row = wc * 48 + (lane & 7) + ((lane >> 4) & 1) * 8;
    const int b_cb  = ((lane >> 3) & 1) * 4;

    // prologue: tile 0
    float4 pa[2], pb[6];
    #pragma unroll
    for (int r = 0; r < 2; r++) pa[r] = ldA(0, r);
    #pragma unroll
    for (int r = 0; r < 6; r++) pb[r] = ldB(0, r);
    store_stage(0, pa, pb);
    __syncthreads();

    const int nk = K >> 5;
    for (int it = 0; it < nk; it++) {
        const int st = it & 1;
        if (it + 1 < nk) {
            int kk = (it + 1) * 32;
            #pragma unroll
            for (int r = 0; r < 2; r++) pa[r] = ldA(kk, r);
            #pragma unroll
            for (int r = 0; r < 6; r++) pb[r] = ldB(kk, r);
        }
        const uint32_t stAh = sbase + (st * STAGE_U32 + OFF_AH) * 4;
        const uint32_t stAl = sbase + (st * STAGE_U32 + OFF_AL) * 4;
        const uint32_t stBh = sbase + (st * STAGE_U32 + OFF_BH) * 4;
        const uint32_t stBl = sbase + (st * STAGE_U32 + OFF_BL) * 4;

        #pragma unroll
        for (int k16 = 0; k16 < 2; k16++) {
            const int kp = k16 * 8;
            uint32_t ah[4], al[4];
            {
                uint32_t off = (uint32_t)(((a_row) * ASTR + kp + a_cb) * 4);
                ldsm_x4(ah[0], ah[1], ah[2], ah[3], stAh + off);
                ldsm_x4(al[0], al[1], al[2], al[3], stAl + off);
            }
            uint32_t ah2[4], al2[4];
            {
                uint32_t off = (uint32_t)(((a_row + 16) * ASTR + kp + a_cb) * 4);
                ldsm_x4(ah2[0], ah2[1], ah2[2], ah2[3], stAh + off);
                ldsm_x4(al2[0], al2[1], al2[2], al2[3], stAl + off);
            }
            uint32_t bh[12], bl[12];
            #pragma unroll
            for (int p = 0; p < 3; p++) {
                uint32_t off = (uint32_t)(((b_row + p * 16) * ASTR + kp + b_cb) * 4);
                ldsm_x4(bh[p * 4 + 0], bh[p * 4 + 1], bh[p * 4 + 2], bh[p * 4 + 3], stBh + off);
                ldsm_x4(bl[p * 4 + 0], bl[p * 4 + 1], bl[p * 4 + 2], bl[p * 4 + 3], stBl + off);
            }
            #pragma unroll
            for (int nt = 0; nt < 6; nt++) {
                uint32_t bh0 = bh[nt * 2], bh1 = bh[nt * 2 + 1];
                uint32_t bl0 = bl[nt * 2], bl1 = bl[nt * 2 + 1];
                mma_bf16(acc[0][nt], ah[0], ah[1], ah[2], ah[3], bh0, bh1);
                mma_bf16(acc[0][nt], ah[0], ah[1], ah[2], ah[3], bl0, bl1);
                mma_bf16(acc[0][nt], al[0], al[1], al[2], al[3], bh0, bh1);
                mma_bf16(acc[1][nt], ah2[0], ah2[1], ah2[2], ah2[3], bh0, bh1);
                mma_bf16(acc[1][nt], ah2[0], ah2[1], ah2[2], ah2[3], bl0, bl1);
                mma_bf16(acc[1][nt], al2[0], al2[1], al2[2], al2[3], bh0, bh1);
            }
        }
        if (it + 1 < nk) store_stage(st ^ 1, pa, pb);
        __syncthreads();
    }

    // ================= epilogue =================
    if (EPI == 0) {
        #pragma unroll
        for (int mt = 0; mt < 2; mt++) {
            int r0 = row0 + wr * 32 + mt * 16 + (lane >> 2);
            #pragma unroll
            for (int nt = 0; nt < 6; nt++) {
                int c = col0 + wc * 48 + nt * 8 + 2 * (lane & 3);
                float bx = bias[c], by = bias[c + 1];
                float2 o0, o1;
                o0.x = acc[mt][nt][0] + bx; o0.y = acc[mt][nt][1] + by;
                o1.x = acc[mt][nt][2] + bx; o1.y = acc[mt][nt][3] + by;
                if (RELU) {
                    o0.x = fmaxf(o0.x, 0.f); o0.y = fmaxf(o0.y, 0.f);
                    o1.x = fmaxf(o1.x, 0.f); o1.y = fmaxf(o1.y, 0.f);
                }
                *(float2*)&C[(size_t)r0 * N + c]       = o0;
                *(float2*)&C[(size_t)(r0 + 8) * N + c] = o1;
            }
        }
        return;
    }

    // LN epilogues: N == 192 (full row per block), col0 == 0
    float* rsum = (float*)sm;        // [64]
    float* rsq  = (float*)sm + 64;   // [64]
    if (tid < 64) { rsum[tid] = 0.f; rsq[tid] = 0.f; }
    __syncthreads();

    #pragma unroll
    for (int mt = 0; mt < 2; mt++) {
        #pragma unroll
        for (int half = 0; half < 2; half++) {
            int row = wr * 32 + mt * 16 + (lane >> 2) + half * 8;
            float s1 = 0.f, s2 = 0.f;
            #pragma unroll
            for (int nt = 0; nt < 6; nt++) {
                int c = wc * 48 + nt * 8 + 2 * (lane & 3);
                float2 res;
                if (EPI == 1) {
                    int v = sv[row];
                    res = *(const float2*)&e_src[(size_t)v * CDIM + c];
                } else {
                    res = *(const float2*)&e_x[(size_t)(row0 + row) * CDIM + c];
                }
                float v0 = acc[mt][nt][half * 2 + 0] + bias[c]     + res.x;
                float v1 = acc[mt][nt][half * 2 + 1] + bias[c + 1] + res.y;
                acc[mt][nt][half * 2 + 0] = v0;
                acc[mt][nt][half * 2 + 1] = v1;
                s1 += v0 + v1; s2 += v0 * v0 + v1 * v1;
            }
            atomicAdd(&rsum[row], s1);
            atomicAdd(&rsq[row],  s2);
        }
    }
    __syncthreads();

    if (EPI == 1) {
        #pragma unroll
        for (int mt = 0; mt < 2; mt++) {
            #pragma unroll
            for (int half = 0; half < 2; half++) {
                int row = wr * 32 + mt * 16 + (lane >> 2) + half * 8;
                int v = sv[row];
                float mean = rsum[row] * (1.f / CDIM);
                float var  = rsq[row] * (1.f / CDIM) - mean * mean;
                float inv  = rsqrtf(var + 1e-5f);
                #pragma unroll
                for (int nt = 0; nt < 6; nt++) {
                    int c = wc * 48 + nt * 8 + 2 * (lane & 3);
                    float2 o;
                    o.x = (acc[mt][nt][half * 2 + 0] - mean) * inv * e_g1[c]     + e_b1[c];
                    o.y = (acc[mt][nt][half * 2 + 1] - mean) * inv * e_g1[c + 1] + e_b1[c + 1];
                    *(float2*)&C[(size_t)v * CDIM + c] = o;
                }
            }
        }
        return;
    }

    // EPI == 2: LN2 then +src then LN3
    float su1[4], su2[4];
    #pragma unroll
    for (int mt = 0; mt < 2; mt++) {
        #pragma unroll
        for (int half = 0; half < 2; half++) {
            int row = wr * 32 + mt * 16 + (lane >> 2) + half * 8;
            float mean = rsum[row] * (1.f / CDIM);
            float var  = rsq[row] * (1.f / CDIM) - mean * mean;
            float inv  = rsqrtf(var + 1e-5f);
            float s1 = 0.f, s2 = 0.f;
            #pragma unroll
            for (int nt = 0; nt < 6; nt++) {
                int c = wc * 48 + nt * 8 + 2 * (lane & 3);
                float2 sr = *(const float2*)&e_src[(size_t)(row0 + row) * CDIM + c];
                float u0 = (acc[mt][nt][half * 2 + 0] - mean) * inv * e_g1[c]     + e_b1[c]     + sr.x;
                float u1 = (acc[mt][nt][half * 2 + 1] - mean) * inv * e_g1[c + 1] + e_b1[c + 1] + sr.y;
                acc[mt][nt][half * 2 + 0] = u0;
                acc[mt][nt][half * 2 + 1] = u1;
                s1 += u0 + u1; s2 += u0 * u0 + u1 * u1;
            }
            su1[mt * 2 + half] = s1;
            su2[mt * 2 + half] = s2;
        }
    }
    __syncthreads();
    if (tid < 64) { rsum[tid] = 0.f; rsq[tid] = 0.f; }
    __syncthreads();
    #pragma unroll
    for (int mt = 0; mt < 2; mt++) {
        #pragma unroll
        for (int half = 0; half < 2; half++) {
            int row = wr * 32 + mt * 16 + (lane >> 2) + half * 8;
            atomicAdd(&rsum[row], su1[mt * 2 + half]);
            atomicAdd(&rsq[row],  su2[mt * 2 + half]);
        }
    }
    __syncthreads();
    #pragma unroll
    for (int mt = 0; mt < 2; mt++) {
        #pragma unroll
        for (int half = 0; half < 2; half++) {
            int row = wr * 32 + mt * 16 + (lane >> 2) + half * 8;
            float mean = rsum[row] * (1.f / CDIM);
            float var  = rsq[row] * (1.f / CDIM) - mean * mean;
            float inv  = rsqrtf(var + 1e-5f);
            #pragma unroll
            for (int nt = 0; nt < 6; nt++) {
                int c = wc * 48 + nt * 8 + 2 * (lane & 3);
                float2 o;
                o.x = (acc[mt][nt][half * 2 + 0] - mean) * inv * e_g2[c]     + e_b2[c];
                o.y = (acc[mt][nt][half * 2 + 1] - mean) * inv * e_g2[c + 1] + e_b2[c + 1];
                *(float2*)&C[(size_t)(row0 + row) * CDIM + c] = o;
            }
        }
    }
}

// ---------------- attention: 192 threads = 4 (set,head) pairs ---------------
__global__ void __launch_bounds__(192)
attn_kernel(const uint8_t* __restrict__ mask)
{
    const int p   = threadIdx.x / SETSZ;
    const int i   = threadIdx.x % SETSZ;
    const int gp  = blockIdx.x * 4 + p;
    const int s   = gp >> 3;
    const int h   = gp & 7;

    __shared__ float ks[4][SETSZ][28];
    __shared__ float vs[4][SETSZ][28];
    __shared__ float mf[4][SETSZ];

    const size_t ro = (size_t)s * SETSZ + i;
    const float* qrow = &g_qk[ro * (2 * CDIM) + h * HD];

    float4 q[6];
    #pragma unroll
    for (int t = 0; t < 6; t++) {
        q[t] = *(const float4*)&qrow[t * 4];
        float4 kk = *(const float4*)&qrow[CDIM + t * 4];
        *(float4*)&ks[p][i][t * 4] = kk;
        float4 vv = *(const float4*)&g_v[ro * CDIM + h * HD + t * 4];
        *(float4*)&vs[p][i][t * 4] = vv;
    }
    mf[p][i] = (mask[(size_t)s * SETSZ + i] != 0) ? -1e9f : 0.f;
    __syncthreads();

    const float scale = 0.20412414523193154f; // 1/sqrt(24)
    float sc[SETSZ];
    #pragma unroll 8
    for (int j = 0; j < SETSZ; j++) {
        float4 k0 = *(const float4*)&ks[p][j][0];
        float4 k1 = *(const float4*)&ks[p][j][4];
        float4 k2 = *(const float4*)&ks[p][j][8];
        float4 k3 = *(const float4*)&ks[p][j][12];
        float4 k4 = *(const float4*)&ks[p][j][16];
        float4 k5 = *(const float4*)&ks[p][j][20];
        float a0 = q[0].x * k0.x + q[0].y * k0.y + q[0].z * k0.z + q[0].w * k0.w;
        float a1 = q[1].x * k1.x + q[1].y * k1.y + q[1].z * k1.z + q[1].w * k1.w;
        float a2 = q[2].x * k2.x + q[2].y * k2.y + q[2].z * k2.z + q[2].w * k2.w;
        float a3 = q[3].x * k3.x + q[3].y * k3.y + q[3].z * k3.z + q[3].w * k3.w;
        float a4 = q[4].x * k4.x + q[4].y * k4.y + q[4].z * k4.z + q[4].w * k4.w;
        float a5 = q[5].x * k5.x + q[5].y * k5.y + q[5].z * k5.z + q[5].w * k5.w;
        sc[j] = ((a0 + a1) + (a2 + a3) + (a4 + a5)) * scale + mf[p][j];
    }

    float m = -1e30f;
    #pragma unroll
    for (int j = 0; j < SETSZ; j++) m = fmaxf(m, sc[j]);
    float sum = 0.f;
    #pragma unroll
    for (int j = 0; j < SETSZ; j++) { float e = __expf(sc[j] - m); sc[j] = e; sum += e; }
    float inv = 1.f / sum;

    float4 o[6];
    #pragma unroll
    for (int t = 0; t < 6; t++) { o[t].x = 0.f; o[t].y = 0.f; o[t].z = 0.f; o[t].w = 0.f; }
    #pragma unroll 4
    for (int j = 0; j < SETSZ; j++) {
        float pr = sc[j] * inv;
        #pragma unroll
        for (int t = 0; t < 6; t++) {
            float4 v4 = *(const float4*)&vs[p][j][t * 4];
            o[t].x += pr * v4.x; o[t].y += pr * v4.y;
            o[t].z += pr * v4.z; o[t].w += pr * v4.w;
        }
    }
    float* crow = &g_ctx[ro * CDIM + h * HD];
    #pragma unroll
    for (int t = 0; t < 6; t++) *(float4*)&crow[t * 4] = o[t];
}

// ---------------- launch --------------------------------------------------
extern "C" void kernel_launch(void* const* d_in, const int* in_sizes, int n_in,
                              void* d_out, int out_size)
{
    const float* src   = (const float*)d_in[0];
    const float* pos   = (const float*)d_in[1];
    const float* w_qkv = (const float*)d_in[2];
    const float* b_qkv = (const float*)d_in[3];
    const float* w_out = (const float*)d_in[4];
    const float* b_out = (const float*)d_in[5];
    const float* w1    = (const float*)d_in[6];
    const float* b1    = (const float*)d_in[7];
    const float* w2    = (const float*)d_in[8];
    const float* b2    = (const float*)d_in[9];
    const float* ln1g  = (const float*)d_in[10];
    const float* ln1b  = (const float*)d_in[11];
    const float* ln2g  = (const float*)d_in[12];
    const float* ln2b  = (const float*)d_in[13];
    const float* ln3g  = (const float*)d_in[14];
    const float* ln3b  = (const float*)d_in[15];
    const int*   vidx  = (const int*)d_in[16];
    const uint8_t* msk = (const uint8_t*)d_in[17];
    float* out = (float*)d_out;

    float *p_qk, *p_v, *p_ctx, *p_x, *p_h;
    cudaGetSymbolAddress((void**)&p_qk,  g_qk);
    cudaGetSymbolAddress((void**)&p_v,   g_v);
    cudaGetSymbolAddress((void**)&p_ctx, g_ctx);
    cudaGetSymbolAddress((void**)&p_x,   g_x);
    cudaGetSymbolAddress((void**)&p_h,   g_h);

    cudaFuncSetAttribute(gemm_bf16x3<0,1,0>, cudaFuncAttributeMaxDynamicSharedMemorySize, GEMM_SMEM_BYTES);
    cudaFuncSetAttribute(gemm_bf16x3<0,2,0>, cudaFuncAttributeMaxDynamicSharedMemorySize, GEMM_SMEM_BYTES);
    cudaFuncSetAttribute(gemm_bf16x3<0,0,1>, cudaFuncAttributeMaxDynamicSharedMemorySize, GEMM_SMEM_BYTES);
    cudaFuncSetAttribute(gemm_bf16x3<1,0,0>, cudaFuncAttributeMaxDynamicSharedMemorySize, GEMM_SMEM_BYTES);
    cudaFuncSetAttribute(gemm_bf16x3<0,0,2>, cudaFuncAttributeMaxDynamicSharedMemorySize, GEMM_SMEM_BYTES);

    const int MB = NVOX / 64;  // 3072

    // 1) q,k projection with fused gather (src+pos): (N x 384)
    gemm_bf16x3<0,1,0><<<dim3(MB, 2), 256, GEMM_SMEM_BYTES>>>(
        src, pos, vidx, w_qkv, b_qkv, p_qk,
        nullptr, nullptr, nullptr, nullptr, nullptr, nullptr,
        NVOX, 2 * CDIM, CDIM);

    // 2) v projection with fused gather (src): (N x 192)
    gemm_bf16x3<0,2,0><<<dim3(MB, 1), 256, GEMM_SMEM_BYTES>>>(
        src, nullptr, vidx, w_qkv + (size_t)2 * CDIM * CDIM, b_qkv + 2 * CDIM, p_v,
        nullptr, nullptr, nullptr, nullptr, nullptr, nullptr,
        NVOX, CDIM, CDIM);

    // 3) attention
    attn_kernel<<<(SETS * NHEAD) / 4, 192>>>(msk);

    // 4) output projection + fused scatter + residual + LN1 -> g_x (voxel order)
    gemm_bf16x3<0,0,1><<<dim3(MB, 1), 256, GEMM_SMEM_BYTES>>>(
        p_ctx, nullptr, vidx, w_out, b_out, p_x,
        src, nullptr, ln1g, ln1b, nullptr, nullptr,
        NVOX, CDIM, CDIM);

    // 5) FFN1 (relu)
    gemm_bf16x3<1,0,0><<<dim3(MB, 2), 256, GEMM_SMEM_BYTES>>>(
        p_x, nullptr, nullptr, w1, b1, p_h,
        nullptr, nullptr, nullptr, nullptr, nullptr, nullptr,
        NVOX, DFF, CDIM);

    // 6) FFN2 + fused LN2 + residual + LN3 -> out
    gemm_bf16x3<0,0,2><<<dim3(MB, 1), 256, GEMM_SMEM_BYTES>>>(
        p_h, nullptr, nullptr, w2, b2, out,
        src, p_x, ln2g, ln2b, ln3g, ln3b,
        NVOX, CDIM, DFF);
}

// round 8
// speedup vs baseline: 1.5539x; 1.2121x over previous
#include <cuda_runtime.h>
#include <cuda_bf16.h>
#include <cstdint>
#include <cstddef>

// ---------------- problem constants ----------------
#define NVOX   196608
#define CDIM   192
#define SETS   4096
#define SETSZ  48
#define NHEAD  8
#define HD     24
#define DFF    384

// ---------------- scratch (device globals) ----------------
__device__ float g_qk [(size_t)NVOX * 2 * CDIM]; // q cols 0..191, k 192..383 (set-slot order)
__device__ float g_v  [(size_t)NVOX * CDIM];
__device__ float g_ctx[(size_t)NVOX * CDIM];
__device__ float g_x  [(size_t)NVOX * CDIM];     // after LN1, voxel order
__device__ float g_h  [(size_t)NVOX * DFF];

// ---------------- bf16x2 tensor-core GEMM, BM=64 BN=192 BK=32, 256 thr ----
// A fp32 split hi+lo bf16 (exact); B rounded to bf16 (weights-in-bf16).
// C[m,n] = sum_k A[m,k]*B[n,k] + bias[n]
// GATHER: 0 none | 1 A=src[vidx]+pos[vidx] | 2 A=src[vidx]
// EPI: 0 plain(+RELU) | 1 LN1 scatter | 2 LN2+res+LN3
#define ASTR 20  // u32 row stride (16 data pairs + 4 pad) -> ldmatrix conflict-free

#define OFF_AH 0
#define OFF_AL (64 * ASTR)
#define OFF_BH (128 * ASTR)
#define STAGE_U32 (320 * ASTR)            // 6400 u32 per stage (25.6 KB)
#define OFF_SV (2 * STAGE_U32)            // vidx cache (64 ints)
#define GEMM_SMEM_BYTES ((OFF_SV + 64) * 4)

__device__ __forceinline__ void split_pack(float x, float y, uint32_t& h, uint32_t& l)
{
    __nv_bfloat162 h2 = __floats2bfloat162_rn(x, y);
    h = *reinterpret_cast<const uint32_t*>(&h2);
    float rx = x - __bfloat162float(h2.x);
    float ry = y - __bfloat162float(h2.y);
    __nv_bfloat162 l2 = __floats2bfloat162_rn(rx, ry);
    l = *reinterpret_cast<const uint32_t*>(&l2);
}
__device__ __forceinline__ uint32_t pack_bf16(float x, float y)
{
    __nv_bfloat162 h2 = __floats2bfloat162_rn(x, y);
    return *reinterpret_cast<const uint32_t*>(&h2);
}

__device__ __forceinline__ void mma_bf16(float c[4],
    uint32_t a0, uint32_t a1, uint32_t a2, uint32_t a3,
    uint32_t b0, uint32_t b1)
{
    asm volatile(
        "mma.sync.aligned.m16n8k16.row.col.f32.bf16.bf16.f32 "
        "{%0,%1,%2,%3}, {%4,%5,%6,%7}, {%8,%9}, {%0,%1,%2,%3};\n"
        : "+f"(c[0]), "+f"(c[1]), "+f"(c[2]), "+f"(c[3])
        : "r"(a0), "r"(a1), "r"(a2), "r"(a3), "r"(b0), "r"(b1));
}

__device__ __forceinline__ void ldsm_x4(uint32_t& r0, uint32_t& r1,
                                        uint32_t& r2, uint32_t& r3, uint32_t addr)
{
    asm volatile("ldmatrix.sync.aligned.m8n8.x4.shared.b16 {%0,%1,%2,%3}, [%4];"
                 : "=r"(r0), "=r"(r1), "=r"(r2), "=r"(r3) : "r"(addr));
}

template <int RELU, int GATHER, int EPI>
__global__ void __launch_bounds__(256, 2)
gemm_bf16x2(const float* __restrict__ A, const float* __restrict__ A2,
            const int* __restrict__ vidx,
            const float* __restrict__ B, const float* __restrict__ bias,
            float* __restrict__ C,
            const float* __restrict__ e_src, const float* __restrict__ e_x,
            const float* __restrict__ e_g1, const float* __restrict__ e_b1,
            const float* __restrict__ e_g2, const float* __restrict__ e_b2,
            int M, int N, int K)
{
    extern __shared__ uint32_t sm[];
    int* sv = (int*)(sm + OFF_SV);

    const int tid  = threadIdx.x;
    const int lane = tid & 31;
    const int warp = tid >> 5;
    const int wr   = warp >> 2;   // 0..1 -> m offset 32*wr
    const int wc   = warp & 3;    // 0..3 -> n offset 48*wc
    const int row0 = blockIdx.x * 64;
    const int col0 = blockIdx.y * 192;

    if (GATHER || EPI == 1) {
        if (tid < 64) sv[tid] = vidx[row0 + tid];
        __syncthreads();
    }

    float acc[2][6][4];
    #pragma unroll
    for (int m = 0; m < 2; m++)
        #pragma unroll
        for (int n = 0; n < 6; n++)
            #pragma unroll
            for (int i = 0; i < 4; i++) acc[m][n][i] = 0.f;

    const int ar = tid >> 3;   // 0..31
    const int ac = tid & 7;    // 0..7 (float4 col)

    auto ldA = [&](int kk, int rr) -> float4 {
        int row = ar + rr * 32;
        if (GATHER) {
            int vr = sv[row];
            float4 v = *(const float4*)&A[(size_t)vr * K + kk + ac * 4];
            if (GATHER == 1) {
                float4 p = *(const float4*)&A2[(size_t)vr * K + kk + ac * 4];
                v.x += p.x; v.y += p.y; v.z += p.z; v.w += p.w;
            }
            return v;
        }
        return *(const float4*)&A[(size_t)(row0 + row) * K + kk + ac * 4];
    };
    auto ldB = [&](int kk, int rr) -> float4 {
        return *(const float4*)&B[(size_t)(col0 + ar + rr * 32) * K + kk + ac * 4];
    };
    auto store_stage = [&](int st, const float4* pa, const float4* pb) {
        uint32_t* Ah = sm + st * STAGE_U32 + OFF_AH;
        uint32_t* Al = sm + st * STAGE_U32 + OFF_AL;
        uint32_t* Bh = sm + st * STAGE_U32 + OFF_BH;
        uint32_t h0, l0, h1, l1;
        #pragma unroll
        for (int r = 0; r < 2; r++) {
            int row = ar + r * 32;
            split_pack(pa[r].x, pa[r].y, h0, l0); split_pack(pa[r].z, pa[r].w, h1, l1);
            Ah[row * ASTR + ac * 2] = h0; Ah[row * ASTR + ac * 2 + 1] = h1;
            Al[row * ASTR + ac * 2] = l0; Al[row * ASTR + ac * 2 + 1] = l1;
        }
        #pragma unroll
        for (int r = 0; r < 6; r++) {
            int row = ar + r * 32;
            Bh[row * ASTR + ac * 2]     = pack_bf16(pb[r].x, pb[r].y);
            Bh[row * ASTR + ac * 2 + 1] = pack_bf16(pb[r].z, pb[r].w);
        }
    };

    const uint32_t sbase = (uint32_t)__cvta_generic_to_shared(sm);
    // ldmatrix lane address components (verified fragment mapping)
    const int a_row = wr * 32 + (lane & 7) + ((lane >> 3) & 1) * 8;
    const int a_cb  = ((lane >> 4) & 1) * 4;
    const int b_row = wc * 48 + (lane & 7) + ((lane >> 4) & 1) * 8;
    const int b_cb  = ((lane >> 3) & 1) * 4;

    // prologue: tile 0
    float4 pa[2], pb[6];
    #pragma unroll
    for (int r = 0; r < 2; r++) pa[r] = ldA(0, r);
    #pragma unroll
    for (int r = 0; r < 6; r++) pb[r] = ldB(0, r);
    store_stage(0, pa, pb);
    __syncthreads();

    const int nk = K >> 5;
    for (int it = 0; it < nk; it++) {
        const int st = it & 1;
        if (it + 1 < nk) {
            int kk = (it + 1) * 32;
            #pragma unroll
            for (int r = 0; r < 2; r++) pa[r] = ldA(kk, r);
            #pragma unroll
            for (int r = 0; r < 6; r++) pb[r] = ldB(kk, r);
        }
        const uint32_t stAh = sbase + (st * STAGE_U32 + OFF_AH) * 4;
        const uint32_t stAl = sbase + (st * STAGE_U32 + OFF_AL) * 4;
        const uint32_t stBh = sbase + (st * STAGE_U32 + OFF_BH) * 4;

        #pragma unroll
        for (int k16 = 0; k16 < 2; k16++) {
            const int kp = k16 * 8;
            uint32_t ah[4], al[4], ah2[4], al2[4];
            {
                uint32_t off = (uint32_t)(((a_row) * ASTR + kp + a_cb) * 4);
                ldsm_x4(ah[0], ah[1], ah[2], ah[3], stAh + off);
                ldsm_x4(al[0], al[1], al[2], al[3], stAl + off);
            }
            {
                uint32_t off = (uint32_t)(((a_row + 16) * ASTR + kp + a_cb) * 4);
                ldsm_x4(ah2[0], ah2[1], ah2[2], ah2[3], stAh + off);
                ldsm_x4(al2[0], al2[1], al2[2], al2[3], stAl + off);
            }
            uint32_t bh[12];
            #pragma unroll
            for (int p = 0; p < 3; p++) {
                uint32_t off = (uint32_t)(((b_row + p * 16) * ASTR + kp + b_cb) * 4);
                ldsm_x4(bh[p * 4 + 0], bh[p * 4 + 1], bh[p * 4 + 2], bh[p * 4 + 3], stBh + off);
            }
            #pragma unroll
            for (int nt = 0; nt < 6; nt++) {
                uint32_t bh0 = bh[nt * 2], bh1 = bh[nt * 2 + 1];
                mma_bf16(acc[0][nt], ah[0],  ah[1],  ah[2],  ah[3],  bh0, bh1);
                mma_bf16(acc[0][nt], al[0],  al[1],  al[2],  al[3],  bh0, bh1);
                mma_bf16(acc[1][nt], ah2[0], ah2[1], ah2[2], ah2[3], bh0, bh1);
                mma_bf16(acc[1][nt], al2[0], al2[1], al2[2], al2[3], bh0, bh1);
            }
        }
        if (it + 1 < nk) store_stage(st ^ 1, pa, pb);
        __syncthreads();
    }

    // ================= epilogue =================
    if (EPI == 0) {
        #pragma unroll
        for (int mt = 0; mt < 2; mt++) {
            int r0 = row0 + wr * 32 + mt * 16 + (lane >> 2);
            #pragma unroll
            for (int nt = 0; nt < 6; nt++) {
                int c = col0 + wc * 48 + nt * 8 + 2 * (lane & 3);
                float bx = bias[c], by = bias[c + 1];
                float2 o0, o1;
                o0.x = acc[mt][nt][0] + bx; o0.y = acc[mt][nt][1] + by;
                o1.x = acc[mt][nt][2] + bx; o1.y = acc[mt][nt][3] + by;
                if (RELU) {
                    o0.x = fmaxf(o0.x, 0.f); o0.y = fmaxf(o0.y, 0.f);
                    o1.x = fmaxf(o1.x, 0.f); o1.y = fmaxf(o1.y, 0.f);
                }
                *(float2*)&C[(size_t)r0 * N + c]       = o0;
                *(float2*)&C[(size_t)(r0 + 8) * N + c] = o1;
            }
        }
        return;
    }

    // LN epilogues: N == 192 (full row per block), col0 == 0
    float* rsum = (float*)sm;        // [64]
    float* rsq  = (float*)sm + 64;   // [64]
    if (tid < 64) { rsum[tid] = 0.f; rsq[tid] = 0.f; }
    __syncthreads();

    #pragma unroll
    for (int mt = 0; mt < 2; mt++) {
        #pragma unroll
        for (int half = 0; half < 2; half++) {
            int row = wr * 32 + mt * 16 + (lane >> 2) + half * 8;
            float s1 = 0.f, s2 = 0.f;
            #pragma unroll
            for (int nt = 0; nt < 6; nt++) {
                int c = wc * 48 + nt * 8 + 2 * (lane & 3);
                float2 res;
                if (EPI == 1) {
                    int v = sv[row];
                    res = *(const float2*)&e_src[(size_t)v * CDIM + c];
                } else {
                    res = *(const float2*)&e_x[(size_t)(row0 + row) * CDIM + c];
                }
                float v0 = acc[mt][nt][half * 2 + 0] + bias[c]     + res.x;
                float v1 = acc[mt][nt][half * 2 + 1] + bias[c + 1] + res.y;
                acc[mt][nt][half * 2 + 0] = v0;
                acc[mt][nt][half * 2 + 1] = v1;
                s1 += v0 + v1; s2 += v0 * v0 + v1 * v1;
            }
            atomicAdd(&rsum[row], s1);
            atomicAdd(&rsq[row],  s2);
        }
    }
    __syncthreads();

    if (EPI == 1) {
        #pragma unroll
        for (int mt = 0; mt < 2; mt++) {
            #pragma unroll
            for (int half = 0; half < 2; half++) {
                int row = wr * 32 + mt * 16 + (lane >> 2) + half * 8;
                int v = sv[row];
                float mean = rsum[row] * (1.f / CDIM);
                float var  = rsq[row] * (1.f / CDIM) - mean * mean;
                float inv  = rsqrtf(var + 1e-5f);
                #pragma unroll
                for (int nt = 0; nt < 6; nt++) {
                    int c = wc * 48 + nt * 8 + 2 * (lane & 3);
                    float2 o;
                    o.x = (acc[mt][nt][half * 2 + 0] - mean) * inv * e_g1[c]     + e_b1[c];
                    o.y = (acc[mt][nt][half * 2 + 1] - mean) * inv * e_g1[c + 1] + e_b1[c + 1];
                    *(float2*)&C[(size_t)v * CDIM + c] = o;
                }
            }
        }
        return;
    }

    // EPI == 2: LN2 then +src then LN3
    float su1[4], su2[4];
    #pragma unroll
    for (int mt = 0; mt < 2; mt++) {
        #pragma unroll
        for (int half = 0; half < 2; half++) {
            int row = wr * 32 + mt * 16 + (lane >> 2) + half * 8;
            float mean = rsum[row] * (1.f / CDIM);
            float var  = rsq[row] * (1.f / CDIM) - mean * mean;
            float inv  = rsqrtf(var + 1e-5f);
            float s1 = 0.f, s2 = 0.f;
            #pragma unroll
            for (int nt = 0; nt < 6; nt++) {
                int c = wc * 48 + nt * 8 + 2 * (lane & 3);
                float2 sr = *(const float2*)&e_src[(size_t)(row0 + row) * CDIM + c];
                float u0 = (acc[mt][nt][half * 2 + 0] - mean) * inv * e_g1[c]     + e_b1[c]     + sr.x;
                float u1 = (acc[mt][nt][half * 2 + 1] - mean) * inv * e_g1[c + 1] + e_b1[c + 1] + sr.y;
                acc[mt][nt][half * 2 + 0] = u0;
                acc[mt][nt][half * 2 + 1] = u1;
                s1 += u0 + u1; s2 += u0 * u0 + u1 * u1;
            }
            su1[mt * 2 + half] = s1;
            su2[mt * 2 + half] = s2;
        }
    }
    __syncthreads();
    if (tid < 64) { rsum[tid] = 0.f; rsq[tid] = 0.f; }
    __syncthreads();
    #pragma unroll
    for (int mt = 0; mt < 2; mt++) {
        #pragma unroll
        for (int half = 0; half < 2; half++) {
            int row = wr * 32 + mt * 16 + (lane >> 2) + half * 8;
            atomicAdd(&rsum[row], su1[mt * 2 + half]);
            atomicAdd(&rsq[row],  su2[mt * 2 + half]);
        }
    }
    __syncthreads();
    #pragma unroll
    for (int mt = 0; mt < 2; mt++) {
        #pragma unroll
        for (int half = 0; half < 2; half++) {
            int row = wr * 32 + mt * 16 + (lane >> 2) + half * 8;
            float mean = rsum[row] * (1.f / CDIM);
            float var  = rsq[row] * (1.f / CDIM) - mean * mean;
            float inv  = rsqrtf(var + 1e-5f);
            #pragma unroll
            for (int nt = 0; nt < 6; nt++) {
                int c = wc * 48 + nt * 8 + 2 * (lane & 3);
                float2 o;
                o.x = (acc[mt][nt][half * 2 + 0] - mean) * inv * e_g2[c]     + e_b2[c];
                o.y = (acc[mt][nt][half * 2 + 1] - mean) * inv * e_g2[c + 1] + e_b2[c + 1];
                *(float2*)&C[(size_t)(row0 + row) * CDIM + c] = o;
            }
        }
    }
}

// ---------------- attention: 192 threads = 4 (set,head) pairs ---------------
__global__ void __launch_bounds__(192)
attn_kernel(const uint8_t* __restrict__ mask)
{
    const int p   = threadIdx.x / SETSZ;
    const int i   = threadIdx.x % SETSZ;
    const int gp  = blockIdx.x * 4 + p;
    const int s   = gp >> 3;
    const int h   = gp & 7;

    __shared__ float ks[4][SETSZ][28];
    __shared__ float vs[4][SETSZ][28];
    __shared__ float mf[4][SETSZ];

    const size_t ro = (size_t)s * SETSZ + i;
    const float* qrow = &g_qk[ro * (2 * CDIM) + h * HD];

    float4 q[6];
    #pragma unroll
    for (int t = 0; t < 6; t++) {
        q[t] = *(const float4*)&qrow[t * 4];
        float4 kk = *(const float4*)&qrow[CDIM + t * 4];
        *(float4*)&ks[p][i][t * 4] = kk;
        float4 vv = *(const float4*)&g_v[ro * CDIM + h * HD + t * 4];
        *(float4*)&vs[p][i][t * 4] = vv;
    }
    mf[p][i] = (mask[(size_t)s * SETSZ + i] != 0) ? -1e9f : 0.f;
    __syncthreads();

    const float scale = 0.20412414523193154f; // 1/sqrt(24)
    float sc[SETSZ];
    #pragma unroll 8
    for (int j = 0; j < SETSZ; j++) {
        float4 k0 = *(const float4*)&ks[p][j][0];
        float4 k1 = *(const float4*)&ks[p][j][4];
        float4 k2 = *(const float4*)&ks[p][j][8];
        float4 k3 = *(const float4*)&ks[p][j][12];
        float4 k4 = *(const float4*)&ks[p][j][16];
        float4 k5 = *(const float4*)&ks[p][j][20];
        float a0 = q[0].x * k0.x + q[0].y * k0.y + q[0].z * k0.z + q[0].w * k0.w;
        float a1 = q[1].x * k1.x + q[1].y * k1.y + q[1].z * k1.z + q[1].w * k1.w;
        float a2 = q[2].x * k2.x + q[2].y * k2.y + q[2].z * k2.z + q[2].w * k2.w;
        float a3 = q[3].x * k3.x + q[3].y * k3.y + q[3].z * k3.z + q[3].w * k3.w;
        float a4 = q[4].x * k4.x + q[4].y * k4.y + q[4].z * k4.z + q[4].w * k4.w;
        float a5 = q[5].x * k5.x + q[5].y * k5.y + q[5].z * k5.z + q[5].w * k5.w;
        sc[j] = ((a0 + a1) + (a2 + a3) + (a4 + a5)) * scale + mf[p][j];
    }

    float m = -1e30f;
    #pragma unroll
    for (int j = 0; j < SETSZ; j++) m = fmaxf(m, sc[j]);
    float sum = 0.f;
    #pragma unroll
    for (int j = 0; j < SETSZ; j++) { float e = __expf(sc[j] - m); sc[j] = e; sum += e; }
    float inv = 1.f / sum;

    float4 o[6];
    #pragma unroll
    for (int t = 0; t < 6; t++) { o[t].x = 0.f; o[t].y = 0.f; o[t].z = 0.f; o[t].w = 0.f; }
    #pragma unroll 4
    for (int j = 0; j < SETSZ; j++) {
        float pr = sc[j] * inv;
        #pragma unroll
        for (int t = 0; t < 6; t++) {
            float4 v4 = *(const float4*)&vs[p][j][t * 4];
            o[t].x += pr * v4.x; o[t].y += pr * v4.y;
            o[t].z += pr * v4.z; o[t].w += pr * v4.w;
        }
    }
    float* crow = &g_ctx[ro * CDIM + h * HD];
    #pragma unroll
    for (int t = 0; t < 6; t++) *(float4*)&crow[t * 4] = o[t];
}

// ---------------- launch --------------------------------------------------
extern "C" void kernel_launch(void* const* d_in, const int* in_sizes, int n_in,
                              void* d_out, int out_size)
{
    const float* src   = (const float*)d_in[0];
    const float* pos   = (const float*)d_in[1];
    const float* w_qkv = (const float*)d_in[2];
    const float* b_qkv = (const float*)d_in[3];
    const float* w_out = (const float*)d_in[4];
    const float* b_out = (const float*)d_in[5];
    const float* w1    = (const float*)d_in[6];
    const float* b1    = (const float*)d_in[7];
    const float* w2    = (const float*)d_in[8];
    const float* b2    = (const float*)d_in[9];
    const float* ln1g  = (const float*)d_in[10];
    const float* ln1b  = (const float*)d_in[11];
    const float* ln2g  = (const float*)d_in[12];
    const float* ln2b  = (const float*)d_in[13];
    const float* ln3g  = (const float*)d_in[14];
    const float* ln3b  = (const float*)d_in[15];
    const int*   vidx  = (const int*)d_in[16];
    const uint8_t* msk = (const uint8_t*)d_in[17];
    float* out = (float*)d_out;

    float *p_qk, *p_v, *p_ctx, *p_x, *p_h;
    cudaGetSymbolAddress((void**)&p_qk,  g_qk);
    cudaGetSymbolAddress((void**)&p_v,   g_v);
    cudaGetSymbolAddress((void**)&p_ctx, g_ctx);
    cudaGetSymbolAddress((void**)&p_x,   g_x);
    cudaGetSymbolAddress((void**)&p_h,   g_h);

    cudaFuncSetAttribute(gemm_bf16x2<0,1,0>, cudaFuncAttributeMaxDynamicSharedMemorySize, GEMM_SMEM_BYTES);
    cudaFuncSetAttribute(gemm_bf16x2<0,2,0>, cudaFuncAttributeMaxDynamicSharedMemorySize, GEMM_SMEM_BYTES);
    cudaFuncSetAttribute(gemm_bf16x2<0,0,1>, cudaFuncAttributeMaxDynamicSharedMemorySize, GEMM_SMEM_BYTES);
    cudaFuncSetAttribute(gemm_bf16x2<1,0,0>, cudaFuncAttributeMaxDynamicSharedMemorySize, GEMM_SMEM_BYTES);
    cudaFuncSetAttribute(gemm_bf16x2<0,0,2>, cudaFuncAttributeMaxDynamicSharedMemorySize, GEMM_SMEM_BYTES);

    const int MB = NVOX / 64;  // 3072

    // 1) q,k projection with fused gather (src+pos): (N x 384)
    gemm_bf16x2<0,1,0><<<dim3(MB, 2), 256, GEMM_SMEM_BYTES>>>(
        src, pos, vidx, w_qkv, b_qkv, p_qk,
        nullptr, nullptr, nullptr, nullptr, nullptr, nullptr,
        NVOX, 2 * CDIM, CDIM);

    // 2) v projection with fused gather (src): (N x 192)
    gemm_bf16x2<0,2,0><<<dim3(MB, 1), 256, GEMM_SMEM_BYTES>>>(
        src, nullptr, vidx, w_qkv + (size_t)2 * CDIM * CDIM, b_qkv + 2 * CDIM, p_v,
        nullptr, nullptr, nullptr, nullptr, nullptr, nullptr,
        NVOX, CDIM, CDIM);

    // 3) attention
    attn_kernel<<<(SETS * NHEAD) / 4, 192>>>(msk);

    // 4) output projection + fused scatter + residual + LN1 -> g_x (voxel order)
    gemm_bf16x2<0,0,1><<<dim3(MB, 1), 256, GEMM_SMEM_BYTES>>>(
        p_ctx, nullptr, vidx, w_out, b_out, p_x,
        src, nullptr, ln1g, ln1b, nullptr, nullptr,
        NVOX, CDIM, CDIM);

    // 5) FFN1 (relu)
    gemm_bf16x2<1,0,0><<<dim3(MB, 2), 256, GEMM_SMEM_BYTES>>>(
        p_x, nullptr, nullptr, w1, b1, p_h,
        nullptr, nullptr, nullptr, nullptr, nullptr, nullptr,
        NVOX, DFF, CDIM);

    // 6) FFN2 + fused LN2 + residual + LN3 -> out
    gemm_bf16x2<0,0,2><<<dim3(MB, 1), 256, GEMM_SMEM_BYTES>>>(
        p_h, nullptr, nullptr, w2, b2, out,
        src, p_x, ln2g, ln2b, ln3g, ln3b,
        NVOX, CDIM, DFF);
}

// round 9
// speedup vs baseline: 1.6407x; 1.0559x over previous
#include <cuda_runtime.h>
#include <cuda_bf16.h>
#include <cstdint>
#include <cstddef>

// ---------------- problem constants ----------------
#define NVOX   196608
#define CDIM   192
#define SETS   4096
#define SETSZ  48
#define NHEAD  8
#define HD     24
#define DFF    384

// ---------------- scratch (device globals) ----------------
__device__ float g_qk [(size_t)NVOX * 2 * CDIM]; // q cols 0..191, k 192..383 (set-slot order)
__device__ float g_v  [(size_t)NVOX * CDIM];
__device__ float g_ctx[(size_t)NVOX * CDIM];
__device__ float g_x  [(size_t)NVOX * CDIM];     // after LN1, voxel order
__device__ float g_h  [(size_t)NVOX * DFF];

// ---------------- bf16 tensor-core GEMM, BM=64 BN=192 BK=32, 256 thr ------
// A and B both rounded to bf16 (fp32 accumulate).
// C[m,n] = sum_k A[m,k]*B[n,k] + bias[n]
// GATHER: 0 none | 1 A=src[vidx]+pos[vidx] | 2 A=src[vidx]
// EPI: 0 plain(+RELU) | 1 LN1 scatter | 2 LN2+res+LN3
#define ASTR 20  // u32 row stride (16 data pairs + 4 pad) -> ldmatrix conflict-free

#define OFF_AH 0
#define OFF_BH (64 * ASTR)
#define STAGE_U32 (256 * ASTR)            // 5120 u32 per stage (20.5 KB)
#define OFF_SV (2 * STAGE_U32)            // vidx cache (64 ints)
#define GEMM_SMEM_BYTES ((OFF_SV + 64) * 4)

__device__ __forceinline__ uint32_t pack_bf16(float x, float y)
{
    __nv_bfloat162 h2 = __floats2bfloat162_rn(x, y);
    return *reinterpret_cast<const uint32_t*>(&h2);
}

__device__ __forceinline__ void mma_bf16(float c[4],
    uint32_t a0, uint32_t a1, uint32_t a2, uint32_t a3,
    uint32_t b0, uint32_t b1)
{
    asm volatile(
        "mma.sync.aligned.m16n8k16.row.col.f32.bf16.bf16.f32 "
        "{%0,%1,%2,%3}, {%4,%5,%6,%7}, {%8,%9}, {%0,%1,%2,%3};\n"
        : "+f"(c[0]), "+f"(c[1]), "+f"(c[2]), "+f"(c[3])
        : "r"(a0), "r"(a1), "r"(a2), "r"(a3), "r"(b0), "r"(b1));
}

__device__ __forceinline__ void ldsm_x4(uint32_t& r0, uint32_t& r1,
                                        uint32_t& r2, uint32_t& r3, uint32_t addr)
{
    asm volatile("ldmatrix.sync.aligned.m8n8.x4.shared.b16 {%0,%1,%2,%3}, [%4];"
                 : "=r"(r0), "=r"(r1), "=r"(r2), "=r"(r3) : "r"(addr));
}

template <int RELU, int GATHER, int EPI>
__global__ void __launch_bounds__(256, 2)
gemm_bf16(const float* __restrict__ A, const float* __restrict__ A2,
          const int* __restrict__ vidx,
          const float* __restrict__ B, const float* __restrict__ bias,
          float* __restrict__ C,
          const float* __restrict__ e_src, const float* __restrict__ e_x,
          const float* __restrict__ e_g1, const float* __restrict__ e_b1,
          const float* __restrict__ e_g2, const float* __restrict__ e_b2,
          int M, int N, int K)
{
    extern __shared__ uint32_t sm[];
    int* sv = (int*)(sm + OFF_SV);

    const int tid  = threadIdx.x;
    const int lane = tid & 31;
    const int warp = tid >> 5;
    const int wr   = warp >> 2;   // 0..1 -> m offset 32*wr
    const int wc   = warp & 3;    // 0..3 -> n offset 48*wc
    const int row0 = blockIdx.x * 64;
    const int col0 = blockIdx.y * 192;

    if (GATHER || EPI == 1) {
        if (tid < 64) sv[tid] = vidx[row0 + tid];
        __syncthreads();
    }

    float acc[2][6][4];
    #pragma unroll
    for (int m = 0; m < 2; m++)
        #pragma unroll
        for (int n = 0; n < 6; n++)
            #pragma unroll
            for (int i = 0; i < 4; i++) acc[m][n][i] = 0.f;

    const int ar = tid >> 3;   // 0..31
    const int ac = tid & 7;    // 0..7 (float4 col)

    auto ldA = [&](int kk, int rr) -> float4 {
        int row = ar + rr * 32;
        if (GATHER) {
            int vr = sv[row];
            float4 v = *(const float4*)&A[(size_t)vr * K + kk + ac * 4];
            if (GATHER == 1) {
                float4 p = *(const float4*)&A2[(size_t)vr * K + kk + ac * 4];
                v.x += p.x; v.y += p.y; v.z += p.z; v.w += p.w;
            }
            return v;
        }
        return *(const float4*)&A[(size_t)(row0 + row) * K + kk + ac * 4];
    };
    auto ldB = [&](int kk, int rr) -> float4 {
        return *(const float4*)&B[(size_t)(col0 + ar + rr * 32) * K + kk + ac * 4];
    };
    auto store_stage = [&](int st, const float4* pa, const float4* pb) {
        uint32_t* Ah = sm + st * STAGE_U32 + OFF_AH;
        uint32_t* Bh = sm + st * STAGE_U32 + OFF_BH;
        #pragma unroll
        for (int r = 0; r < 2; r++) {
            int row = ar + r * 32;
            Ah[row * ASTR + ac * 2]     = pack_bf16(pa[r].x, pa[r].y);
            Ah[row * ASTR + ac * 2 + 1] = pack_bf16(pa[r].z, pa[r].w);
        }
        #pragma unroll
        for (int r = 0; r < 6; r++) {
            int row = ar + r * 32;
            Bh[row * ASTR + ac * 2]     = pack_bf16(pb[r].x, pb[r].y);
            Bh[row * ASTR + ac * 2 + 1] = pack_bf16(pb[r].z, pb[r].w);
        }
    };

    const uint32_t sbase = (uint32_t)__cvta_generic_to_shared(sm);
    // ldmatrix lane address components (verified fragment mapping)
    const int a_row = wr * 32 + (lane & 7) + ((lane >> 3) & 1) * 8;
    const int a_cb  = ((lane >> 4) & 1) * 4;
    const int b_row = wc * 48 + (lane & 7) + ((lane >> 4) & 1) * 8;
    const int b_cb  = ((lane >> 3) & 1) * 4;

    // prologue: tile 0
    float4 pa[2], pb[6];
    #pragma unroll
    for (int r = 0; r < 2; r++) pa[r] = ldA(0, r);
    #pragma unroll
    for (int r = 0; r < 6; r++) pb[r] = ldB(0, r);
    store_stage(0, pa, pb);
    __syncthreads();

    const int nk = K >> 5;
    for (int it = 0; it < nk; it++) {
        const int st = it & 1;
        if (it + 1 < nk) {
            int kk = (it + 1) * 32;
            #pragma unroll
            for (int r = 0; r < 2; r++) pa[r] = ldA(kk, r);
            #pragma unroll
            for (int r = 0; r < 6; r++) pb[r] = ldB(kk, r);
        }
        const uint32_t stAh = sbase + (st * STAGE_U32 + OFF_AH) * 4;
        const uint32_t stBh = sbase + (st * STAGE_U32 + OFF_BH) * 4;

        #pragma unroll
        for (int k16 = 0; k16 < 2; k16++) {
            const int kp = k16 * 8;
            uint32_t ah[4], ah2[4];
            {
                uint32_t off = (uint32_t)(((a_row) * ASTR + kp + a_cb) * 4);
                ldsm_x4(ah[0], ah[1], ah[2], ah[3], stAh + off);
            }
            {
                uint32_t off = (uint32_t)(((a_row + 16) * ASTR + kp + a_cb) * 4);
                ldsm_x4(ah2[0], ah2[1], ah2[2], ah2[3], stAh + off);
            }
            uint32_t bh[12];
            #pragma unroll
            for (int p = 0; p < 3; p++) {
                uint32_t off = (uint32_t)(((b_row + p * 16) * ASTR + kp + b_cb) * 4);
                ldsm_x4(bh[p * 4 + 0], bh[p * 4 + 1], bh[p * 4 + 2], bh[p * 4 + 3], stBh + off);
            }
            #pragma unroll
            for (int nt = 0; nt < 6; nt++) {
                uint32_t bh0 = bh[nt * 2], bh1 = bh[nt * 2 + 1];
                mma_bf16(acc[0][nt], ah[0],  ah[1],  ah[2],  ah[3],  bh0, bh1);
                mma_bf16(acc[1][nt], ah2[0], ah2[1], ah2[2], ah2[3], bh0, bh1);
            }
        }
        if (it + 1 < nk) store_stage(st ^ 1, pa, pb);
        __syncthreads();
    }

    // ================= epilogue =================
    if (EPI == 0) {
        #pragma unroll
        for (int mt = 0; mt < 2; mt++) {
            int r0 = row0 + wr * 32 + mt * 16 + (lane >> 2);
            #pragma unroll
            for (int nt = 0; nt < 6; nt++) {
                int c = col0 + wc * 48 + nt * 8 + 2 * (lane & 3);
                float bx = bias[c], by = bias[c + 1];
                float2 o0, o1;
                o0.x = acc[mt][nt][0] + bx; o0.y = acc[mt][nt][1] + by;
                o1.x = acc[mt][nt][2] + bx; o1.y = acc[mt][nt][3] + by;
                if (RELU) {
                    o0.x = fmaxf(o0.x, 0.f); o0.y = fmaxf(o0.y, 0.f);
                    o1.x = fmaxf(o1.x, 0.f); o1.y = fmaxf(o1.y, 0.f);
                }
                *(float2*)&C[(size_t)r0 * N + c]       = o0;
                *(float2*)&C[(size_t)(r0 + 8) * N + c] = o1;
            }
        }
        return;
    }

    // LN epilogues: N == 192 (full row per block), col0 == 0
    float* rsum = (float*)sm;        // [64]
    float* rsq  = (float*)sm + 64;   // [64]
    if (tid < 64) { rsum[tid] = 0.f; rsq[tid] = 0.f; }
    __syncthreads();

    #pragma unroll
    for (int mt = 0; mt < 2; mt++) {
        #pragma unroll
        for (int half = 0; half < 2; half++) {
            int row = wr * 32 + mt * 16 + (lane >> 2) + half * 8;
            float s1 = 0.f, s2 = 0.f;
            #pragma unroll
            for (int nt = 0; nt < 6; nt++) {
                int c = wc * 48 + nt * 8 + 2 * (lane & 3);
                float2 res;
                if (EPI == 1) {
                    int v = sv[row];
                    res = *(const float2*)&e_src[(size_t)v * CDIM + c];
                } else {
                    res = *(const float2*)&e_x[(size_t)(row0 + row) * CDIM + c];
                }
                float v0 = acc[mt][nt][half * 2 + 0] + bias[c]     + res.x;
                float v1 = acc[mt][nt][half * 2 + 1] + bias[c + 1] + res.y;
                acc[mt][nt][half * 2 + 0] = v0;
                acc[mt][nt][half * 2 + 1] = v1;
                s1 += v0 + v1; s2 += v0 * v0 + v1 * v1;
            }
            atomicAdd(&rsum[row], s1);
            atomicAdd(&rsq[row],  s2);
        }
    }
    __syncthreads();

    if (EPI == 1) {
        #pragma unroll
        for (int mt = 0; mt < 2; mt++) {
            #pragma unroll
            for (int half = 0; half < 2; half++) {
                int row = wr * 32 + mt * 16 + (lane >> 2) + half * 8;
                int v = sv[row];
                float mean = rsum[row] * (1.f / CDIM);
                float var  = rsq[row] * (1.f / CDIM) - mean * mean;
                float inv  = rsqrtf(var + 1e-5f);
                #pragma unroll
                for (int nt = 0; nt < 6; nt++) {
                    int c = wc * 48 + nt * 8 + 2 * (lane & 3);
                    float2 o;
                    o.x = (acc[mt][nt][half * 2 + 0] - mean) * inv * e_g1[c]     + e_b1[c];
                    o.y = (acc[mt][nt][half * 2 + 1] - mean) * inv * e_g1[c + 1] + e_b1[c + 1];
                    *(float2*)&C[(size_t)v * CDIM + c] = o;
                }
            }
        }
        return;
    }

    // EPI == 2: LN2 then +src then LN3
    float su1[4], su2[4];
    #pragma unroll
    for (int mt = 0; mt < 2; mt++) {
        #pragma unroll
        for (int half = 0; half < 2; half++) {
            int row = wr * 32 + mt * 16 + (lane >> 2) + half * 8;
            float mean = rsum[row] * (1.f / CDIM);
            float var  = rsq[row] * (1.f / CDIM) - mean * mean;
            float inv  = rsqrtf(var + 1e-5f);
            float s1 = 0.f, s2 = 0.f;
            #pragma unroll
            for (int nt = 0; nt < 6; nt++) {
                int c = wc * 48 + nt * 8 + 2 * (lane & 3);
                float2 sr = *(const float2*)&e_src[(size_t)(row0 + row) * CDIM + c];
                float u0 = (acc[mt][nt][half * 2 + 0] - mean) * inv * e_g1[c]     + e_b1[c]     + sr.x;
                float u1 = (acc[mt][nt][half * 2 + 1] - mean) * inv * e_g1[c + 1] + e_b1[c + 1] + sr.y;
                acc[mt][nt][half * 2 + 0] = u0;
                acc[mt][nt][half * 2 + 1] = u1;
                s1 += u0 + u1; s2 += u0 * u0 + u1 * u1;
            }
            su1[mt * 2 + half] = s1;
            su2[mt * 2 + half] = s2;
        }
    }
    __syncthreads();
    if (tid < 64) { rsum[tid] = 0.f; rsq[tid] = 0.f; }
    __syncthreads();
    #pragma unroll
    for (int mt = 0; mt < 2; mt++) {
        #pragma unroll
        for (int half = 0; half < 2; half++) {
            int row = wr * 32 + mt * 16 + (lane >> 2) + half * 8;
            atomicAdd(&rsum[row], su1[mt * 2 + half]);
            atomicAdd(&rsq[row],  su2[mt * 2 + half]);
        }
    }
    __syncthreads();
    #pragma unroll
    for (int mt = 0; mt < 2; mt++) {
        #pragma unroll
        for (int half = 0; half < 2; half++) {
            int row = wr * 32 + mt * 16 + (lane >> 2) + half * 8;
            float mean = rsum[row] * (1.f / CDIM);
            float var  = rsq[row] * (1.f / CDIM) - mean * mean;
            float inv  = rsqrtf(var + 1e-5f);
            #pragma unroll
            for (int nt = 0; nt < 6; nt++) {
                int c = wc * 48 + nt * 8 + 2 * (lane & 3);
                float2 o;
                o.x = (acc[mt][nt][half * 2 + 0] - mean) * inv * e_g2[c]     + e_b2[c];
                o.y = (acc[mt][nt][half * 2 + 1] - mean) * inv * e_g2[c + 1] + e_b2[c + 1];
                *(float2*)&C[(size_t)(row0 + row) * CDIM + c] = o;
            }
        }
    }
}

// ---------------- attention: 192 threads = 4 (set,head) pairs ---------------
__global__ void __launch_bounds__(192)
attn_kernel(const uint8_t* __restrict__ mask)
{
    const int p   = threadIdx.x / SETSZ;
    const int i   = threadIdx.x % SETSZ;
    const int gp  = blockIdx.x * 4 + p;
    const int s   = gp >> 3;
    const int h   = gp & 7;

    __shared__ float ks[4][SETSZ][28];
    __shared__ float vs[4][SETSZ][28];
    __shared__ float mf[4][SETSZ];

    const size_t ro = (size_t)s * SETSZ + i;
    const float* qrow = &g_qk[ro * (2 * CDIM) + h * HD];

    float4 q[6];
    #pragma unroll
    for (int t = 0; t < 6; t++) {
        q[t] = *(const float4*)&qrow[t * 4];
        float4 kk = *(const float4*)&qrow[CDIM + t * 4];
        *(float4*)&ks[p][i][t * 4] = kk;
        float4 vv = *(const float4*)&g_v[ro * CDIM + h * HD + t * 4];
        *(float4*)&vs[p][i][t * 4] = vv;
    }
    mf[p][i] = (mask[(size_t)s * SETSZ + i] != 0) ? -1e9f : 0.f;
    __syncthreads();

    const float scale = 0.20412414523193154f; // 1/sqrt(24)
    float sc[SETSZ];
    #pragma unroll 8
    for (int j = 0; j < SETSZ; j++) {
        float4 k0 = *(const float4*)&ks[p][j][0];
        float4 k1 = *(const float4*)&ks[p][j][4];
        float4 k2 = *(const float4*)&ks[p][j][8];
        float4 k3 = *(const float4*)&ks[p][j][12];
        float4 k4 = *(const float4*)&ks[p][j][16];
        float4 k5 = *(const float4*)&ks[p][j][20];
        float a0 = q[0].x * k0.x + q[0].y * k0.y + q[0].z * k0.z + q[0].w * k0.w;
        float a1 = q[1].x * k1.x + q[1].y * k1.y + q[1].z * k1.z + q[1].w * k1.w;
        float a2 = q[2].x * k2.x + q[2].y * k2.y + q[2].z * k2.z + q[2].w * k2.w;
        float a3 = q[3].x * k3.x + q[3].y * k3.y + q[3].z * k3.z + q[3].w * k3.w;
        float a4 = q[4].x * k4.x + q[4].y * k4.y + q[4].z * k4.z + q[4].w * k4.w;
        float a5 = q[5].x * k5.x + q[5].y * k5.y + q[5].z * k5.z + q[5].w * k5.w;
        sc[j] = ((a0 + a1) + (a2 + a3) + (a4 + a5)) * scale + mf[p][j];
    }

    float m = -1e30f;
    #pragma unroll
    for (int j = 0; j < SETSZ; j++) m = fmaxf(m, sc[j]);
    float sum = 0.f;
    #pragma unroll
    for (int j = 0; j < SETSZ; j++) { float e = __expf(sc[j] - m); sc[j] = e; sum += e; }
    float inv = 1.f / sum;

    float4 o[6];
    #pragma unroll
    for (int t = 0; t < 6; t++) { o[t].x = 0.f; o[t].y = 0.f; o[t].z = 0.f; o[t].w = 0.f; }
    #pragma unroll 4
    for (int j = 0; j < SETSZ; j++) {
        float pr = sc[j] * inv;
        #pragma unroll
        for (int t = 0; t < 6; t++) {
            float4 v4 = *(const float4*)&vs[p][j][t * 4];
            o[t].x += pr * v4.x; o[t].y += pr * v4.y;
            o[t].z += pr * v4.z; o[t].w += pr * v4.w;
        }
    }
    float* crow = &g_ctx[ro * CDIM + h * HD];
    #pragma unroll
    for (int t = 0; t < 6; t++) *(float4*)&crow[t * 4] = o[t];
}

// ---------------- launch --------------------------------------------------
extern "C" void kernel_launch(void* const* d_in, const int* in_sizes, int n_in,
                              void* d_out, int out_size)
{
    const float* src   = (const float*)d_in[0];
    const float* pos   = (const float*)d_in[1];
    const float* w_qkv = (const float*)d_in[2];
    const float* b_qkv = (const float*)d_in[3];
    const float* w_out = (const float*)d_in[4];
    const float* b_out = (const float*)d_in[5];
    const float* w1    = (const float*)d_in[6];
    const float* b1    = (const float*)d_in[7];
    const float* w2    = (const float*)d_in[8];
    const float* b2    = (const float*)d_in[9];
    const float* ln1g  = (const float*)d_in[10];
    const float* ln1b  = (const float*)d_in[11];
    const float* ln2g  = (const float*)d_in[12];
    const float* ln2b  = (const float*)d_in[13];
    const float* ln3g  = (const float*)d_in[14];
    const float* ln3b  = (const float*)d_in[15];
    const int*   vidx  = (const int*)d_in[16];
    const uint8_t* msk = (const uint8_t*)d_in[17];
    float* out = (float*)d_out;

    float *p_qk, *p_v, *p_ctx, *p_x, *p_h;
    cudaGetSymbolAddress((void**)&p_qk,  g_qk);
    cudaGetSymbolAddress((void**)&p_v,   g_v);
    cudaGetSymbolAddress((void**)&p_ctx, g_ctx);
    cudaGetSymbolAddress((void**)&p_x,   g_x);
    cudaGetSymbolAddress((void**)&p_h,   g_h);

    cudaFuncSetAttribute(gemm_bf16<0,1,0>, cudaFuncAttributeMaxDynamicSharedMemorySize, GEMM_SMEM_BYTES);
    cudaFuncSetAttribute(gemm_bf16<0,2,0>, cudaFuncAttributeMaxDynamicSharedMemorySize, GEMM_SMEM_BYTES);
    cudaFuncSetAttribute(gemm_bf16<0,0,1>, cudaFuncAttributeMaxDynamicSharedMemorySize, GEMM_SMEM_BYTES);
    cudaFuncSetAttribute(gemm_bf16<1,0,0>, cudaFuncAttributeMaxDynamicSharedMemorySize, GEMM_SMEM_BYTES);
    cudaFuncSetAttribute(gemm_bf16<0,0,2>, cudaFuncAttributeMaxDynamicSharedMemorySize, GEMM_SMEM_BYTES);

    const int MB = NVOX / 64;  // 3072

    // 1) q,k projection with fused gather (src+pos): (N x 384)
    gemm_bf16<0,1,0><<<dim3(MB, 2), 256, GEMM_SMEM_BYTES>>>(
        src, pos, vidx, w_qkv, b_qkv, p_qk,
        nullptr, nullptr, nullptr, nullptr, nullptr, nullptr,
        NVOX, 2 * CDIM, CDIM);

    // 2) v projection with fused gather (src): (N x 192)
    gemm_bf16<0,2,0><<<dim3(MB, 1), 256, GEMM_SMEM_BYTES>>>(
        src, nullptr, vidx, w_qkv + (size_t)2 * CDIM * CDIM, b_qkv + 2 * CDIM, p_v,
        nullptr, nullptr, nullptr, nullptr, nullptr, nullptr,
        NVOX, CDIM, CDIM);

    // 3) attention
    attn_kernel<<<(SETS * NHEAD) / 4, 192>>>(msk);

    // 4) output projection + fused scatter + residual + LN1 -> g_x (voxel order)
    gemm_bf16<0,0,1><<<dim3(MB, 1), 256, GEMM_SMEM_BYTES>>>(
        p_ctx, nullptr, vidx, w_out, b_out, p_x,
        src, nullptr, ln1g, ln1b, nullptr, nullptr,
        NVOX, CDIM, CDIM);

    // 5) FFN1 (relu)
    gemm_bf16<1,0,0><<<dim3(MB, 2), 256, GEMM_SMEM_BYTES>>>(
        p_x, nullptr, nullptr, w1, b1, p_h,
        nullptr, nullptr, nullptr, nullptr, nullptr, nullptr,
        NVOX, DFF, CDIM);

    // 6) FFN2 + fused LN2 + residual + LN3 -> out
    gemm_bf16<0,0,2><<<dim3(MB, 1), 256, GEMM_SMEM_BYTES>>>(
        p_h, nullptr, nullptr, w2, b2, out,
        src, p_x, ln2g, ln2b, ln3g, ln3b,
        NVOX, CDIM, DFF);
}

// round 10
// speedup vs baseline: 1.9103x; 1.1643x over previous
#include <cuda_runtime.h>
#include <cuda_bf16.h>
#include <cstdint>
#include <cstddef>

// ---------------- problem constants ----------------
#define NVOX   196608
#define CDIM   192
#define SETS   4096
#define SETSZ  48
#define NHEAD  8
#define HD     24
#define DFF    384

// ---------------- scratch (device globals) ----------------
__device__ __nv_bfloat16 g_qkin[(size_t)NVOX * CDIM];   // gathered src+pos (set-slot order)
__device__ __nv_bfloat16 g_feat[(size_t)NVOX * CDIM];   // gathered src
__device__ __nv_bfloat16 g_qk  [(size_t)NVOX * 2 * CDIM];
__device__ __nv_bfloat16 g_v   [(size_t)NVOX * CDIM];
__device__ __nv_bfloat16 g_ctx [(size_t)NVOX * CDIM];
__device__ float         g_x   [(size_t)NVOX * CDIM];   // LN1 out, fp32 (residual precision)
__device__ __nv_bfloat16 g_xb  [(size_t)NVOX * CDIM];   // LN1 out, bf16 (FFN1 input)
__device__ __nv_bfloat16 g_h   [(size_t)NVOX * DFF];
// bf16 weights
__device__ __nv_bfloat16 g_wqkv[3 * CDIM * CDIM];
__device__ __nv_bfloat16 g_wout[CDIM * CDIM];
__device__ __nv_bfloat16 g_w1  [DFF * CDIM];
__device__ __nv_bfloat16 g_w2  [CDIM * DFF];

// ---------------- helpers ----------------
__device__ __forceinline__ uint32_t pack_bf16(float x, float y)
{
    __nv_bfloat162 h2 = __floats2bfloat162_rn(x, y);
    return *reinterpret_cast<const uint32_t*>(&h2);
}
__device__ __forceinline__ void bf8_to_f(const __nv_bfloat16* p, float* f)
{
    uint4 u = *(const uint4*)p;
    float2 a = __bfloat1622float2(*(__nv_bfloat162*)&u.x);
    float2 b = __bfloat1622float2(*(__nv_bfloat162*)&u.y);
    float2 c = __bfloat1622float2(*(__nv_bfloat162*)&u.z);
    float2 d = __bfloat1622float2(*(__nv_bfloat162*)&u.w);
    f[0] = a.x; f[1] = a.y; f[2] = b.x; f[3] = b.y;
    f[4] = c.x; f[5] = c.y; f[6] = d.x; f[7] = d.y;
}

__device__ __forceinline__ void mma_bf16(float c[4],
    uint32_t a0, uint32_t a1, uint32_t a2, uint32_t a3,
    uint32_t b0, uint32_t b1)
{
    asm volatile(
        "mma.sync.aligned.m16n8k16.row.col.f32.bf16.bf16.f32 "
        "{%0,%1,%2,%3}, {%4,%5,%6,%7}, {%8,%9}, {%0,%1,%2,%3};\n"
        : "+f"(c[0]), "+f"(c[1]), "+f"(c[2]), "+f"(c[3])
        : "r"(a0), "r"(a1), "r"(a2), "r"(a3), "r"(b0), "r"(b1));
}
__device__ __forceinline__ void ldsm_x4(uint32_t& r0, uint32_t& r1,
                                        uint32_t& r2, uint32_t& r3, uint32_t addr)
{
    asm volatile("ldmatrix.sync.aligned.m8n8.x4.shared.b16 {%0,%1,%2,%3}, [%4];"
                 : "=r"(r0), "=r"(r1), "=r"(r2), "=r"(r3) : "r"(addr));
}
__device__ __forceinline__ void cp16(uint32_t saddr, const void* gaddr)
{
    asm volatile("cp.async.cg.shared.global [%0], [%1], 16;"
                 :: "r"(saddr), "l"(gaddr) : "memory");
}

// ---------------- weight fp32 -> bf16 conversion ----------------
__global__ void cvt_kernel(const float* __restrict__ in, __nv_bfloat16* __restrict__ out, int n2)
{
    int i = blockIdx.x * blockDim.x + threadIdx.x;   // per 2 elements
    if (i < n2) {
        ((uint32_t*)out)[i] = pack_bf16(in[2 * i], in[2 * i + 1]);
    }
}

// ---------------- gather: qkin = bf16(src[v]+pos[v]), feat = bf16(src[v]) ---
__global__ void __launch_bounds__(256)
gather_kernel(const float* __restrict__ src, const float* __restrict__ pos,
              const int* __restrict__ vidx)
{
    size_t i = (size_t)blockIdx.x * blockDim.x + threadIdx.x; // per 8 elements
    if (i >= (size_t)NVOX * (CDIM / 8)) return;
    int slot = (int)(i / (CDIM / 8));
    int c8   = (int)(i % (CDIM / 8)) * 8;
    int v = vidx[slot];
    const float4* s4 = (const float4*)(src + (size_t)v * CDIM + c8);
    const float4* p4 = (const float4*)(pos + (size_t)v * CDIM + c8);
    float4 s0 = s4[0], s1 = s4[1];
    float4 p0 = p4[0], p1 = p4[1];
    uint4 fo, qo;
    fo.x = pack_bf16(s0.x, s0.y); fo.y = pack_bf16(s0.z, s0.w);
    fo.z = pack_bf16(s1.x, s1.y); fo.w = pack_bf16(s1.z, s1.w);
    qo.x = pack_bf16(s0.x + p0.x, s0.y + p0.y); qo.y = pack_bf16(s0.z + p0.z, s0.w + p0.w);
    qo.z = pack_bf16(s1.x + p1.x, s1.y + p1.y); qo.w = pack_bf16(s1.z + p1.z, s1.w + p1.w);
    *(uint4*)(g_feat + i * 8) = fo;
    *(uint4*)(g_qkin + i * 8) = qo;
}

// ---------------- bf16 GEMM, BM=64 BN=192 BK=32, cp.async 3-stage ----------
// C[m,n] = sum_k A[m,k]*B[n,k] + bias[n];  A,B bf16 row-major (B = weight [N,K]).
// EPI: 0 plain(+RELU) -> bf16 C
//      1 LN1: scatter C1[vidx] fp32 + C2[vidx] bf16,  res = e_src[vidx]
//      2 LN2(acc+bias+e_x) -> +e_src -> LN3 -> fp32 C
#define STAGE_B 20480                 // A 64*80 + B 192*80 bytes
#define OFF_B_ST 5120
#define OFF_SV_B (3 * STAGE_B)        // 61440
#define GEMM_SMEM_BYTES (OFF_SV_B + 256)

template <int RELU, int EPI>
__global__ void __launch_bounds__(256, 2)
gemm_bf16(const __nv_bfloat16* __restrict__ A, const __nv_bfloat16* __restrict__ B,
          const float* __restrict__ bias,
          void* __restrict__ Cv, void* __restrict__ C2v,
          const int* __restrict__ vidx,
          const float* __restrict__ e_src, const float* __restrict__ e_x,
          const float* __restrict__ e_g1, const float* __restrict__ e_b1,
          const float* __restrict__ e_g2, const float* __restrict__ e_b2,
          int N, int K)
{
    extern __shared__ char smem[];
    const uint32_t sbase = (uint32_t)__cvta_generic_to_shared(smem);
    int* sv = (int*)(smem + OFF_SV_B);

    const int tid  = threadIdx.x;
    const int lane = tid & 31;
    const int warp = tid >> 5;
    const int wr   = warp >> 2;   // 0..1
    const int wc   = warp & 3;    // 0..3
    const int row0 = blockIdx.x * 64;
    const int col0 = blockIdx.y * 192;

    if (EPI == 1 && tid < 64) sv[tid] = vidx[row0 + tid];

    float acc[2][6][4];
    #pragma unroll
    for (int m = 0; m < 2; m++)
        #pragma unroll
        for (int n = 0; n < 6; n++)
            #pragma unroll
            for (int i = 0; i < 4; i++) acc[m][n][i] = 0.f;

    const __nv_bfloat16* Arow = A + (size_t)row0 * K;
    const __nv_bfloat16* Brow = B + (size_t)col0 * K;
    const int arow = tid >> 2;   // 0..63
    const int ach  = tid & 3;    // 16B chunk

    auto issue = [&](int it) {
        int st = it % 3;
        uint32_t sA = sbase + st * STAGE_B;
        int kb = it * 32;
        cp16(sA + arow * 80 + ach * 16, Arow + (size_t)arow * K + kb + ach * 8);
        uint32_t sB = sA + OFF_B_ST;
        #pragma unroll
        for (int r = 0; r < 3; r++) {
            int rr = arow + r * 64;
            cp16(sB + rr * 80 + ach * 16, Brow + (size_t)rr * K + kb + ach * 8);
        }
        asm volatile("cp.async.commit_group;" ::: "memory");
    };

    // ldmatrix lane address components (verified fragment mapping, 80B row stride)
    const int a_row = wr * 32 + (lane & 7) + ((lane >> 3) & 1) * 8;
    const int a_cb  = ((lane >> 4) & 1) * 4;
    const int b_row = wc * 48 + (lane & 7) + ((lane >> 4) & 1) * 8;
    const int b_cb  = ((lane >> 3) & 1) * 4;

    const int nk = K >> 5;
    issue(0); issue(1);

    for (int it = 0; it < nk; it++) {
        asm volatile("cp.async.wait_group 1;" ::: "memory");
        __syncthreads();
        if (it + 2 < nk) issue(it + 2);
        else asm volatile("cp.async.commit_group;" ::: "memory");

        const int st = it % 3;
        const uint32_t stA = sbase + st * STAGE_B;
        const uint32_t stB = stA + OFF_B_ST;
        #pragma unroll
        for (int k16 = 0; k16 < 2; k16++) {
            const int kp = k16 * 8;
            uint32_t ah[4], ah2[4];
            ldsm_x4(ah[0], ah[1], ah[2], ah[3],
                    stA + (uint32_t)((a_row * 20 + kp + a_cb) * 4));
            ldsm_x4(ah2[0], ah2[1], ah2[2], ah2[3],
                    stA + (uint32_t)(((a_row + 16) * 20 + kp + a_cb) * 4));
            uint32_t bh[12];
            #pragma unroll
            for (int p = 0; p < 3; p++) {
                ldsm_x4(bh[p * 4 + 0], bh[p * 4 + 1], bh[p * 4 + 2], bh[p * 4 + 3],
                        stB + (uint32_t)(((b_row + p * 16) * 20 + kp + b_cb) * 4));
            }
            #pragma unroll
            for (int nt = 0; nt < 6; nt++) {
                uint32_t bh0 = bh[nt * 2], bh1 = bh[nt * 2 + 1];
                mma_bf16(acc[0][nt], ah[0],  ah[1],  ah[2],  ah[3],  bh0, bh1);
                mma_bf16(acc[1][nt], ah2[0], ah2[1], ah2[2], ah2[3], bh0, bh1);
            }
        }
        __syncthreads();
    }

    // ================= epilogue =================
    if (EPI == 0) {
        __nv_bfloat16* Cb = (__nv_bfloat16*)Cv;
        #pragma unroll
        for (int mt = 0; mt < 2; mt++) {
            int r0 = row0 + wr * 32 + mt * 16 + (lane >> 2);
            #pragma unroll
            for (int nt = 0; nt < 6; nt++) {
                int c = col0 + wc * 48 + nt * 8 + 2 * (lane & 3);
                float bx = bias[c], by = bias[c + 1];
                float o0x = acc[mt][nt][0] + bx, o0y = acc[mt][nt][1] + by;
                float o1x = acc[mt][nt][2] + bx, o1y = acc[mt][nt][3] + by;
                if (RELU) {
                    o0x = fmaxf(o0x, 0.f); o0y = fmaxf(o0y, 0.f);
                    o1x = fmaxf(o1x, 0.f); o1y = fmaxf(o1y, 0.f);
                }
                *(uint32_t*)&Cb[(size_t)r0 * N + c]       = pack_bf16(o0x, o0y);
                *(uint32_t*)&Cb[(size_t)(r0 + 8) * N + c] = pack_bf16(o1x, o1y);
            }
        }
        return;
    }

    // LN epilogues: N == 192 (full row per block), col0 == 0
    float* rsum = (float*)smem;        // [64]
    float* rsq  = (float*)smem + 64;   // [64]
    if (tid < 64) { rsum[tid] = 0.f; rsq[tid] = 0.f; }
    __syncthreads();

    #pragma unroll
    for (int mt = 0; mt < 2; mt++) {
        #pragma unroll
        for (int half = 0; half < 2; half++) {
            int row = wr * 32 + mt * 16 + (lane >> 2) + half * 8;
            float s1 = 0.f, s2 = 0.f;
            #pragma unroll
            for (int nt = 0; nt < 6; nt++) {
                int c = wc * 48 + nt * 8 + 2 * (lane & 3);
                float2 res;
                if (EPI == 1) {
                    int v = sv[row];
                    res = *(const float2*)&e_src[(size_t)v * CDIM + c];
                } else {
                    res = *(const float2*)&e_x[(size_t)(row0 + row) * CDIM + c];
                }
                float v0 = acc[mt][nt][half * 2 + 0] + bias[c]     + res.x;
                float v1 = acc[mt][nt][half * 2 + 1] + bias[c + 1] + res.y;
                acc[mt][nt][half * 2 + 0] = v0;
                acc[mt][nt][half * 2 + 1] = v1;
                s1 += v0 + v1; s2 += v0 * v0 + v1 * v1;
            }
            atomicAdd(&rsum[row], s1);
            atomicAdd(&rsq[row],  s2);
        }
    }
    __syncthreads();

    if (EPI == 1) {
        float* Cf = (float*)Cv;
        __nv_bfloat16* Cb2 = (__nv_bfloat16*)C2v;
        #pragma unroll
        for (int mt = 0; mt < 2; mt++) {
            #pragma unroll
            for (int half = 0; half < 2; half++) {
                int row = wr * 32 + mt * 16 + (lane >> 2) + half * 8;
                int v = sv[row];
                float mean = rsum[row] * (1.f / CDIM);
                float var  = rsq[row] * (1.f / CDIM) - mean * mean;
                float inv  = rsqrtf(var + 1e-5f);
                #pragma unroll
                for (int nt = 0; nt < 6; nt++) {
                    int c = wc * 48 + nt * 8 + 2 * (lane & 3);
                    float ox = (acc[mt][nt][half * 2 + 0] - mean) * inv * e_g1[c]     + e_b1[c];
                    float oy = (acc[mt][nt][half * 2 + 1] - mean) * inv * e_g1[c + 1] + e_b1[c + 1];
                    float2 o; o.x = ox; o.y = oy;
                    *(float2*)&Cf[(size_t)v * CDIM + c] = o;
                    *(uint32_t*)&Cb2[(size_t)v * CDIM + c] = pack_bf16(ox, oy);
                }
            }
        }
        return;
    }

    // EPI == 2: LN2 then +src then LN3 -> fp32
    float su1[4], su2[4];
    #pragma unroll
    for (int mt = 0; mt < 2; mt++) {
        #pragma unroll
        for (int half = 0; half < 2; half++) {
            int row = wr * 32 + mt * 16 + (lane >> 2) + half * 8;
            float mean = rsum[row] * (1.f / CDIM);
            float var  = rsq[row] * (1.f / CDIM) - mean * mean;
            float inv  = rsqrtf(var + 1e-5f);
            float s1 = 0.f, s2 = 0.f;
            #pragma unroll
            for (int nt = 0; nt < 6; nt++) {
                int c = wc * 48 + nt * 8 + 2 * (lane & 3);
                float2 sr = *(const float2*)&e_src[(size_t)(row0 + row) * CDIM + c];
                float u0 = (acc[mt][nt][half * 2 + 0] - mean) * inv * e_g1[c]     + e_b1[c]     + sr.x;
                float u1 = (acc[mt][nt][half * 2 + 1] - mean) * inv * e_g1[c + 1] + e_b1[c + 1] + sr.y;
                acc[mt][nt][half * 2 + 0] = u0;
                acc[mt][nt][half * 2 + 1] = u1;
                s1 += u0 + u1; s2 += u0 * u0 + u1 * u1;
            }
            su1[mt * 2 + half] = s1;
            su2[mt * 2 + half] = s2;
        }
    }
    __syncthreads();
    if (tid < 64) { rsum[tid] = 0.f; rsq[tid] = 0.f; }
    __syncthreads();
    #pragma unroll
    for (int mt = 0; mt < 2; mt++) {
        #pragma unroll
        for (int half = 0; half < 2; half++) {
            int row = wr * 32 + mt * 16 + (lane >> 2) + half * 8;
            atomicAdd(&rsum[row], su1[mt * 2 + half]);
            atomicAdd(&rsq[row],  su2[mt * 2 + half]);
        }
    }
    __syncthreads();
    {
        float* Cf = (float*)Cv;
        #pragma unroll
        for (int mt = 0; mt < 2; mt++) {
            #pragma unroll
            for (int half = 0; half < 2; half++) {
                int row = wr * 32 + mt * 16 + (lane >> 2) + half * 8;
                float mean = rsum[row] * (1.f / CDIM);
                float var  = rsq[row] * (1.f / CDIM) - mean * mean;
                float inv  = rsqrtf(var + 1e-5f);
                #pragma unroll
                for (int nt = 0; nt < 6; nt++) {
                    int c = wc * 48 + nt * 8 + 2 * (lane & 3);
                    float2 o;
                    o.x = (acc[mt][nt][half * 2 + 0] - mean) * inv * e_g2[c]     + e_b2[c];
                    o.y = (acc[mt][nt][half * 2 + 1] - mean) * inv * e_g2[c + 1] + e_b2[c + 1];
                    *(float2*)&Cf[(size_t)(row0 + row) * CDIM + c] = o;
                }
            }
        }
    }
}

// ---------------- attention: 192 threads = 4 (set,head) pairs, bf16 io ------
__global__ void __launch_bounds__(192)
attn_kernel(const uint8_t* __restrict__ mask)
{
    const int p   = threadIdx.x / SETSZ;
    const int i   = threadIdx.x % SETSZ;
    const int gp  = blockIdx.x * 4 + p;
    const int s   = gp >> 3;
    const int h   = gp & 7;

    __shared__ float ks[4][SETSZ][28];
    __shared__ float vs[4][SETSZ][28];
    __shared__ float mf[4][SETSZ];

    const size_t ro = (size_t)s * SETSZ + i;
    const __nv_bfloat16* qrow = g_qk + ro * (2 * CDIM) + (size_t)h * HD;
    const __nv_bfloat16* vrow = g_v  + ro * CDIM + (size_t)h * HD;

    float qf[24], kf[24], vf[24];
    bf8_to_f(qrow,      qf);      bf8_to_f(qrow + 8,       qf + 8);  bf8_to_f(qrow + 16,       qf + 16);
    bf8_to_f(qrow+CDIM, kf);      bf8_to_f(qrow+CDIM + 8,  kf + 8);  bf8_to_f(qrow+CDIM + 16,  kf + 16);
    bf8_to_f(vrow,      vf);      bf8_to_f(vrow + 8,       vf + 8);  bf8_to_f(vrow + 16,       vf + 16);

    float4 q[6];
    #pragma unroll
    for (int t = 0; t < 6; t++) {
        q[t] = make_float4(qf[4*t], qf[4*t+1], qf[4*t+2], qf[4*t+3]);
        *(float4*)&ks[p][i][t * 4] = make_float4(kf[4*t], kf[4*t+1], kf[4*t+2], kf[4*t+3]);
        *(float4*)&vs[p][i][t * 4] = make_float4(vf[4*t], vf[4*t+1], vf[4*t+2], vf[4*t+3]);
    }
    mf[p][i] = (mask[(size_t)s * SETSZ + i] != 0) ? -1e9f : 0.f;
    __syncthreads();

    const float scale = 0.20412414523193154f; // 1/sqrt(24)
    float sc[SETSZ];
    #pragma unroll 8
    for (int j = 0; j < SETSZ; j++) {
        float4 k0 = *(const float4*)&ks[p][j][0];
        float4 k1 = *(const float4*)&ks[p][j][4];
        float4 k2 = *(const float4*)&ks[p][j][8];
        float4 k3 = *(const float4*)&ks[p][j][12];
        float4 k4 = *(const float4*)&ks[p][j][16];
        float4 k5 = *(const float4*)&ks[p][j][20];
        float a0 = q[0].x * k0.x + q[0].y * k0.y + q[0].z * k0.z + q[0].w * k0.w;
        float a1 = q[1].x * k1.x + q[1].y * k1.y + q[1].z * k1.z + q[1].w * k1.w;
        float a2 = q[2].x * k2.x + q[2].y * k2.y + q[2].z * k2.z + q[2].w * k2.w;
        float a3 = q[3].x * k3.x + q[3].y * k3.y + q[3].z * k3.z + q[3].w * k3.w;
        float a4 = q[4].x * k4.x + q[4].y * k4.y + q[4].z * k4.z + q[4].w * k4.w;
        float a5 = q[5].x * k5.x + q[5].y * k5.y + q[5].z * k5.z + q[5].w * k5.w;
        sc[j] = ((a0 + a1) + (a2 + a3) + (a4 + a5)) * scale + mf[p][j];
    }

    float m = -1e30f;
    #pragma unroll
    for (int j = 0; j < SETSZ; j++) m = fmaxf(m, sc[j]);
    float sum = 0.f;
    #pragma unroll
    for (int j = 0; j < SETSZ; j++) { float e = __expf(sc[j] - m); sc[j] = e; sum += e; }
    float inv = 1.f / sum;

    float4 o[6];
    #pragma unroll
    for (int t = 0; t < 6; t++) { o[t].x = 0.f; o[t].y = 0.f; o[t].z = 0.f; o[t].w = 0.f; }
    #pragma unroll 4
    for (int j = 0; j < SETSZ; j++) {
        float pr = sc[j] * inv;
        #pragma unroll
        for (int t = 0; t < 6; t++) {
            float4 v4 = *(const float4*)&vs[p][j][t * 4];
            o[t].x += pr * v4.x; o[t].y += pr * v4.y;
            o[t].z += pr * v4.z; o[t].w += pr * v4.w;
        }
    }
    __nv_bfloat16* crow = g_ctx + ro * CDIM + (size_t)h * HD;
    uint4 u0, u1, u2;
    u0.x = pack_bf16(o[0].x, o[0].y); u0.y = pack_bf16(o[0].z, o[0].w);
    u0.z = pack_bf16(o[1].x, o[1].y); u0.w = pack_bf16(o[1].z, o[1].w);
    u1.x = pack_bf16(o[2].x, o[2].y); u1.y = pack_bf16(o[2].z, o[2].w);
    u1.z = pack_bf16(o[3].x, o[3].y); u1.w = pack_bf16(o[3].z, o[3].w);
    u2.x = pack_bf16(o[4].x, o[4].y); u2.y = pack_bf16(o[4].z, o[4].w);
    u2.z = pack_bf16(o[5].x, o[5].y); u2.w = pack_bf16(o[5].z, o[5].w);
    *(uint4*)(crow)      = u0;
    *(uint4*)(crow + 8)  = u1;
    *(uint4*)(crow + 16) = u2;
}

// ---------------- launch --------------------------------------------------
extern "C" void kernel_launch(void* const* d_in, const int* in_sizes, int n_in,
                              void* d_out, int out_size)
{
    const float* src   = (const float*)d_in[0];
    const float* pos   = (const float*)d_in[1];
    const float* w_qkv = (const float*)d_in[2];
    const float* b_qkv = (const float*)d_in[3];
    const float* w_out = (const float*)d_in[4];
    const float* b_out = (const float*)d_in[5];
    const float* w1    = (const float*)d_in[6];
    const float* b1    = (const float*)d_in[7];
    const float* w2    = (const float*)d_in[8];
    const float* b2    = (const float*)d_in[9];
    const float* ln1g  = (const float*)d_in[10];
    const float* ln1b  = (const float*)d_in[11];
    const float* ln2g  = (const float*)d_in[12];
    const float* ln2b  = (const float*)d_in[13];
    const float* ln3g  = (const float*)d_in[14];
    const float* ln3b  = (const float*)d_in[15];
    const int*   vidx  = (const int*)d_in[16];
    const uint8_t* msk = (const uint8_t*)d_in[17];
    float* out = (float*)d_out;

    __nv_bfloat16 *p_qkin, *p_feat, *p_qk, *p_v, *p_ctx, *p_xb, *p_h;
    __nv_bfloat16 *p_wqkv, *p_wout, *p_w1, *p_w2;
    float *p_x;
    cudaGetSymbolAddress((void**)&p_qkin, g_qkin);
    cudaGetSymbolAddress((void**)&p_feat, g_feat);
    cudaGetSymbolAddress((void**)&p_qk,   g_qk);
    cudaGetSymbolAddress((void**)&p_v,    g_v);
    cudaGetSymbolAddress((void**)&p_ctx,  g_ctx);
    cudaGetSymbolAddress((void**)&p_x,    g_x);
    cudaGetSymbolAddress((void**)&p_xb,   g_xb);
    cudaGetSymbolAddress((void**)&p_h,    g_h);
    cudaGetSymbolAddress((void**)&p_wqkv, g_wqkv);
    cudaGetSymbolAddress((void**)&p_wout, g_wout);
    cudaGetSymbolAddress((void**)&p_w1,   g_w1);
    cudaGetSymbolAddress((void**)&p_w2,   g_w2);

    cudaFuncSetAttribute(gemm_bf16<0,0>, cudaFuncAttributeMaxDynamicSharedMemorySize, GEMM_SMEM_BYTES);
    cudaFuncSetAttribute(gemm_bf16<1,0>, cudaFuncAttributeMaxDynamicSharedMemorySize, GEMM_SMEM_BYTES);
    cudaFuncSetAttribute(gemm_bf16<0,1>, cudaFuncAttributeMaxDynamicSharedMemorySize, GEMM_SMEM_BYTES);
    cudaFuncSetAttribute(gemm_bf16<0,2>, cudaFuncAttributeMaxDynamicSharedMemorySize, GEMM_SMEM_BYTES);

    // 0) weights -> bf16
    cvt_kernel<<<(3*CDIM*CDIM/2 + 255)/256, 256>>>(w_qkv, p_wqkv, 3*CDIM*CDIM/2);
    cvt_kernel<<<(CDIM*CDIM/2   + 255)/256, 256>>>(w_out, p_wout, CDIM*CDIM/2);
    cvt_kernel<<<(DFF*CDIM/2    + 255)/256, 256>>>(w1,    p_w1,   DFF*CDIM/2);
    cvt_kernel<<<(CDIM*DFF/2    + 255)/256, 256>>>(w2,    p_w2,   CDIM*DFF/2);

    // 1) gather (bf16)
    gather_kernel<<<(int)(((size_t)NVOX*(CDIM/8) + 255)/256), 256>>>(src, pos, vidx);

    const int MB = NVOX / 64;  // 3072

    // 2) q,k projection: (N x 384) bf16
    gemm_bf16<0,0><<<dim3(MB, 2), 256, GEMM_SMEM_BYTES>>>(
        p_qkin, p_wqkv, b_qkv, p_qk, nullptr, nullptr,
        nullptr, nullptr, nullptr, nullptr, nullptr, nullptr,
        2 * CDIM, CDIM);

    // 3) v projection: (N x 192) bf16
    gemm_bf16<0,0><<<dim3(MB, 1), 256, GEMM_SMEM_BYTES>>>(
        p_feat, p_wqkv + (size_t)2 * CDIM * CDIM, b_qkv + 2 * CDIM, p_v, nullptr, nullptr,
        nullptr, nullptr, nullptr, nullptr, nullptr, nullptr,
        CDIM, CDIM);

    // 4) attention (bf16 in/out)
    attn_kernel<<<(SETS * NHEAD) / 4, 192>>>(msk);

    // 5) out-proj + scatter + residual + LN1 -> g_x (fp32) + g_xb (bf16)
    gemm_bf16<0,1><<<dim3(MB, 1), 256, GEMM_SMEM_BYTES>>>(
        p_ctx, p_wout, b_out, p_x, p_xb, vidx,
        src, nullptr, ln1g, ln1b, nullptr, nullptr,
        CDIM, CDIM);

    // 6) FFN1 (relu) -> g_h bf16
    gemm_bf16<1,0><<<dim3(MB, 2), 256, GEMM_SMEM_BYTES>>>(
        p_xb, p_w1, b1, p_h, nullptr, nullptr,
        nullptr, nullptr, nullptr, nullptr, nullptr, nullptr,
        DFF, CDIM);

    // 7) FFN2 + LN2 + residual + LN3 -> out (fp32)
    gemm_bf16<0,2><<<dim3(MB, 1), 256, GEMM_SMEM_BYTES>>>(
        p_h, p_w2, b2, out, nullptr, nullptr,
        src, p_x, ln2g, ln2b, ln3g, ln3b,
        CDIM, DFF);
}

// round 11
// speedup vs baseline: 2.3344x; 1.2220x over previous
#include <cuda_runtime.h>
#include <cuda_bf16.h>
#include <cstdint>
#include <cstddef>

// ---------------- problem constants ----------------
#define NVOX   196608
#define CDIM   192
#define SETS   4096
#define SETSZ  48
#define NHEAD  8
#define HD     24
#define DFF    384

// ---------------- scratch (device globals) ----------------
__device__ __nv_bfloat16 g_qkin[(size_t)NVOX * CDIM];   // gathered src+pos (set-slot order)
__device__ __nv_bfloat16 g_feat[(size_t)NVOX * CDIM];   // gathered src
__device__ __nv_bfloat16 g_qk  [(size_t)NVOX * 2 * CDIM];
__device__ __nv_bfloat16 g_v   [(size_t)NVOX * CDIM];
__device__ __nv_bfloat16 g_ctx [(size_t)NVOX * CDIM];
__device__ float         g_x   [(size_t)NVOX * CDIM];   // LN1 out, fp32 (residual precision)
__device__ __nv_bfloat16 g_xb  [(size_t)NVOX * CDIM];   // LN1 out, bf16 (FFN1 input)
__device__ __nv_bfloat16 g_h   [(size_t)NVOX * DFF];
// bf16 weights
__device__ __nv_bfloat16 g_wqkv[3 * CDIM * CDIM];
__device__ __nv_bfloat16 g_wout[CDIM * CDIM];
__device__ __nv_bfloat16 g_w1  [DFF * CDIM];
__device__ __nv_bfloat16 g_w2  [CDIM * DFF];

// ---------------- helpers ----------------
__device__ __forceinline__ uint32_t pack_bf16(float x, float y)
{
    __nv_bfloat162 h2 = __floats2bfloat162_rn(x, y);
    return *reinterpret_cast<const uint32_t*>(&h2);
}

__device__ __forceinline__ void mma_bf16(float c[4],
    uint32_t a0, uint32_t a1, uint32_t a2, uint32_t a3,
    uint32_t b0, uint32_t b1)
{
    asm volatile(
        "mma.sync.aligned.m16n8k16.row.col.f32.bf16.bf16.f32 "
        "{%0,%1,%2,%3}, {%4,%5,%6,%7}, {%8,%9}, {%0,%1,%2,%3};\n"
        : "+f"(c[0]), "+f"(c[1]), "+f"(c[2]), "+f"(c[3])
        : "r"(a0), "r"(a1), "r"(a2), "r"(a3), "r"(b0), "r"(b1));
}
__device__ __forceinline__ void ldsm_x4(uint32_t& r0, uint32_t& r1,
                                        uint32_t& r2, uint32_t& r3, uint32_t addr)
{
    asm volatile("ldmatrix.sync.aligned.m8n8.x4.shared.b16 {%0,%1,%2,%3}, [%4];"
                 : "=r"(r0), "=r"(r1), "=r"(r2), "=r"(r3) : "r"(addr));
}
__device__ __forceinline__ void ldsm_x4_t(uint32_t& r0, uint32_t& r1,
                                          uint32_t& r2, uint32_t& r3, uint32_t addr)
{
    asm volatile("ldmatrix.sync.aligned.m8n8.x4.trans.shared.b16 {%0,%1,%2,%3}, [%4];"
                 : "=r"(r0), "=r"(r1), "=r"(r2), "=r"(r3) : "r"(addr));
}
__device__ __forceinline__ void cp16(uint32_t saddr, const void* gaddr)
{
    asm volatile("cp.async.cg.shared.global [%0], [%1], 16;"
                 :: "r"(saddr), "l"(gaddr) : "memory");
}

// ---------------- weight fp32 -> bf16 conversion ----------------
__global__ void cvt_kernel(const float* __restrict__ in, __nv_bfloat16* __restrict__ out, int n2)
{
    int i = blockIdx.x * blockDim.x + threadIdx.x;
    if (i < n2) ((uint32_t*)out)[i] = pack_bf16(in[2 * i], in[2 * i + 1]);
}

// ---------------- gather: qkin = bf16(src[v]+pos[v]), feat = bf16(src[v]) ---
__global__ void __launch_bounds__(256)
gather_kernel(const float* __restrict__ src, const float* __restrict__ pos,
              const int* __restrict__ vidx)
{
    size_t i = (size_t)blockIdx.x * blockDim.x + threadIdx.x; // per 8 elements
    if (i >= (size_t)NVOX * (CDIM / 8)) return;
    int slot = (int)(i / (CDIM / 8));
    int c8   = (int)(i % (CDIM / 8)) * 8;
    int v = vidx[slot];
    const float4* s4 = (const float4*)(src + (size_t)v * CDIM + c8);
    const float4* p4 = (const float4*)(pos + (size_t)v * CDIM + c8);
    float4 s0 = s4[0], s1 = s4[1];
    float4 p0 = p4[0], p1 = p4[1];
    uint4 fo, qo;
    fo.x = pack_bf16(s0.x, s0.y); fo.y = pack_bf16(s0.z, s0.w);
    fo.z = pack_bf16(s1.x, s1.y); fo.w = pack_bf16(s1.z, s1.w);
    qo.x = pack_bf16(s0.x + p0.x, s0.y + p0.y); qo.y = pack_bf16(s0.z + p0.z, s0.w + p0.w);
    qo.z = pack_bf16(s1.x + p1.x, s1.y + p1.y); qo.w = pack_bf16(s1.z + p1.z, s1.w + p1.w);
    *(uint4*)(g_feat + i * 8) = fo;
    *(uint4*)(g_qkin + i * 8) = qo;
}

// ---------------- bf16 GEMM, BM=64 BN=192 BK=32, cp.async 3-stage ----------
#define STAGE_B 20480
#define OFF_B_ST 5120
#define OFF_SV_B (3 * STAGE_B)
#define GEMM_SMEM_BYTES (OFF_SV_B + 256)

template <int RELU, int EPI>
__global__ void __launch_bounds__(256, 2)
gemm_bf16(const __nv_bfloat16* __restrict__ A, const __nv_bfloat16* __restrict__ B,
          const float* __restrict__ bias,
          void* __restrict__ Cv, void* __restrict__ C2v,
          const int* __restrict__ vidx,
          const float* __restrict__ e_src, const float* __restrict__ e_x,
          const float* __restrict__ e_g1, const float* __restrict__ e_b1,
          const float* __restrict__ e_g2, const float* __restrict__ e_b2,
          int N, int K)
{
    extern __shared__ char smem[];
    const uint32_t sbase = (uint32_t)__cvta_generic_to_shared(smem);
    int* sv = (int*)(smem + OFF_SV_B);

    const int tid  = threadIdx.x;
    const int lane = tid & 31;
    const int warp = tid >> 5;
    const int wr   = warp >> 2;
    const int wc   = warp & 3;
    const int row0 = blockIdx.x * 64;
    const int col0 = blockIdx.y * 192;

    if (EPI == 1 && tid < 64) sv[tid] = vidx[row0 + tid];

    float acc[2][6][4];
    #pragma unroll
    for (int m = 0; m < 2; m++)
        #pragma unroll
        for (int n = 0; n < 6; n++)
            #pragma unroll
            for (int i = 0; i < 4; i++) acc[m][n][i] = 0.f;

    const __nv_bfloat16* Arow = A + (size_t)row0 * K;
    const __nv_bfloat16* Brow = B + (size_t)col0 * K;
    const int arow = tid >> 2;
    const int ach  = tid & 3;

    auto issue = [&](int it) {
        int st = it % 3;
        uint32_t sA = sbase + st * STAGE_B;
        int kb = it * 32;
        cp16(sA + arow * 80 + ach * 16, Arow + (size_t)arow * K + kb + ach * 8);
        uint32_t sB = sA + OFF_B_ST;
        #pragma unroll
        for (int r = 0; r < 3; r++) {
            int rr = arow + r * 64;
            cp16(sB + rr * 80 + ach * 16, Brow + (size_t)rr * K + kb + ach * 8);
        }
        asm volatile("cp.async.commit_group;" ::: "memory");
    };

    const int a_row = wr * 32 + (lane & 7) + ((lane >> 3) & 1) * 8;
    const int a_cb  = ((lane >> 4) & 1) * 4;
    const int b_row = wc * 48 + (lane & 7) + ((lane >> 4) & 1) * 8;
    const int b_cb  = ((lane >> 3) & 1) * 4;

    const int nk = K >> 5;
    issue(0); issue(1);

    for (int it = 0; it < nk; it++) {
        asm volatile("cp.async.wait_group 1;" ::: "memory");
        __syncthreads();
        if (it + 2 < nk) issue(it + 2);
        else asm volatile("cp.async.commit_group;" ::: "memory");

        const int st = it % 3;
        const uint32_t stA = sbase + st * STAGE_B;
        const uint32_t stB = stA + OFF_B_ST;
        #pragma unroll
        for (int k16 = 0; k16 < 2; k16++) {
            const int kp = k16 * 8;
            uint32_t ah[4], ah2[4];
            ldsm_x4(ah[0], ah[1], ah[2], ah[3],
                    stA + (uint32_t)((a_row * 20 + kp + a_cb) * 4));
            ldsm_x4(ah2[0], ah2[1], ah2[2], ah2[3],
                    stA + (uint32_t)(((a_row + 16) * 20 + kp + a_cb) * 4));
            uint32_t bh[12];
            #pragma unroll
            for (int p = 0; p < 3; p++) {
                ldsm_x4(bh[p * 4 + 0], bh[p * 4 + 1], bh[p * 4 + 2], bh[p * 4 + 3],
                        stB + (uint32_t)(((b_row + p * 16) * 20 + kp + b_cb) * 4));
            }
            #pragma unroll
            for (int nt = 0; nt < 6; nt++) {
                uint32_t bh0 = bh[nt * 2], bh1 = bh[nt * 2 + 1];
                mma_bf16(acc[0][nt], ah[0],  ah[1],  ah[2],  ah[3],  bh0, bh1);
                mma_bf16(acc[1][nt], ah2[0], ah2[1], ah2[2], ah2[3], bh0, bh1);
            }
        }
        __syncthreads();
    }

    // ================= epilogue =================
    if (EPI == 0) {
        __nv_bfloat16* Cb = (__nv_bfloat16*)Cv;
        #pragma unroll
        for (int mt = 0; mt < 2; mt++) {
            int r0 = row0 + wr * 32 + mt * 16 + (lane >> 2);
            #pragma unroll
            for (int nt = 0; nt < 6; nt++) {
                int c = col0 + wc * 48 + nt * 8 + 2 * (lane & 3);
                float bx = bias[c], by = bias[c + 1];
                float o0x = acc[mt][nt][0] + bx, o0y = acc[mt][nt][1] + by;
                float o1x = acc[mt][nt][2] + bx, o1y = acc[mt][nt][3] + by;
                if (RELU) {
                    o0x = fmaxf(o0x, 0.f); o0y = fmaxf(o0y, 0.f);
                    o1x = fmaxf(o1x, 0.f); o1y = fmaxf(o1y, 0.f);
                }
                *(uint32_t*)&Cb[(size_t)r0 * N + c]       = pack_bf16(o0x, o0y);
                *(uint32_t*)&Cb[(size_t)(r0 + 8) * N + c] = pack_bf16(o1x, o1y);
            }
        }
        return;
    }

    float* rsum = (float*)smem;
    float* rsq  = (float*)smem + 64;
    if (tid < 64) { rsum[tid] = 0.f; rsq[tid] = 0.f; }
    __syncthreads();

    #pragma unroll
    for (int mt = 0; mt < 2; mt++) {
        #pragma unroll
        for (int half = 0; half < 2; half++) {
            int row = wr * 32 + mt * 16 + (lane >> 2) + half * 8;
            float s1 = 0.f, s2 = 0.f;
            #pragma unroll
            for (int nt = 0; nt < 6; nt++) {
                int c = wc * 48 + nt * 8 + 2 * (lane & 3);
                float2 res;
                if (EPI == 1) {
                    int v = sv[row];
                    res = *(const float2*)&e_src[(size_t)v * CDIM + c];
                } else {
                    res = *(const float2*)&e_x[(size_t)(row0 + row) * CDIM + c];
                }
                float v0 = acc[mt][nt][half * 2 + 0] + bias[c]     + res.x;
                float v1 = acc[mt][nt][half * 2 + 1] + bias[c + 1] + res.y;
                acc[mt][nt][half * 2 + 0] = v0;
                acc[mt][nt][half * 2 + 1] = v1;
                s1 += v0 + v1; s2 += v0 * v0 + v1 * v1;
            }
            atomicAdd(&rsum[row], s1);
            atomicAdd(&rsq[row],  s2);
        }
    }
    __syncthreads();

    if (EPI == 1) {
        float* Cf = (float*)Cv;
        __nv_bfloat16* Cb2 = (__nv_bfloat16*)C2v;
        #pragma unroll
        for (int mt = 0; mt < 2; mt++) {
            #pragma unroll
            for (int half = 0; half < 2; half++) {
                int row = wr * 32 + mt * 16 + (lane >> 2) + half * 8;
                int v = sv[row];
                float mean = rsum[row] * (1.f / CDIM);
                float var  = rsq[row] * (1.f / CDIM) - mean * mean;
                float inv  = rsqrtf(var + 1e-5f);
                #pragma unroll
                for (int nt = 0; nt < 6; nt++) {
                    int c = wc * 48 + nt * 8 + 2 * (lane & 3);
                    float ox = (acc[mt][nt][half * 2 + 0] - mean) * inv * e_g1[c]     + e_b1[c];
                    float oy = (acc[mt][nt][half * 2 + 1] - mean) * inv * e_g1[c + 1] + e_b1[c + 1];
                    float2 o; o.x = ox; o.y = oy;
                    *(float2*)&Cf[(size_t)v * CDIM + c] = o;
                    *(uint32_t*)&Cb2[(size_t)v * CDIM + c] = pack_bf16(ox, oy);
                }
            }
        }
        return;
    }

    // EPI == 2
    float su1[4], su2[4];
    #pragma unroll
    for (int mt = 0; mt < 2; mt++) {
        #pragma unroll
        for (int half = 0; half < 2; half++) {
            int row = wr * 32 + mt * 16 + (lane >> 2) + half * 8;
            float mean = rsum[row] * (1.f / CDIM);
            float var  = rsq[row] * (1.f / CDIM) - mean * mean;
            float inv  = rsqrtf(var + 1e-5f);
            float s1 = 0.f, s2 = 0.f;
            #pragma unroll
            for (int nt = 0; nt < 6; nt++) {
                int c = wc * 48 + nt * 8 + 2 * (lane & 3);
                float2 sr = *(const float2*)&e_src[(size_t)(row0 + row) * CDIM + c];
                float u0 = (acc[mt][nt][half * 2 + 0] - mean) * inv * e_g1[c]     + e_b1[c]     + sr.x;
                float u1 = (acc[mt][nt][half * 2 + 1] - mean) * inv * e_g1[c + 1] + e_b1[c + 1] + sr.y;
                acc[mt][nt][half * 2 + 0] = u0;
                acc[mt][nt][half * 2 + 1] = u1;
                s1 += u0 + u1; s2 += u0 * u0 + u1 * u1;
            }
            su1[mt * 2 + half] = s1;
            su2[mt * 2 + half] = s2;
        }
    }
    __syncthreads();
    if (tid < 64) { rsum[tid] = 0.f; rsq[tid] = 0.f; }
    __syncthreads();
    #pragma unroll
    for (int mt = 0; mt < 2; mt++) {
        #pragma unroll
        for (int half = 0; half < 2; half++) {
            int row = wr * 32 + mt * 16 + (lane >> 2) + half * 8;
            atomicAdd(&rsum[row], su1[mt * 2 + half]);
            atomicAdd(&rsq[row],  su2[mt * 2 + half]);
        }
    }
    __syncthreads();
    {
        float* Cf = (float*)Cv;
        #pragma unroll
        for (int mt = 0; mt < 2; mt++) {
            #pragma unroll
            for (int half = 0; half < 2; half++) {
                int row = wr * 32 + mt * 16 + (lane >> 2) + half * 8;
                float mean = rsum[row] * (1.f / CDIM);
                float var  = rsq[row] * (1.f / CDIM) - mean * mean;
                float inv  = rsqrtf(var + 1e-5f);
                #pragma unroll
                for (int nt = 0; nt < 6; nt++) {
                    int c = wc * 48 + nt * 8 + 2 * (lane & 3);
                    float2 o;
                    o.x = (acc[mt][nt][half * 2 + 0] - mean) * inv * e_g2[c]     + e_b2[c];
                    o.y = (acc[mt][nt][half * 2 + 1] - mean) * inv * e_g2[c + 1] + e_b2[c + 1];
                    *(float2*)&Cf[(size_t)(row0 + row) * CDIM + c] = o;
                }
            }
        }
    }
}

// ---------------- attention (tensor-core): 192 thr = 2 pairs x 3 warps ------
// scores via mma (K pad 24->32), softmax in fragments, P@V via acc->A reuse
// with hi/lo bf16 split (exact), V via ldmatrix.trans.
__global__ void __launch_bounds__(192)
attn_kernel(const uint8_t* __restrict__ mask)
{
    __shared__ __nv_bfloat16 qs[2][SETSZ][40];
    __shared__ __nv_bfloat16 ks[2][SETSZ][40];
    __shared__ __nv_bfloat16 vs[2][SETSZ][40];
    __shared__ float mf[2][SETSZ];

    const int tid  = threadIdx.x;
    const int lane = tid & 31;
    const int warp = tid >> 5;          // 0..5
    const int p    = warp / 3;          // pair 0..1
    const int w    = warp % 3;          // m-tile

    // ---- cooperative load: 96 threads per pair ----
    {
        int lt = tid % 96;
        int pp = tid / 96;
        int gpp = blockIdx.x * 2 + pp;
        int ss = gpp >> 3, hh = gpp & 7;
        for (int task = lt; task < SETSZ * 3; task += 96) {
            int row = task / 3, ch = task % 3;
            size_t ro = (size_t)ss * SETSZ + row;
            const __nv_bfloat16* qrow = g_qk + ro * (2 * CDIM) + (size_t)hh * HD + ch * 8;
            *(uint4*)&qs[pp][row][ch * 8] = *(const uint4*)qrow;
            *(uint4*)&ks[pp][row][ch * 8] = *(const uint4*)(qrow + CDIM);
            *(uint4*)&vs[pp][row][ch * 8] = *(const uint4*)(g_v + ro * CDIM + (size_t)hh * HD + ch * 8);
        }
        for (int row = lt; row < SETSZ; row += 96) {
            *(uint4*)&qs[pp][row][24] = make_uint4(0, 0, 0, 0);
            *(uint4*)&ks[pp][row][24] = make_uint4(0, 0, 0, 0);
            *(uint4*)&vs[pp][row][24] = make_uint4(0, 0, 0, 0);
            mf[pp][row] = (mask[(size_t)ss * SETSZ + row] != 0) ? -1e9f : 0.f;
        }
    }
    __syncthreads();

    const int gp = blockIdx.x * 2 + p;
    const int s  = gp >> 3;
    const int h  = gp & 7;

    const uint32_t sq = (uint32_t)__cvta_generic_to_shared(&qs[p][0][0]);
    const uint32_t sk = (uint32_t)__cvta_generic_to_shared(&ks[p][0][0]);
    const uint32_t svv = (uint32_t)__cvta_generic_to_shared(&vs[p][0][0]);

    // ---- scores: Q(m16 rows w*16..) @ K^T ----
    const int a_row = w * 16 + (lane & 7) + ((lane >> 3) & 1) * 8;
    const int a_cb  = ((lane >> 4) & 1) * 4;
    const int b_row = (lane & 7) + ((lane >> 4) & 1) * 8;
    const int b_cb  = ((lane >> 3) & 1) * 4;

    float sacc[6][4];
    #pragma unroll
    for (int nt = 0; nt < 6; nt++)
        #pragma unroll
        for (int i = 0; i < 4; i++) sacc[nt][i] = 0.f;

    #pragma unroll
    for (int kt = 0; kt < 2; kt++) {
        uint32_t qa[4];
        ldsm_x4(qa[0], qa[1], qa[2], qa[3],
                sq + (uint32_t)((a_row * 20 + kt * 8 + a_cb) * 4));
        uint32_t kb[12];
        #pragma unroll
        for (int t = 0; t < 3; t++)
            ldsm_x4(kb[t * 4 + 0], kb[t * 4 + 1], kb[t * 4 + 2], kb[t * 4 + 3],
                    sk + (uint32_t)(((b_row + t * 16) * 20 + kt * 8 + b_cb) * 4));
        #pragma unroll
        for (int nt = 0; nt < 6; nt++)
            mma_bf16(sacc[nt], qa[0], qa[1], qa[2], qa[3], kb[nt * 2], kb[nt * 2 + 1]);
    }

    // ---- softmax in fragments (rows r=w*16+(lane>>2) and r+8) ----
    const float scale = 0.20412414523193154f; // 1/sqrt(24)
    float m0 = -1e30f, m1 = -1e30f;
    #pragma unroll
    for (int nt = 0; nt < 6; nt++) {
        int j0 = nt * 8 + (lane & 3) * 2;
        float mv0 = mf[p][j0], mv1 = mf[p][j0 + 1];
        sacc[nt][0] = sacc[nt][0] * scale + mv0;
        sacc[nt][1] = sacc[nt][1] * scale + mv1;
        sacc[nt][2] = sacc[nt][2] * scale + mv0;
        sacc[nt][3] = sacc[nt][3] * scale + mv1;
        m0 = fmaxf(m0, fmaxf(sacc[nt][0], sacc[nt][1]));
        m1 = fmaxf(m1, fmaxf(sacc[nt][2], sacc[nt][3]));
    }
    m0 = fmaxf(m0, __shfl_xor_sync(0xFFFFFFFFu, m0, 1));
    m0 = fmaxf(m0, __shfl_xor_sync(0xFFFFFFFFu, m0, 2));
    m1 = fmaxf(m1, __shfl_xor_sync(0xFFFFFFFFu, m1, 1));
    m1 = fmaxf(m1, __shfl_xor_sync(0xFFFFFFFFu, m1, 2));
    float s0 = 0.f, s1 = 0.f;
    #pragma unroll
    for (int nt = 0; nt < 6; nt++) {
        sacc[nt][0] = __expf(sacc[nt][0] - m0);
        sacc[nt][1] = __expf(sacc[nt][1] - m0);
        sacc[nt][2] = __expf(sacc[nt][2] - m1);
        sacc[nt][3] = __expf(sacc[nt][3] - m1);
        s0 += sacc[nt][0] + sacc[nt][1];
        s1 += sacc[nt][2] + sacc[nt][3];
    }
    s0 += __shfl_xor_sync(0xFFFFFFFFu, s0, 1);
    s0 += __shfl_xor_sync(0xFFFFFFFFu, s0, 2);
    s1 += __shfl_xor_sync(0xFFFFFFFFu, s1, 1);
    s1 += __shfl_xor_sync(0xFFFFFFFFu, s1, 2);
    float i0 = 1.f / s0, i1 = 1.f / s1;
    #pragma unroll
    for (int nt = 0; nt < 6; nt++) {
        sacc[nt][0] *= i0; sacc[nt][1] *= i0;
        sacc[nt][2] *= i1; sacc[nt][3] *= i1;
    }

    // ---- convert probs to A-fragments (hi + lo split, exact) ----
    uint32_t pah[3][4], pal[3][4];
    #pragma unroll
    for (int kt = 0; kt < 3; kt++) {
        const float* t0 = sacc[2 * kt];
        const float* t1 = sacc[2 * kt + 1];
        float src4[4][2] = {{t0[0], t0[1]}, {t0[2], t0[3]}, {t1[0], t1[1]}, {t1[2], t1[3]}};
        #pragma unroll
        for (int r = 0; r < 4; r++) {
            __nv_bfloat162 hh = __floats2bfloat162_rn(src4[r][0], src4[r][1]);
            pah[kt][r] = *reinterpret_cast<const uint32_t*>(&hh);
            float lx = src4[r][0] - __bfloat162float(hh.x);
            float ly = src4[r][1] - __bfloat162float(hh.y);
            pal[kt][r] = pack_bf16(lx, ly);
        }
    }

    // ---- P @ V via ldmatrix.trans B operands ----
    float oacc[3][4];
    #pragma unroll
    for (int d = 0; d < 3; d++)
        #pragma unroll
        for (int i = 0; i < 4; i++) oacc[d][i] = 0.f;

    const int v_row = (lane & 7) + ((lane >> 3) & 1) * 8;
    const int v_cb  = ((lane >> 4) & 1) * 4;
    #pragma unroll
    for (int kt = 0; kt < 3; kt++) {
        uint32_t base = svv + (uint32_t)(((16 * kt + v_row) * 20 + v_cb) * 4);
        uint32_t b0[4], b1[4];
        ldsm_x4_t(b0[0], b0[1], b0[2], b0[3], base);        // d 0-15
        ldsm_x4_t(b1[0], b1[1], b1[2], b1[3], base + 32);   // d 16-31 (24-31 zero)
        mma_bf16(oacc[0], pah[kt][0], pah[kt][1], pah[kt][2], pah[kt][3], b0[0], b0[1]);
        mma_bf16(oacc[0], pal[kt][0], pal[kt][1], pal[kt][2], pal[kt][3], b0[0], b0[1]);
        mma_bf16(oacc[1], pah[kt][0], pah[kt][1], pah[kt][2], pah[kt][3], b0[2], b0[3]);
        mma_bf16(oacc[1], pal[kt][0], pal[kt][1], pal[kt][2], pal[kt][3], b0[2], b0[3]);
        mma_bf16(oacc[2], pah[kt][0], pah[kt][1], pah[kt][2], pah[kt][3], b1[0], b1[1]);
        mma_bf16(oacc[2], pal[kt][0], pal[kt][1], pal[kt][2], pal[kt][3], b1[0], b1[1]);
    }

    // ---- store ctx (bf16) ----
    {
        size_t r0 = (size_t)s * SETSZ + w * 16 + (lane >> 2);
        int dbase = h * HD + (lane & 3) * 2;
        #pragma unroll
        for (int db = 0; db < 3; db++) {
            int dd = dbase + db * 8;
            *(uint32_t*)&g_ctx[r0 * CDIM + dd]       = pack_bf16(oacc[db][0], oacc[db][1]);
            *(uint32_t*)&g_ctx[(r0 + 8) * CDIM + dd] = pack_bf16(oacc[db][2], oacc[db][3]);
        }
    }
}

// ---------------- launch --------------------------------------------------
extern "C" void kernel_launch(void* const* d_in, const int* in_sizes, int n_in,
                              void* d_out, int out_size)
{
    const float* src   = (const float*)d_in[0];
    const float* pos   = (const float*)d_in[1];
    const float* w_qkv = (const float*)d_in[2];
    const float* b_qkv = (const float*)d_in[3];
    const float* w_out = (const float*)d_in[4];
    const float* b_out = (const float*)d_in[5];
    const float* w1    = (const float*)d_in[6];
    const float* b1    = (const float*)d_in[7];
    const float* w2    = (const float*)d_in[8];
    const float* b2    = (const float*)d_in[9];
    const float* ln1g  = (const float*)d_in[10];
    const float* ln1b  = (const float*)d_in[11];
    const float* ln2g  = (const float*)d_in[12];
    const float* ln2b  = (const float*)d_in[13];
    const float* ln3g  = (const float*)d_in[14];
    const float* ln3b  = (const float*)d_in[15];
    const int*   vidx  = (const int*)d_in[16];
    const uint8_t* msk = (const uint8_t*)d_in[17];
    float* out = (float*)d_out;

    __nv_bfloat16 *p_qkin, *p_feat, *p_qk, *p_v, *p_ctx, *p_xb, *p_h;
    __nv_bfloat16 *p_wqkv, *p_wout, *p_w1, *p_w2;
    float *p_x;
    cudaGetSymbolAddress((void**)&p_qkin, g_qkin);
    cudaGetSymbolAddress((void**)&p_feat, g_feat);
    cudaGetSymbolAddress((void**)&p_qk,   g_qk);
    cudaGetSymbolAddress((void**)&p_v,    g_v);
    cudaGetSymbolAddress((void**)&p_ctx,  g_ctx);
    cudaGetSymbolAddress((void**)&p_x,    g_x);
    cudaGetSymbolAddress((void**)&p_xb,   g_xb);
    cudaGetSymbolAddress((void**)&p_h,    g_h);
    cudaGetSymbolAddress((void**)&p_wqkv, g_wqkv);
    cudaGetSymbolAddress((void**)&p_wout, g_wout);
    cudaGetSymbolAddress((void**)&p_w1,   g_w1);
    cudaGetSymbolAddress((void**)&p_w2,   g_w2);

    cudaFuncSetAttribute(gemm_bf16<0,0>, cudaFuncAttributeMaxDynamicSharedMemorySize, GEMM_SMEM_BYTES);
    cudaFuncSetAttribute(gemm_bf16<1,0>, cudaFuncAttributeMaxDynamicSharedMemorySize, GEMM_SMEM_BYTES);
    cudaFuncSetAttribute(gemm_bf16<0,1>, cudaFuncAttributeMaxDynamicSharedMemorySize, GEMM_SMEM_BYTES);
    cudaFuncSetAttribute(gemm_bf16<0,2>, cudaFuncAttributeMaxDynamicSharedMemorySize, GEMM_SMEM_BYTES);

    // 0) weights -> bf16
    cvt_kernel<<<(3*CDIM*CDIM/2 + 255)/256, 256>>>(w_qkv, p_wqkv, 3*CDIM*CDIM/2);
    cvt_kernel<<<(CDIM*CDIM/2   + 255)/256, 256>>>(w_out, p_wout, CDIM*CDIM/2);
    cvt_kernel<<<(DFF*CDIM/2    + 255)/256, 256>>>(w1,    p_w1,   DFF*CDIM/2);
    cvt_kernel<<<(CDIM*DFF/2    + 255)/256, 256>>>(w2,    p_w2,   CDIM*DFF/2);

    // 1) gather (bf16)
    gather_kernel<<<(int)(((size_t)NVOX*(CDIM/8) + 255)/256), 256>>>(src, pos, vidx);

    const int MB = NVOX / 64;  // 3072

    // 2) q,k projection: (N x 384)
    gemm_bf16<0,0><<<dim3(MB, 2), 256, GEMM_SMEM_BYTES>>>(
        p_qkin, p_wqkv, b_qkv, p_qk, nullptr, nullptr,
        nullptr, nullptr, nullptr, nullptr, nullptr, nullptr,
        2 * CDIM, CDIM);

    // 3) v projection: (N x 192)
    gemm_bf16<0,0><<<dim3(MB, 1), 256, GEMM_SMEM_BYTES>>>(
        p_feat, p_wqkv + (size_t)2 * CDIM * CDIM, b_qkv + 2 * CDIM, p_v, nullptr, nullptr,
        nullptr, nullptr, nullptr, nullptr, nullptr, nullptr,
        CDIM, CDIM);

    // 4) attention (tensor cores)
    attn_kernel<<<(SETS * NHEAD) / 2, 192>>>(msk);

    // 5) out-proj + scatter + residual + LN1 -> g_x (fp32) + g_xb (bf16)
    gemm_bf16<0,1><<<dim3(MB, 1), 256, GEMM_SMEM_BYTES>>>(
        p_ctx, p_wout, b_out, p_x, p_xb, vidx,
        src, nullptr, ln1g, ln1b, nullptr, nullptr,
        CDIM, CDIM);

    // 6) FFN1 (relu) -> g_h bf16
    gemm_bf16<1,0><<<dim3(MB, 2), 256, GEMM_SMEM_BYTES>>>(
        p_xb, p_w1, b1, p_h, nullptr, nullptr,
        nullptr, nullptr, nullptr, nullptr, nullptr, nullptr,
        DFF, CDIM);

    // 7) FFN2 + LN2 + residual + LN3 -> out (fp32)
    gemm_bf16<0,2><<<dim3(MB, 1), 256, GEMM_SMEM_BYTES>>>(
        p_h, p_w2, b2, out, nullptr, nullptr,
        src, p_x, ln2g, ln2b, ln3g, ln3b,
        CDIM, DFF);
}